// round 6
// baseline (speedup 1.0000x reference)
#include <cuda_runtime.h>
#include <cstdint>

typedef unsigned long long u64;
typedef unsigned int u32;
typedef unsigned short u16;

// Problem constants
#define TT   32768
#define DD   256
#define HH   256
#define KV   16
#define CH   128          // scan chunk length
#define NC   (TT/CH)      // 256 chunks
#define NBLK 2

// ---------------- device scratch (no allocations allowed) ----------------
__device__ float g_k[TT*KV];
__device__ float g_q[TT*KV];
__device__ float g_v[TT*KV];
__device__ float g_Sagg[NC*256];
__device__ float g_Zagg[NC];
__device__ int   g_pagg[NC];
__device__ float g_Spre[NC*256];
__device__ float g_Zpre[NC];
__device__ float g_ypre[TT*HH];
__device__ float g_x1[TT*HH];
__device__ int   g_startmode;   // 0=u8 bool, 1=int32, 2=float32

// bf16 hi/lo split operand storage
__device__ u16 g_h1hi[TT*HH];
__device__ u16 g_h1lo[TT*HH];
__device__ u16 g_h2hi[TT*HH];
__device__ u16 g_h2lo[TT*HH];
__device__ u16 g_x1hi[TT*HH];
__device__ u16 g_x1lo[TT*HH];
__device__ u16 g_xhi[TT*DD];
__device__ u16 g_xlo[TT*DD];
__device__ u16 g_whi[6*65536];  // [mat][256][256]: per block {Wm2, Wm3, Wskip}
__device__ u16 g_wlo[6*65536];

// ---------------- f32x2 packed helpers (sm_103a FFMA2) ----------------
__device__ __forceinline__ u64 dup2(float x) {
    u64 r;
    asm("mov.b64 %0, {%1, %1};" : "=l"(r) : "r"(__float_as_uint(x)));
    return r;
}
__device__ __forceinline__ u64 fma2(u64 a, u64 b, u64 c) {
    u64 d;
    asm("fma.rn.f32x2 %0, %1, %2, %3;" : "=l"(d) : "l"(a), "l"(b), "l"(c));
    return d;
}
__device__ __forceinline__ void unpack2(u64 v, float& lo, float& hi) {
    u32 a, b;
    asm("mov.b64 {%0, %1}, %2;" : "=r"(a), "=r"(b) : "l"(v));
    lo = __uint_as_float(a); hi = __uint_as_float(b);
}

__device__ __forceinline__ float phi_fn(float t) {
    return (t > 0.f) ? (1.f + t) : __expf(t);
}

__device__ __forceinline__ int read_start(const void* p, int t, int mode) {
    if (mode == 0) return ((const unsigned char*)p)[t] != 0;
    if (mode == 1) return ((const int*)p)[t] != 0;
    return ((const float*)p)[t] != 0.f;
}

// ---------------- bf16 pack helpers ----------------
// packs first arg into LOW half, second into HIGH half
__device__ __forceinline__ u32 pack_bf16x2(float lo, float hi) {
    u32 r;
    asm("cvt.rn.bf16x2.f32 %0, %1, %2;" : "=r"(r) : "f"(hi), "f"(lo));
    return r;
}
__device__ __forceinline__ float bf16lo_f(u32 p) { return __uint_as_float(p << 16); }
__device__ __forceinline__ float bf16hi_f(u32 p) { return __uint_as_float(p & 0xffff0000u); }

__device__ __forceinline__ u32 smem_to_u32(const void* smem_ptr) {
    u32 addr;
    asm("{ .reg .u64 tmp; cvta.to.shared.u64 tmp, %1; cvt.u32.u64 %0, tmp; }"
        : "=r"(addr) : "l"(smem_ptr));
    return addr;
}

__device__ __forceinline__ void cp_async16(u32 saddr, const void* gptr) {
    asm volatile("cp.async.cg.shared.global [%0], [%1], 16;" :: "r"(saddr), "l"(gptr));
}
__device__ __forceinline__ void cp_commit() {
    asm volatile("cp.async.commit_group;" ::: "memory");
}
__device__ __forceinline__ void cp_wait0() {
    asm volatile("cp.async.wait_group 0;" ::: "memory");
}
__device__ __forceinline__ void cp_wait1() {
    asm volatile("cp.async.wait_group 1;" ::: "memory");
}

__device__ __forceinline__ void ldsm_x4(u32& r0, u32& r1, u32& r2, u32& r3, u32 addr) {
    asm volatile("ldmatrix.sync.aligned.m8n8.x4.shared.b16 {%0,%1,%2,%3}, [%4];"
        : "=r"(r0), "=r"(r1), "=r"(r2), "=r"(r3) : "r"(addr));
}

__device__ __forceinline__ void mma16816(float* d, const u32* a, u32 b0, u32 b1) {
    asm volatile(
        "mma.sync.aligned.m16n8k16.row.col.f32.bf16.bf16.f32 "
        "{%0,%1,%2,%3}, {%4,%5,%6,%7}, {%8,%9}, {%0,%1,%2,%3};"
        : "+f"(d[0]), "+f"(d[1]), "+f"(d[2]), "+f"(d[3])
        : "r"(a[0]), "r"(a[1]), "r"(a[2]), "r"(a[3]), "r"(b0), "r"(b1));
}

// ---------------- init: detect + weight split + x split ----------------
// blocks [0,1536): split 6 weight matrices
// block 1536: detect start dtype
// blocks [1537, 1537+8192): split x (1024 elements per block)
__global__ void init_kernel(const unsigned char* __restrict__ p,
                            const float* __restrict__ x,
                            const float* __restrict__ w0, const float* __restrict__ w1,
                            const float* __restrict__ w2, const float* __restrict__ w3,
                            const float* __restrict__ w4, const float* __restrict__ w5)
{
    int tid = threadIdx.x;
    int bid = blockIdx.x;
    if (bid < 1536) {
        int mat = bid >> 8;
        int idx = ((bid & 255) << 8) | tid;
        const float* src;
        switch (mat) {
            case 0: src = w0; break;
            case 1: src = w1; break;
            case 2: src = w2; break;
            case 3: src = w3; break;
            case 4: src = w4; break;
            default: src = w5; break;
        }
        float f = src[idx];
        u32 ph = pack_bf16x2(f, f);
        float r = f - bf16lo_f(ph);
        u32 pl = pack_bf16x2(r, r);
        g_whi[mat*65536 + idx] = (u16)ph;
        g_wlo[mat*65536 + idx] = (u16)pl;
    } else if (bid == 1536) {
        __shared__ int cnt1, cnt3f;
        if (tid == 0) { cnt1 = 0; cnt3f = 0; }
        __syncthreads();
        int l1 = 0, l3 = 0;
        for (int idx = tid; idx < 4096; idx += 256) {
            unsigned char b = p[idx];
            if ((idx & 3) != 0 && b != 0) l1++;
            if ((idx & 3) == 3 && b == 0x3F) l3++;
        }
        atomicAdd(&cnt1, l1); atomicAdd(&cnt3f, l3);
        __syncthreads();
        if (tid == 0) g_startmode = (cnt3f > 0) ? 2 : ((cnt1 > 0) ? 0 : 1);
    } else {
        int base = (bid - 1537) * 1024 + tid * 4;
        float4 v = *(const float4*)(x + base);
        u32 h0 = pack_bf16x2(v.x, v.y);
        u32 h1 = pack_bf16x2(v.z, v.w);
        u32 l0 = pack_bf16x2(v.x - bf16lo_f(h0), v.y - bf16hi_f(h0));
        u32 l1 = pack_bf16x2(v.z - bf16lo_f(h1), v.w - bf16hi_f(h1));
        *(u32*)(g_xhi + base)     = h0;
        *(u32*)(g_xhi + base + 2) = h1;
        *(u32*)(g_xlo + base)     = l0;
        *(u32*)(g_xlo + base + 2) = l1;
    }
}

// ---------------- k,q,v projections + fused chunk aggregate ----------------
// CTA covers 128 rows = exactly one scan chunk (blockIdx.x = chunk id)
#define KQV_ROWS 128
__global__ void kqv_kernel(const float* __restrict__ xext, int use_x1,
                           const float* __restrict__ Wk, const float* __restrict__ Wq,
                           const float* __restrict__ Wv, const float* __restrict__ bv,
                           const void* __restrict__ startp)
{
    extern __shared__ float sm[];
    float* wt = sm;                  // 256*64
    float* xs = sm + 256*64;         // 128*257 (reused for ks/vs after compute)
    const float* x = use_x1 ? g_x1 : xext;
    int tid = threadIdx.x;
    int base = blockIdx.x * KQV_ROWS;
    int mode = g_startmode;

    for (int idx = tid; idx < 48*256; idx += 256) {
        int o = idx >> 8, c = idx & 255;
        float w;
        if (o < 16)      w = Wk[o*256 + c];
        else if (o < 32) w = Wq[(o-16)*256 + c];
        else             w = Wv[(o-32)*256 + c];
        int gg = o / 6, mm = o - gg*6;
        wt[c*64 + gg*8 + mm] = w;
    }
    {
        const float* xg = x + (size_t)base * 256;
        for (int idx = tid; idx < KQV_ROWS*64; idx += 256) {
            int r = idx >> 6, c4 = (idx & 63) * 4;
            float4 v = *(const float4*)(xg + r*256 + c4);
            float* d = xs + r*257 + c4;
            d[0] = v.x; d[1] = v.y; d[2] = v.z; d[3] = v.w;
        }
    }
    __syncthreads();

    int r0 = tid & 31;
    int g  = tid >> 5;
    u64 acc[4][3];
    #pragma unroll
    for (int rr = 0; rr < 4; rr++)
        #pragma unroll
        for (int pi = 0; pi < 3; pi++) acc[rr][pi] = 0ull;

    const float* wbase = wt + g*8;
    #pragma unroll 2
    for (int c = 0; c < 256; c++) {
        const float* wr = wbase + c*64;
        u64 w0 = *(const u64*)(wr + 0);
        u64 w1 = *(const u64*)(wr + 2);
        u64 w2 = *(const u64*)(wr + 4);
        #pragma unroll
        for (int rr = 0; rr < 4; rr++) {
            float xv = xs[(r0 + rr*32)*257 + c];
            u64 xd = dup2(xv);
            acc[rr][0] = fma2(xd, w0, acc[rr][0]);
            acc[rr][1] = fma2(xd, w1, acc[rr][1]);
            acc[rr][2] = fma2(xd, w2, acc[rr][2]);
        }
    }
    __syncthreads();   // xs no longer needed as input tile -> reuse region

    float* ks_sm = xs;              // 128*16
    float* vs_sm = xs + 2048;       // 128*16
    float* ksums = xs + 4096;       // 128
    int*   stb   = (int*)(xs + 4224); // 128

    #pragma unroll
    for (int rr = 0; rr < 4; rr++) {
        int lr = r0 + rr*32;
        int t  = base + lr;
        #pragma unroll
        for (int pi = 0; pi < 3; pi++) {
            float lo, hi;
            unpack2(acc[rr][pi], lo, hi);
            #pragma unroll
            for (int h = 0; h < 2; h++) {
                int o = g*6 + pi*2 + h;
                float val = h ? hi : lo;
                if (o < 16) {
                    float pk = phi_fn(val);
                    g_k[t*16 + o] = pk;
                    ks_sm[lr*16 + o] = pk;
                } else if (o < 32) {
                    g_q[t*16 + (o-16)] = phi_fn(val);
                } else {
                    float vv = val + bv[o-32];
                    g_v[t*16 + (o-32)] = vv;
                    vs_sm[lr*16 + (o-32)] = vv;
                }
            }
        }
    }
    __syncthreads();

    if (tid < 128) {
        float s = 0.f;
        #pragma unroll
        for (int i = 0; i < 16; i++) s += ks_sm[tid*16 + i];
        ksums[tid] = s;
        stb[tid] = read_start(startp, base + tid, mode);
    }
    __syncthreads();

    int i = tid & 15, j = tid >> 4;
    float S = 0.f, Zs = 0.f; int p = 0;
    for (int t = 0; t < CH; t++) {
        if (stb[t]) { S = 0.f; Zs = 0.f; p = 1; }
        S  += ks_sm[t*16 + i] * vs_sm[t*16 + j];
        Zs += ksums[t];
    }
    g_Sagg[blockIdx.x*256 + tid] = S;
    if (tid == 0) { g_Zagg[blockIdx.x] = Zs; g_pagg[blockIdx.x] = p; }
}

// ---------------- pass 2: chunk-prefix scan (1 CTA, software-pipelined) --------
#define PD 16
__global__ void prefix_kernel(const float* __restrict__ s0, const float* __restrict__ z0)
{
    int tid = threadIdx.x;
    int i = tid & 15, j = tid >> 4;
    float S = s0[i*16 + j];
    float Zs = 0.f;
    #pragma unroll
    for (int l = 0; l < 16; l++) Zs += z0[l];

    float sa[PD], za[PD]; int pp[PD];
    #pragma unroll
    for (int d = 0; d < PD; d++) {
        sa[d] = g_Sagg[d*256 + tid];
        za[d] = g_Zagg[d];
        pp[d] = g_pagg[d];
    }
    for (int c = 0; c < NC; c += PD) {
        #pragma unroll
        for (int d = 0; d < PD; d++) {
            g_Spre[(c+d)*256 + tid] = S;
            if (tid == 0) g_Zpre[c+d] = Zs;
            float s_ = sa[d], z_ = za[d];
            int   p_ = pp[d];
            int n = c + d + PD;
            if (n < NC) {
                sa[d] = g_Sagg[n*256 + tid];
                za[d] = g_Zagg[n];
                pp[d] = g_pagg[n];
            }
            if (p_) { S = 0.f; Zs = 0.f; }
            S += s_; Zs += z_;
        }
    }
}

// ------- pass 3: replay + attention output + MLP layer 1 (batched, h1 split out) -------
__global__ void apply_kernel(const void* __restrict__ startp,
                             const float* __restrict__ Wm1, const float* __restrict__ bm1)
{
    __shared__ float ks[CH*16], qs[CH*16], vs[CH*16], ksums[CH], qsums[CH];
    __shared__ int stb[CH];
    __shared__ float outb[2][16][17];
    int tid = threadIdx.x;
    int c = blockIdx.x;
    int tb = c * CH;
    int mode = g_startmode;
    for (int idx = tid; idx < CH*16; idx += 256) {
        ks[idx] = g_k[tb*16 + idx];
        qs[idx] = g_q[tb*16 + idx];
        vs[idx] = g_v[tb*16 + idx];
    }
    for (int idx = tid; idx < CH; idx += 256)
        stb[idx] = read_start(startp, tb + idx, mode);
    __syncthreads();
    for (int t = tid; t < CH; t += 256) {
        float sk = 0.f, sq = 0.f;
        #pragma unroll
        for (int i = 0; i < 16; i++) { sk += ks[t*16+i]; sq += qs[t*16+i]; }
        ksums[t] = sk; qsums[t] = sq;
    }
    float wm1r[16];
    #pragma unroll
    for (int l = 0; l < 16; l++) wm1r[l] = Wm1[tid*16 + l];
    float b1 = bm1[tid];
    float S  = g_Spre[c*256 + tid];
    float Zs = g_Zpre[c];
    __syncthreads();

    int i = tid & 15, j = tid >> 4;
    for (int t0 = 0; t0 < CH; t0 += 16) {
        int buf = (t0 >> 4) & 1;
        #pragma unroll
        for (int tt = 0; tt < 16; tt++) {
            int t = t0 + tt;
            if (stb[t]) { S = 0.f; Zs = 0.f; }
            S  += ks[t*16 + i] * vs[t*16 + j];
            Zs += ksums[t];
            float pv = S * qs[t*16 + i];
            pv += __shfl_down_sync(0xffffffffu, pv, 8, 16);
            pv += __shfl_down_sync(0xffffffffu, pv, 4, 16);
            pv += __shfl_down_sync(0xffffffffu, pv, 2, 16);
            pv += __shfl_down_sync(0xffffffffu, pv, 1, 16);
            if (i == 0) {
                float denom = fmaxf(Zs * qsums[t], 1e-6f);
                outb[buf][tt][j] = pv / denom;
            }
        }
        __syncthreads();
        #pragma unroll
        for (int tt = 0; tt < 16; tt++) {
            const float* ob = outb[buf][tt];
            float h = b1;
            #pragma unroll
            for (int l = 0; l < 16; l++) h += wm1r[l] * ob[l];
            h = (h > 0.f) ? h : 0.01f * h;
            u32 ph = pack_bf16x2(h, h);
            float res = h - bf16lo_f(ph);
            u32 pl = pack_bf16x2(res, res);
            size_t off = (size_t)(tb + t0 + tt) * 256 + tid;
            g_h1hi[off] = (u16)ph;
            g_h1lo[off] = (u16)pl;
        }
    }
}

// ================= HMMA big GEMM (bf16x3 split, double-buffered cp.async) =================
// variant 0: h2(split) = leaky(h1 @ W1^T + b1)                   (K=256)
// variant 1/2: g_ypre = A1 @ W1^T + A2 @ W2^T + b1 + b2          (K=512)
#define TSTRIDE 72
#define BUFSTRIDE 73728
#define OFF_AHI   0
#define OFF_ALO   18432
#define OFF_BHI   36864
#define OFF_BLO   55296
#define OFF_BIAS  (2*BUFSTRIDE)
#define GEMM_SMEM (OFF_BIAS + 512)

__device__ __forceinline__ void gemm_stage(
    u32 sbase, int bufbase, int kc,
    const u16* __restrict__ a1hi, const u16* __restrict__ a1lo,
    const u16* __restrict__ a2hi, const u16* __restrict__ a2lo,
    const u16* __restrict__ w1hi, const u16* __restrict__ w1lo,
    const u16* __restrict__ w2hi, const u16* __restrict__ w2lo,
    int rowbase, int colbase, int tid)
{
    int koff = (kc & 3) * 64;
    const u16* Whi = (kc < 4) ? w1hi : w2hi;
    const u16* Wlo = (kc < 4) ? w1lo : w2lo;
    const u16* Ahi = (kc < 4) ? a1hi : a2hi;
    const u16* Alo = (kc < 4) ? a1lo : a2lo;
    #pragma unroll
    for (int s = 0; s < 4; s++) {
        int idx = tid + s*256;        // 0..1023
        int r = idx >> 3, sg = idx & 7;
        u32 soff = r*144 + sg*16;
        size_t geb = (size_t)(colbase + r) * 256 + koff + sg*8;
        cp_async16(sbase + bufbase + OFF_BHI + soff, Whi + geb);
        cp_async16(sbase + bufbase + OFF_BLO + soff, Wlo + geb);
        size_t gea = (size_t)(rowbase + r) * 256 + koff + sg*8;
        cp_async16(sbase + bufbase + OFF_AHI + soff, Ahi + gea);
        cp_async16(sbase + bufbase + OFF_ALO + soff, Alo + gea);
    }
}

__global__ void __launch_bounds__(256, 1)
gemm_mma_kernel(const u16* __restrict__ a1hi, const u16* __restrict__ a1lo,
                const u16* __restrict__ a2hi, const u16* __restrict__ a2lo,
                const u16* __restrict__ w1hi, const u16* __restrict__ w1lo,
                const u16* __restrict__ w2hi, const u16* __restrict__ w2lo,
                const float* __restrict__ b1p, const float* __restrict__ b2p,
                int variant)
{
    extern __shared__ char smc[];
    u32 sbase = smem_to_u32(smc);
    float* bias_sm = (float*)(smc + OFF_BIAS);

    int nchunk = (variant == 0) ? 4 : 8;

    int tid  = threadIdx.x;
    int wid  = tid >> 5;
    int lane = tid & 31;
    int colbase = blockIdx.x * 128;
    int rowbase = blockIdx.y * 128;

    int warp_m = (wid >> 1) * 32;
    int warp_n = (wid & 1) * 64;

    for (int i = tid; i < 128; i += 256)
        bias_sm[i] = b1p[colbase + i] + ((variant != 0) ? b2p[colbase + i] : 0.f);

    float acc[2][8][4];
    #pragma unroll
    for (int mi = 0; mi < 2; mi++)
        #pragma unroll
        for (int nt = 0; nt < 8; nt++)
            #pragma unroll
            for (int r = 0; r < 4; r++) acc[mi][nt][r] = 0.f;

    // prologue: stage chunk 0 into buffer 0
    gemm_stage(sbase, 0, 0, a1hi, a1lo, a2hi, a2lo, w1hi, w1lo, w2hi, w2lo,
               rowbase, colbase, tid);
    cp_commit();

    for (int kc = 0; kc < nchunk; kc++) {
        int bb = (kc & 1) * BUFSTRIDE;
        if (kc + 1 < nchunk) {
            gemm_stage(sbase, ((kc+1) & 1) * BUFSTRIDE, kc + 1,
                       a1hi, a1lo, a2hi, a2lo, w1hi, w1lo, w2hi, w2lo,
                       rowbase, colbase, tid);
            cp_commit();
            cp_wait1();     // chunk kc's loads complete (kc+1 may be in flight)
        } else {
            cp_wait0();
        }
        __syncthreads();

        // compute on buffer bb: 4 k16 steps
        #pragma unroll
        for (int ks = 0; ks < 4; ks++) {
            int k0 = ks * 16;
            int lrow = lane & 15;
            int lcol = (lane >> 4) * 16;   // byte offset of k8 half
            u32 ahi[2][4], alo[2][4];
            #pragma unroll
            for (int mi = 0; mi < 2; mi++) {
                u32 aoff = (u32)bb + (u32)(((warp_m + mi*16 + lrow)*TSTRIDE + k0) * 2) + lcol;
                ldsm_x4(ahi[mi][0], ahi[mi][1], ahi[mi][2], ahi[mi][3], sbase + OFF_AHI + aoff);
                ldsm_x4(alo[mi][0], alo[mi][1], alo[mi][2], alo[mi][3], sbase + OFF_ALO + aoff);
            }
            #pragma unroll
            for (int gg = 0; gg < 4; gg++) {
                u32 boff = (u32)bb + (u32)(((warp_n + gg*16 + lrow)*TSTRIDE + k0) * 2) + lcol;
                u32 bh[4], bl[4];
                ldsm_x4(bh[0], bh[1], bh[2], bh[3], sbase + OFF_BHI + boff);
                ldsm_x4(bl[0], bl[1], bl[2], bl[3], sbase + OFF_BLO + boff);
                #pragma unroll
                for (int mi = 0; mi < 2; mi++) {
                    #pragma unroll
                    for (int nj = 0; nj < 2; nj++) {
                        float* d = acc[mi][gg*2 + nj];
                        mma16816(d, ahi[mi], bh[nj], bh[2 + nj]);
                        mma16816(d, ahi[mi], bl[nj], bl[2 + nj]);
                        mma16816(d, alo[mi], bh[nj], bh[2 + nj]);
                    }
                }
            }
        }
        __syncthreads();   // all warps done reading bb before it is restaged
    }

    // ---------------- epilogue ----------------
    #pragma unroll
    for (int mi = 0; mi < 2; mi++) {
        int row0 = rowbase + warp_m + mi*16 + (lane >> 2);
        #pragma unroll
        for (int nt = 0; nt < 8; nt++) {
            int colL = warp_n + nt*8 + (lane & 3)*2;
            int col  = colbase + colL;
            float b0 = bias_sm[colL], b1 = bias_sm[colL + 1];
            float v0 = acc[mi][nt][0] + b0;
            float v1 = acc[mi][nt][1] + b1;
            float v2 = acc[mi][nt][2] + b0;
            float v3 = acc[mi][nt][3] + b1;
            if (variant == 0) {
                v0 = (v0 > 0.f) ? v0 : 0.01f * v0;
                v1 = (v1 > 0.f) ? v1 : 0.01f * v1;
                v2 = (v2 > 0.f) ? v2 : 0.01f * v2;
                v3 = (v3 > 0.f) ? v3 : 0.01f * v3;
                u32 hp0 = pack_bf16x2(v0, v1);
                u32 lp0 = pack_bf16x2(v0 - bf16lo_f(hp0), v1 - bf16hi_f(hp0));
                u32 hp1 = pack_bf16x2(v2, v3);
                u32 lp1 = pack_bf16x2(v2 - bf16lo_f(hp1), v3 - bf16hi_f(hp1));
                size_t o0 = (size_t)row0 * 256 + col;
                size_t o1 = (size_t)(row0 + 8) * 256 + col;
                *(u32*)(g_h2hi + o0) = hp0;
                *(u32*)(g_h2lo + o0) = lp0;
                *(u32*)(g_h2hi + o1) = hp1;
                *(u32*)(g_h2lo + o1) = lp1;
            } else {
                *(float2*)(g_ypre + (size_t)row0 * 256 + col)       = make_float2(v0, v1);
                *(float2*)(g_ypre + (size_t)(row0 + 8) * 256 + col) = make_float2(v2, v3);
            }
        }
    }
}

// ---------------- LayerNorm + residual ----------------
// mode 0: g_x1 (+split) = xext + LN(g_ypre)   (block 0)
// mode 1: outext = LN(g_ypre)                 (block 1, final output)
__global__ void ln_kernel(const float* __restrict__ xext, float* __restrict__ outext,
                          const float* __restrict__ lw, const float* __restrict__ lb, int mode)
{
    int tid = threadIdx.x;
    int lane = tid & 31, w = tid >> 5;
    int row = blockIdx.x * 8 + w;
    const float* yp = g_ypre + (size_t)row * 256;
    float vals[8];
    float s = 0.f;
    #pragma unroll
    for (int u = 0; u < 8; u++) { vals[u] = yp[lane + u*32]; s += vals[u]; }
    #pragma unroll
    for (int d = 16; d >= 1; d >>= 1) s += __shfl_xor_sync(0xffffffffu, s, d);
    float mean = s * (1.f / 256.f);
    float v2 = 0.f;
    #pragma unroll
    for (int u = 0; u < 8; u++) { float d = vals[u] - mean; v2 += d * d; }
    #pragma unroll
    for (int d = 16; d >= 1; d >>= 1) v2 += __shfl_xor_sync(0xffffffffu, v2, d);
    float rstd = rsqrtf(v2 * (1.f / 256.f) + 1e-5f);

    if (mode == 0) {
        float* o = g_x1 + (size_t)row * 256;
        const float* xr = xext + (size_t)row * 256;
        #pragma unroll
        for (int u = 0; u < 8; u++) {
            int cl = lane + u*32;
            float y = xr[cl] + (vals[u] - mean) * rstd * lw[cl] + lb[cl];
            o[cl] = y;
            u32 ph = pack_bf16x2(y, y);
            float res = y - bf16lo_f(ph);
            u32 pl = pack_bf16x2(res, res);
            size_t off = (size_t)row * 256 + cl;
            g_x1hi[off] = (u16)ph;
            g_x1lo[off] = (u16)pl;
        }
    } else {
        float* o = outext + (size_t)row * 256;
        #pragma unroll
        for (int u = 0; u < 8; u++) {
            int cl = lane + u*32;
            o[cl] = (vals[u] - mean) * rstd * lw[cl] + lb[cl];
        }
    }
}

// ---------------- launch ----------------
extern "C" void kernel_launch(void* const* d_in, const int* in_sizes, int n_in,
                              void* d_out, int out_size)
{
    const float* x     = (const float*)d_in[0];
    const void*  start = d_in[1];
    const float* s0    = (const float*)d_in[2];
    const float* z0    = (const float*)d_in[3];
    const float* Wk    = (const float*)d_in[4];
    const float* Wq    = (const float*)d_in[5];
    const float* Wv    = (const float*)d_in[6];
    const float* bv    = (const float*)d_in[7];
    const float* Wskip = (const float*)d_in[8];
    const float* bskip = (const float*)d_in[9];
    const float* Wm1   = (const float*)d_in[10];
    const float* bm1   = (const float*)d_in[11];
    const float* Wm2   = (const float*)d_in[12];
    const float* bm2   = (const float*)d_in[13];
    const float* Wm3   = (const float*)d_in[14];
    const float* bm3   = (const float*)d_in[15];
    const float* lnw   = (const float*)d_in[16];
    const float* lnb   = (const float*)d_in[17];
    float* out = (float*)d_out;

    const int kqv_smem = (256*64 + KQV_ROWS*257) * 4;
    cudaFuncSetAttribute(kqv_kernel, cudaFuncAttributeMaxDynamicSharedMemorySize, kqv_smem);
    cudaFuncSetAttribute(gemm_mma_kernel, cudaFuncAttributeMaxDynamicSharedMemorySize, GEMM_SMEM);

    static u16 *whi_p = nullptr, *wlo_p = nullptr;
    static u16 *h1hi_p, *h1lo_p, *h2hi_p, *h2lo_p, *x1hi_p, *x1lo_p, *xhi_p, *xlo_p;
    if (!whi_p) {
        cudaGetSymbolAddress((void**)&whi_p,  g_whi);
        cudaGetSymbolAddress((void**)&wlo_p,  g_wlo);
        cudaGetSymbolAddress((void**)&h1hi_p, g_h1hi);
        cudaGetSymbolAddress((void**)&h1lo_p, g_h1lo);
        cudaGetSymbolAddress((void**)&h2hi_p, g_h2hi);
        cudaGetSymbolAddress((void**)&h2lo_p, g_h2lo);
        cudaGetSymbolAddress((void**)&x1hi_p, g_x1hi);
        cudaGetSymbolAddress((void**)&x1lo_p, g_x1lo);
        cudaGetSymbolAddress((void**)&xhi_p,  g_xhi);
        cudaGetSymbolAddress((void**)&xlo_p,  g_xlo);
    }

    // weight-matrix table: [b*3+0]=Wm2_b, [b*3+1]=Wm3_b, [b*3+2]=Wskip_b
    init_kernel<<<1537 + 8192, 256>>>((const unsigned char*)start, x,
        Wm2, Wm3, Wskip, Wm2 + 65536, Wm3 + 65536, Wskip + 65536);

    for (int b = 0; b < NBLK; b++) {
        kqv_kernel<<<NC, 256, kqv_smem>>>(x, b,
            Wk + b*16*256, Wq + b*16*256, Wv + b*16*256, bv + b*16, start);
        prefix_kernel<<<1, 256>>>(s0 + b*256, z0 + b*16);
        apply_kernel<<<NC, 256>>>(start, Wm1 + b*256*16, bm1 + b*256);

        const u16* wm2hi = whi_p + (b*3 + 0)*65536;
        const u16* wm2lo = wlo_p + (b*3 + 0)*65536;
        const u16* wm3hi = whi_p + (b*3 + 1)*65536;
        const u16* wm3lo = wlo_p + (b*3 + 1)*65536;
        const u16* wskhi = whi_p + (b*3 + 2)*65536;
        const u16* wsklo = wlo_p + (b*3 + 2)*65536;

        // h2 = leaky(h1 @ Wm2^T + bm2)
        gemm_mma_kernel<<<dim3(2, TT/128), 256, GEMM_SMEM>>>(
            h1hi_p, h1lo_p, h1hi_p, h1lo_p,
            wm2hi, wm2lo, wm2hi, wm2lo, bm2 + b*256, bm2 + b*256, 0);
        // ypre = h2 @ Wm3^T + A2 @ Wskip^T + bm3 + bskip
        gemm_mma_kernel<<<dim3(2, TT/128), 256, GEMM_SMEM>>>(
            h2hi_p, h2lo_p,
            (b == 0) ? xhi_p : x1hi_p, (b == 0) ? xlo_p : x1lo_p,
            wm3hi, wm3lo, wskhi, wsklo, bm3 + b*256, bskip + b*256,
            (b == 0) ? 1 : 2);
        ln_kernel<<<TT/8, 256>>>(x, out, lnw + b*256, lnb + b*256, (b == 0) ? 0 : 1);
    }
}

// round 8
// speedup vs baseline: 1.0292x; 1.0292x over previous
#include <cuda_runtime.h>
#include <cstdint>

typedef unsigned long long u64;
typedef unsigned int u32;
typedef unsigned short u16;

// Problem constants
#define TT   32768
#define DD   256
#define HH   256
#define KV   16
#define CH   128          // scan chunk length
#define NC   (TT/CH)      // 256 chunks
#define NG   16           // prefix groups (16 chunks each)
#define NBLK 2

// ---------------- device scratch (no allocations allowed) ----------------
__device__ float g_k[TT*KV];
__device__ float g_q[TT*KV];
__device__ float g_v[TT*KV];
__device__ float g_Sagg[NC*256];
__device__ float g_Zagg[NC];
__device__ int   g_pagg[NC];
__device__ float g_Sloc[NC*256];   // local (within-group) exclusive prefixes
__device__ float g_Zloc[NC];
__device__ int   g_ploc[NC];
__device__ float g_SG[NG*256];     // group aggregates
__device__ float g_ZG[NG];
__device__ int   g_pG[NG];
__device__ float g_SGP[NG*256];    // group exclusive prefixes (incl s0 init)
__device__ float g_ZGP[NG];
__device__ float g_ypre[TT*HH];
__device__ float g_x1[TT*HH];
__device__ int   g_startmode;   // 0=u8 bool, 1=int32, 2=float32

// bf16 hi/lo split operand storage
__device__ u16 g_h1hi[TT*HH];
__device__ u16 g_h1lo[TT*HH];
__device__ u16 g_h2hi[TT*HH];
__device__ u16 g_h2lo[TT*HH];
__device__ u16 g_x1hi[TT*HH];
__device__ u16 g_x1lo[TT*HH];
__device__ u16 g_xhi[TT*DD];
__device__ u16 g_xlo[TT*DD];
__device__ u16 g_whi[6*65536];  // [mat][256][256]: per block {Wm2, Wm3, Wskip}
__device__ u16 g_wlo[6*65536];

// ---------------- f32x2 packed helpers ----------------
__device__ __forceinline__ u64 dup2(float x) {
    u64 r;
    asm("mov.b64 %0, {%1, %1};" : "=l"(r) : "r"(__float_as_uint(x)));
    return r;
}
__device__ __forceinline__ u64 fma2(u64 a, u64 b, u64 c) {
    u64 d;
    asm("fma.rn.f32x2 %0, %1, %2, %3;" : "=l"(d) : "l"(a), "l"(b), "l"(c));
    return d;
}
__device__ __forceinline__ void unpack2(u64 v, float& lo, float& hi) {
    u32 a, b;
    asm("mov.b64 {%0, %1}, %2;" : "=r"(a), "=r"(b) : "l"(v));
    lo = __uint_as_float(a); hi = __uint_as_float(b);
}

__device__ __forceinline__ float phi_fn(float t) {
    return (t > 0.f) ? (1.f + t) : __expf(t);
}

__device__ __forceinline__ int read_start(const void* p, int t, int mode) {
    if (mode == 0) return ((const unsigned char*)p)[t] != 0;
    if (mode == 1) return ((const int*)p)[t] != 0;
    return ((const float*)p)[t] != 0.f;
}

// ---------------- bf16 pack helpers ----------------
__device__ __forceinline__ u32 pack_bf16x2(float lo, float hi) {
    u32 r;
    asm("cvt.rn.bf16x2.f32 %0, %1, %2;" : "=r"(r) : "f"(hi), "f"(lo));
    return r;
}
__device__ __forceinline__ float bf16lo_f(u32 p) { return __uint_as_float(p << 16); }
__device__ __forceinline__ float bf16hi_f(u32 p) { return __uint_as_float(p & 0xffff0000u); }

__device__ __forceinline__ u32 smem_to_u32(const void* smem_ptr) {
    u32 addr;
    asm("{ .reg .u64 tmp; cvta.to.shared.u64 tmp, %1; cvt.u32.u64 %0, tmp; }"
        : "=r"(addr) : "l"(smem_ptr));
    return addr;
}

__device__ __forceinline__ void cp_async16(u32 saddr, const void* gptr) {
    asm volatile("cp.async.cg.shared.global [%0], [%1], 16;" :: "r"(saddr), "l"(gptr));
}
__device__ __forceinline__ void cp_async_commit_wait() {
    asm volatile("cp.async.commit_group;" ::: "memory");
    asm volatile("cp.async.wait_group 0;" ::: "memory");
}

__device__ __forceinline__ void ldsm_x4(u32& r0, u32& r1, u32& r2, u32& r3, u32 addr) {
    asm volatile("ldmatrix.sync.aligned.m8n8.x4.shared.b16 {%0,%1,%2,%3}, [%4];"
        : "=r"(r0), "=r"(r1), "=r"(r2), "=r"(r3) : "r"(addr));
}

__device__ __forceinline__ void mma16816(float* d, const u32* a, u32 b0, u32 b1) {
    asm volatile(
        "mma.sync.aligned.m16n8k16.row.col.f32.bf16.bf16.f32 "
        "{%0,%1,%2,%3}, {%4,%5,%6,%7}, {%8,%9}, {%0,%1,%2,%3};"
        : "+f"(d[0]), "+f"(d[1]), "+f"(d[2]), "+f"(d[3])
        : "r"(a[0]), "r"(a[1]), "r"(a[2]), "r"(a[3]), "r"(b0), "r"(b1));
}

// ---------------- init: detect + weight split + x split ----------------
__global__ void init_kernel(const unsigned char* __restrict__ p,
                            const float* __restrict__ x,
                            const float* __restrict__ w0, const float* __restrict__ w1,
                            const float* __restrict__ w2, const float* __restrict__ w3,
                            const float* __restrict__ w4, const float* __restrict__ w5)
{
    int tid = threadIdx.x;
    int bid = blockIdx.x;
    if (bid < 1536) {
        int mat = bid >> 8;
        int idx = ((bid & 255) << 8) | tid;
        const float* src;
        switch (mat) {
            case 0: src = w0; break;
            case 1: src = w1; break;
            case 2: src = w2; break;
            case 3: src = w3; break;
            case 4: src = w4; break;
            default: src = w5; break;
        }
        float f = src[idx];
        u32 ph = pack_bf16x2(f, f);
        float r = f - bf16lo_f(ph);
        u32 pl = pack_bf16x2(r, r);
        g_whi[mat*65536 + idx] = (u16)ph;
        g_wlo[mat*65536 + idx] = (u16)pl;
    } else if (bid == 1536) {
        __shared__ int cnt1, cnt3f;
        if (tid == 0) { cnt1 = 0; cnt3f = 0; }
        __syncthreads();
        int l1 = 0, l3 = 0;
        for (int idx = tid; idx < 4096; idx += 256) {
            unsigned char b = p[idx];
            if ((idx & 3) != 0 && b != 0) l1++;
            if ((idx & 3) == 3 && b == 0x3F) l3++;
        }
        atomicAdd(&cnt1, l1); atomicAdd(&cnt3f, l3);
        __syncthreads();
        if (tid == 0) g_startmode = (cnt3f > 0) ? 2 : ((cnt1 > 0) ? 0 : 1);
    } else {
        int base = (bid - 1537) * 1024 + tid * 4;
        float4 v = *(const float4*)(x + base);
        u32 h0 = pack_bf16x2(v.x, v.y);
        u32 h1 = pack_bf16x2(v.z, v.w);
        u32 l0 = pack_bf16x2(v.x - bf16lo_f(h0), v.y - bf16hi_f(h0));
        u32 l1 = pack_bf16x2(v.z - bf16lo_f(h1), v.w - bf16hi_f(h1));
        *(u32*)(g_xhi + base)     = h0;
        *(u32*)(g_xhi + base + 2) = h1;
        *(u32*)(g_xlo + base)     = l0;
        *(u32*)(g_xlo + base + 2) = l1;
    }
}

// ---------------- k,q,v projections + fused chunk aggregate ----------------
#define KQV_ROWS 128
__global__ void kqv_kernel(const float* __restrict__ xext, int use_x1,
                           const float* __restrict__ Wk, const float* __restrict__ Wq,
                           const float* __restrict__ Wv, const float* __restrict__ bv,
                           const void* __restrict__ startp)
{
    extern __shared__ float sm[];
    float* wt = sm;                  // 256*64
    float* xs = sm + 256*64;         // 128*257 (reused after compute)
    const float* x = use_x1 ? g_x1 : xext;
    int tid = threadIdx.x;
    int base = blockIdx.x * KQV_ROWS;
    int mode = g_startmode;

    for (int idx = tid; idx < 48*256; idx += 256) {
        int o = idx >> 8, c = idx & 255;
        float w;
        if (o < 16)      w = Wk[o*256 + c];
        else if (o < 32) w = Wq[(o-16)*256 + c];
        else             w = Wv[(o-32)*256 + c];
        int gg = o / 6, mm = o - gg*6;
        wt[c*64 + gg*8 + mm] = w;
    }
    {
        const float* xg = x + (size_t)base * 256;
        for (int idx = tid; idx < KQV_ROWS*64; idx += 256) {
            int r = idx >> 6, c4 = (idx & 63) * 4;
            float4 v = *(const float4*)(xg + r*256 + c4);
            float* d = xs + r*257 + c4;
            d[0] = v.x; d[1] = v.y; d[2] = v.z; d[3] = v.w;
        }
    }
    __syncthreads();

    int r0 = tid & 31;
    int g  = tid >> 5;
    u64 acc[4][3];
    #pragma unroll
    for (int rr = 0; rr < 4; rr++)
        #pragma unroll
        for (int pi = 0; pi < 3; pi++) acc[rr][pi] = 0ull;

    const float* wbase = wt + g*8;
    #pragma unroll 2
    for (int c = 0; c < 256; c++) {
        const float* wr = wbase + c*64;
        u64 w0 = *(const u64*)(wr + 0);
        u64 w1 = *(const u64*)(wr + 2);
        u64 w2 = *(const u64*)(wr + 4);
        #pragma unroll
        for (int rr = 0; rr < 4; rr++) {
            float xv = xs[(r0 + rr*32)*257 + c];
            u64 xd = dup2(xv);
            acc[rr][0] = fma2(xd, w0, acc[rr][0]);
            acc[rr][1] = fma2(xd, w1, acc[rr][1]);
            acc[rr][2] = fma2(xd, w2, acc[rr][2]);
        }
    }
    __syncthreads();   // xs reuse

    float* ks_sm = xs;
    float* vs_sm = xs + 2048;
    float* ksums = xs + 4096;
    int*   stb   = (int*)(xs + 4224);

    #pragma unroll
    for (int rr = 0; rr < 4; rr++) {
        int lr = r0 + rr*32;
        int t  = base + lr;
        #pragma unroll
        for (int pi = 0; pi < 3; pi++) {
            float lo, hi;
            unpack2(acc[rr][pi], lo, hi);
            #pragma unroll
            for (int h = 0; h < 2; h++) {
                int o = g*6 + pi*2 + h;
                float val = h ? hi : lo;
                if (o < 16) {
                    float pk = phi_fn(val);
                    g_k[t*16 + o] = pk;
                    ks_sm[lr*16 + o] = pk;
                } else if (o < 32) {
                    g_q[t*16 + (o-16)] = phi_fn(val);
                } else {
                    float vv = val + bv[o-32];
                    g_v[t*16 + (o-32)] = vv;
                    vs_sm[lr*16 + (o-32)] = vv;
                }
            }
        }
    }
    __syncthreads();

    if (tid < 128) {
        float s = 0.f;
        #pragma unroll
        for (int i = 0; i < 16; i++) s += ks_sm[tid*16 + i];
        ksums[tid] = s;
        stb[tid] = read_start(startp, base + tid, mode);
    }
    __syncthreads();

    int i = tid & 15, j = tid >> 4;
    float S = 0.f, Zs = 0.f; int p = 0;
    for (int t = 0; t < CH; t++) {
        if (stb[t]) { S = 0.f; Zs = 0.f; p = 1; }
        S  += ks_sm[t*16 + i] * vs_sm[t*16 + j];
        Zs += ksums[t];
    }
    g_Sagg[blockIdx.x*256 + tid] = S;
    if (tid == 0) { g_Zagg[blockIdx.x] = Zs; g_pagg[blockIdx.x] = p; }
}

// ---------------- prefix level 1: 16 CTAs, 16 chunks each ----------------
__global__ void prefix1_kernel()
{
    int tid = threadIdx.x;
    int g = blockIdx.x;
    float S = 0.f, Zs = 0.f; int p = 0;
    #pragma unroll 4
    for (int d = 0; d < 16; d++) {
        int c = g*16 + d;
        g_Sloc[c*256 + tid] = S;
        if (tid == 0) { g_Zloc[c] = Zs; g_ploc[c] = p; }
        float sa = g_Sagg[c*256 + tid];
        float za = g_Zagg[c];
        int   pa = g_pagg[c];
        if (pa) { S = 0.f; Zs = 0.f; }
        S += sa; Zs += za; p |= pa;
    }
    g_SG[g*256 + tid] = S;
    if (tid == 0) { g_ZG[g] = Zs; g_pG[g] = p; }
}

// ---------------- prefix level 2: scan 16 group aggregates ----------------
__global__ void prefix2_kernel(const float* __restrict__ s0, const float* __restrict__ z0)
{
    int tid = threadIdx.x;
    int i = tid & 15, j = tid >> 4;
    float S = s0[i*16 + j];
    float Zs = 0.f;
    #pragma unroll
    for (int l = 0; l < 16; l++) Zs += z0[l];
    for (int g = 0; g < NG; g++) {
        g_SGP[g*256 + tid] = S;
        if (tid == 0) g_ZGP[g] = Zs;
        float sa = g_SG[g*256 + tid];
        float za = g_ZG[g];
        int   pa = g_pG[g];
        if (pa) { S = 0.f; Zs = 0.f; }
        S += sa; Zs += za;
    }
}

// ------- pass 3: replay + attention output + MLP layer 1 -------
__global__ void apply_kernel(const void* __restrict__ startp,
                             const float* __restrict__ Wm1, const float* __restrict__ bm1)
{
    __shared__ float ks[CH*16], qs[CH*16], vs[CH*16], ksums[CH], qsums[CH];
    __shared__ int stb[CH];
    __shared__ float outb[2][16][17];
    int tid = threadIdx.x;
    int c = blockIdx.x;
    int tb = c * CH;
    int mode = g_startmode;
    for (int idx = tid; idx < CH*16; idx += 256) {
        ks[idx] = g_k[tb*16 + idx];
        qs[idx] = g_q[tb*16 + idx];
        vs[idx] = g_v[tb*16 + idx];
    }
    for (int idx = tid; idx < CH; idx += 256)
        stb[idx] = read_start(startp, tb + idx, mode);
    __syncthreads();
    for (int t = tid; t < CH; t += 256) {
        float sk = 0.f, sq = 0.f;
        #pragma unroll
        for (int i = 0; i < 16; i++) { sk += ks[t*16+i]; sq += qs[t*16+i]; }
        ksums[t] = sk; qsums[t] = sq;
    }
    float wm1r[16];
    #pragma unroll
    for (int l = 0; l < 16; l++) wm1r[l] = Wm1[tid*16 + l];
    float b1 = bm1[tid];
    // combine local prefix with group prefix
    int grp = c >> 4;
    float Sl = g_Sloc[c*256 + tid];
    int   pl = g_ploc[c];
    float S  = pl ? Sl : (g_SGP[grp*256 + tid] + Sl);
    float Zl = g_Zloc[c];
    float Zs = pl ? Zl : (g_ZGP[grp] + Zl);
    __syncthreads();

    int i = tid & 15, j = tid >> 4;
    for (int t0 = 0; t0 < CH; t0 += 16) {
        int buf = (t0 >> 4) & 1;
        #pragma unroll
        for (int tt = 0; tt < 16; tt++) {
            int t = t0 + tt;
            if (stb[t]) { S = 0.f; Zs = 0.f; }
            S  += ks[t*16 + i] * vs[t*16 + j];
            Zs += ksums[t];
            float pv = S * qs[t*16 + i];
            pv += __shfl_down_sync(0xffffffffu, pv, 8, 16);
            pv += __shfl_down_sync(0xffffffffu, pv, 4, 16);
            pv += __shfl_down_sync(0xffffffffu, pv, 2, 16);
            pv += __shfl_down_sync(0xffffffffu, pv, 1, 16);
            if (i == 0) {
                float denom = fmaxf(Zs * qsums[t], 1e-6f);
                outb[buf][tt][j] = pv / denom;
            }
        }
        __syncthreads();
        #pragma unroll
        for (int tt = 0; tt < 16; tt++) {
            const float* ob = outb[buf][tt];
            float h = b1;
            #pragma unroll
            for (int l = 0; l < 16; l++) h += wm1r[l] * ob[l];
            h = (h > 0.f) ? h : 0.01f * h;
            u32 ph = pack_bf16x2(h, h);
            float res = h - bf16lo_f(ph);
            u32 plp = pack_bf16x2(res, res);
            size_t off = (size_t)(tb + t0 + tt) * 256 + tid;
            g_h1hi[off] = (u16)ph;
            g_h1lo[off] = (u16)plp;
        }
    }
}

// ===== HMMA big GEMM: bf16x3 split, cp.async serial staging, K-chunk 64, 2 CTA/SM =====
// variant 0: h2(split) = leaky(h1 @ W1^T + b1)                   (K=256, 4 chunks)
// variant 1/2: g_ypre = A1 @ W1^T + A2 @ W2^T + b1 + b2          (K=512, 8 chunks)
#define TSTRIDE 72
#define OFF_AHI   0
#define OFF_ALO   18432
#define OFF_BHI   36864
#define OFF_BLO   55296
#define OFF_BIAS  73728
#define GEMM_SMEM (73728 + 512)

__global__ void __launch_bounds__(256, 2)
gemm_mma_kernel(const u16* __restrict__ a1hi, const u16* __restrict__ a1lo,
                const u16* __restrict__ a2hi, const u16* __restrict__ a2lo,
                const u16* __restrict__ w1hi, const u16* __restrict__ w1lo,
                const u16* __restrict__ w2hi, const u16* __restrict__ w2lo,
                const float* __restrict__ b1p, const float* __restrict__ b2p,
                int variant)
{
    extern __shared__ char smc[];
    u32 sbase = smem_to_u32(smc);
    float* bias_sm = (float*)(smc + OFF_BIAS);

    int nchunk = (variant == 0) ? 4 : 8;

    int tid  = threadIdx.x;
    int wid  = tid >> 5;
    int lane = tid & 31;
    int colbase = blockIdx.x * 128;
    int rowbase = blockIdx.y * 128;

    int warp_m = (wid >> 1) * 32;
    int warp_n = (wid & 1) * 64;

    for (int i = tid; i < 128; i += 256)
        bias_sm[i] = b1p[colbase + i] + ((variant != 0) ? b2p[colbase + i] : 0.f);

    float acc[2][8][4];
    #pragma unroll
    for (int mi = 0; mi < 2; mi++)
        #pragma unroll
        for (int nt = 0; nt < 8; nt++)
            #pragma unroll
            for (int r = 0; r < 4; r++) acc[mi][nt][r] = 0.f;

    for (int kc = 0; kc < nchunk; kc++) {
        int koff = (kc & 3) * 64;
        __syncthreads();   // previous chunk's compute done before overwrite

        const u16* Whi = (kc < 4) ? w1hi : w2hi;
        const u16* Wlo = (kc < 4) ? w1lo : w2lo;
        const u16* Ahi = (kc < 4) ? a1hi : a2hi;
        const u16* Alo = (kc < 4) ? a1lo : a2lo;

        #pragma unroll
        for (int s = 0; s < 4; s++) {
            int idx = tid + s*256;        // 0..1023
            int r = idx >> 3, sg = idx & 7;
            u32 soff = r*144 + sg*16;     // 144 = 9*16, cp.async-aligned
            size_t geb = (size_t)(colbase + r) * 256 + koff + sg*8;
            cp_async16(sbase + OFF_BHI + soff, Whi + geb);
            cp_async16(sbase + OFF_BLO + soff, Wlo + geb);
            size_t gea = (size_t)(rowbase + r) * 256 + koff + sg*8;
            cp_async16(sbase + OFF_AHI + soff, Ahi + gea);
            cp_async16(sbase + OFF_ALO + soff, Alo + gea);
        }
        cp_async_commit_wait();
        __syncthreads();

        // compute: 4 k16 steps
        #pragma unroll
        for (int ks = 0; ks < 4; ks++) {
            int k0 = ks * 16;
            int lrow = lane & 15;
            int lcol = (lane >> 4) * 16;   // byte offset of k8 half
            u32 ahi[2][4], alo[2][4];
            #pragma unroll
            for (int mi = 0; mi < 2; mi++) {
                u32 aoff = (u32)(((warp_m + mi*16 + lrow)*TSTRIDE + k0) * 2) + lcol;
                ldsm_x4(ahi[mi][0], ahi[mi][1], ahi[mi][2], ahi[mi][3], sbase + OFF_AHI + aoff);
                ldsm_x4(alo[mi][0], alo[mi][1], alo[mi][2], alo[mi][3], sbase + OFF_ALO + aoff);
            }
            #pragma unroll
            for (int gg = 0; gg < 4; gg++) {
                u32 boff = (u32)(((warp_n + gg*16 + lrow)*TSTRIDE + k0) * 2) + lcol;
                u32 bh[4], bl[4];
                ldsm_x4(bh[0], bh[1], bh[2], bh[3], sbase + OFF_BHI + boff);
                ldsm_x4(bl[0], bl[1], bl[2], bl[3], sbase + OFF_BLO + boff);
                #pragma unroll
                for (int mi = 0; mi < 2; mi++) {
                    #pragma unroll
                    for (int nj = 0; nj < 2; nj++) {
                        float* d = acc[mi][gg*2 + nj];
                        mma16816(d, ahi[mi], bh[nj], bh[2 + nj]);
                        mma16816(d, ahi[mi], bl[nj], bl[2 + nj]);
                        mma16816(d, alo[mi], bh[nj], bh[2 + nj]);
                    }
                }
            }
        }
    }

    // ---------------- epilogue ----------------
    #pragma unroll
    for (int mi = 0; mi < 2; mi++) {
        int row0 = rowbase + warp_m + mi*16 + (lane >> 2);
        #pragma unroll
        for (int nt = 0; nt < 8; nt++) {
            int colL = warp_n + nt*8 + (lane & 3)*2;
            int col  = colbase + colL;
            float b0 = bias_sm[colL], b1 = bias_sm[colL + 1];
            float v0 = acc[mi][nt][0] + b0;
            float v1 = acc[mi][nt][1] + b1;
            float v2 = acc[mi][nt][2] + b0;
            float v3 = acc[mi][nt][3] + b1;
            if (variant == 0) {
                v0 = (v0 > 0.f) ? v0 : 0.01f * v0;
                v1 = (v1 > 0.f) ? v1 : 0.01f * v1;
                v2 = (v2 > 0.f) ? v2 : 0.01f * v2;
                v3 = (v3 > 0.f) ? v3 : 0.01f * v3;
                u32 hp0 = pack_bf16x2(v0, v1);
                u32 lp0 = pack_bf16x2(v0 - bf16lo_f(hp0), v1 - bf16hi_f(hp0));
                u32 hp1 = pack_bf16x2(v2, v3);
                u32 lp1 = pack_bf16x2(v2 - bf16lo_f(hp1), v3 - bf16hi_f(hp1));
                size_t o0 = (size_t)row0 * 256 + col;
                size_t o1 = (size_t)(row0 + 8) * 256 + col;
                *(u32*)(g_h2hi + o0) = hp0;
                *(u32*)(g_h2lo + o0) = lp0;
                *(u32*)(g_h2hi + o1) = hp1;
                *(u32*)(g_h2lo + o1) = lp1;
            } else {
                *(float2*)(g_ypre + (size_t)row0 * 256 + col)       = make_float2(v0, v1);
                *(float2*)(g_ypre + (size_t)(row0 + 8) * 256 + col) = make_float2(v2, v3);
            }
        }
    }
}

// ---------------- LayerNorm + residual ----------------
__global__ void ln_kernel(const float* __restrict__ xext, float* __restrict__ outext,
                          const float* __restrict__ lw, const float* __restrict__ lb, int mode)
{
    int tid = threadIdx.x;
    int lane = tid & 31, w = tid >> 5;
    int row = blockIdx.x * 8 + w;
    const float* yp = g_ypre + (size_t)row * 256;
    float vals[8];
    float s = 0.f;
    #pragma unroll
    for (int u = 0; u < 8; u++) { vals[u] = yp[lane + u*32]; s += vals[u]; }
    #pragma unroll
    for (int d = 16; d >= 1; d >>= 1) s += __shfl_xor_sync(0xffffffffu, s, d);
    float mean = s * (1.f / 256.f);
    float v2 = 0.f;
    #pragma unroll
    for (int u = 0; u < 8; u++) { float d = vals[u] - mean; v2 += d * d; }
    #pragma unroll
    for (int d = 16; d >= 1; d >>= 1) v2 += __shfl_xor_sync(0xffffffffu, v2, d);
    float rstd = rsqrtf(v2 * (1.f / 256.f) + 1e-5f);

    if (mode == 0) {
        float* o = g_x1 + (size_t)row * 256;
        const float* xr = xext + (size_t)row * 256;
        #pragma unroll
        for (int u = 0; u < 8; u++) {
            int cl = lane + u*32;
            float y = xr[cl] + (vals[u] - mean) * rstd * lw[cl] + lb[cl];
            o[cl] = y;
            u32 ph = pack_bf16x2(y, y);
            float res = y - bf16lo_f(ph);
            u32 pl = pack_bf16x2(res, res);
            size_t off = (size_t)row * 256 + cl;
            g_x1hi[off] = (u16)ph;
            g_x1lo[off] = (u16)pl;
        }
    } else {
        float* o = outext + (size_t)row * 256;
        #pragma unroll
        for (int u = 0; u < 8; u++) {
            int cl = lane + u*32;
            o[cl] = (vals[u] - mean) * rstd * lw[cl] + lb[cl];
        }
    }
}

// ---------------- launch ----------------
extern "C" void kernel_launch(void* const* d_in, const int* in_sizes, int n_in,
                              void* d_out, int out_size)
{
    const float* x     = (const float*)d_in[0];
    const void*  start = d_in[1];
    const float* s0    = (const float*)d_in[2];
    const float* z0    = (const float*)d_in[3];
    const float* Wk    = (const float*)d_in[4];
    const float* Wq    = (const float*)d_in[5];
    const float* Wv    = (const float*)d_in[6];
    const float* bv    = (const float*)d_in[7];
    const float* Wskip = (const float*)d_in[8];
    const float* bskip = (const float*)d_in[9];
    const float* Wm1   = (const float*)d_in[10];
    const float* bm1   = (const float*)d_in[11];
    const float* Wm2   = (const float*)d_in[12];
    const float* bm2   = (const float*)d_in[13];
    const float* Wm3   = (const float*)d_in[14];
    const float* bm3   = (const float*)d_in[15];
    const float* lnw   = (const float*)d_in[16];
    const float* lnb   = (const float*)d_in[17];
    float* out = (float*)d_out;

    const int kqv_smem = (256*64 + KQV_ROWS*257) * 4;
    cudaFuncSetAttribute(kqv_kernel, cudaFuncAttributeMaxDynamicSharedMemorySize, kqv_smem);
    cudaFuncSetAttribute(gemm_mma_kernel, cudaFuncAttributeMaxDynamicSharedMemorySize, GEMM_SMEM);

    static u16 *whi_p = nullptr, *wlo_p = nullptr;
    static u16 *h1hi_p, *h1lo_p, *h2hi_p, *h2lo_p, *x1hi_p, *x1lo_p, *xhi_p, *xlo_p;
    if (!whi_p) {
        cudaGetSymbolAddress((void**)&whi_p,  g_whi);
        cudaGetSymbolAddress((void**)&wlo_p,  g_wlo);
        cudaGetSymbolAddress((void**)&h1hi_p, g_h1hi);
        cudaGetSymbolAddress((void**)&h1lo_p, g_h1lo);
        cudaGetSymbolAddress((void**)&h2hi_p, g_h2hi);
        cudaGetSymbolAddress((void**)&h2lo_p, g_h2lo);
        cudaGetSymbolAddress((void**)&x1hi_p, g_x1hi);
        cudaGetSymbolAddress((void**)&x1lo_p, g_x1lo);
        cudaGetSymbolAddress((void**)&xhi_p,  g_xhi);
        cudaGetSymbolAddress((void**)&xlo_p,  g_xlo);
    }

    init_kernel<<<1537 + 8192, 256>>>((const unsigned char*)start, x,
        Wm2, Wm3, Wskip, Wm2 + 65536, Wm3 + 65536, Wskip + 65536);

    for (int b = 0; b < NBLK; b++) {
        kqv_kernel<<<NC, 256, kqv_smem>>>(x, b,
            Wk + b*16*256, Wq + b*16*256, Wv + b*16*256, bv + b*16, start);
        prefix1_kernel<<<NG, 256>>>();
        prefix2_kernel<<<1, 256>>>(s0 + b*256, z0 + b*16);
        apply_kernel<<<NC, 256>>>(start, Wm1 + b*256*16, bm1 + b*256);

        const u16* wm2hi = whi_p + (b*3 + 0)*65536;
        const u16* wm2lo = wlo_p + (b*3 + 0)*65536;
        const u16* wm3hi = whi_p + (b*3 + 1)*65536;
        const u16* wm3lo = wlo_p + (b*3 + 1)*65536;
        const u16* wskhi = whi_p + (b*3 + 2)*65536;
        const u16* wsklo = wlo_p + (b*3 + 2)*65536;

        // h2 = leaky(h1 @ Wm2^T + bm2)
        gemm_mma_kernel<<<dim3(2, TT/128), 256, GEMM_SMEM>>>(
            h1hi_p, h1lo_p, h1hi_p, h1lo_p,
            wm2hi, wm2lo, wm2hi, wm2lo, bm2 + b*256, bm2 + b*256, 0);
        // ypre = h2 @ Wm3^T + A2 @ Wskip^T + bm3 + bskip
        gemm_mma_kernel<<<dim3(2, TT/128), 256, GEMM_SMEM>>>(
            h2hi_p, h2lo_p,
            (b == 0) ? xhi_p : x1hi_p, (b == 0) ? xlo_p : x1lo_p,
            wm3hi, wm3lo, wskhi, wsklo, bm3 + b*256, bskip + b*256,
            (b == 0) ? 1 : 2);
        ln_kernel<<<TT/8, 256>>>(x, out, lnw + b*256, lnb + b*256, (b == 0) ? 0 : 1);
    }
}

// round 9
// speedup vs baseline: 1.1242x; 1.0924x over previous
#include <cuda_runtime.h>
#include <cstdint>

typedef unsigned long long u64;
typedef unsigned int u32;
typedef unsigned short u16;

// Problem constants
#define TT   32768
#define DD   256
#define HH   256
#define KV   16
#define CH   128          // scan chunk length
#define NC   (TT/CH)      // 256 chunks
#define NG   16           // prefix groups (16 chunks each)
#define NBLK 2

// ---------------- device scratch (no allocations allowed) ----------------
__device__ float g_k[TT*KV];
__device__ float g_q[TT*KV];
__device__ float g_v[TT*KV];
__device__ float g_Sagg[NC*256];
__device__ float g_Zagg[NC];
__device__ int   g_pagg[NC];
__device__ float g_Sloc[NC*256];   // local (within-group) exclusive prefixes
__device__ float g_Zloc[NC];
__device__ int   g_ploc[NC];
__device__ float g_SG[NG*256];     // group aggregates
__device__ float g_ZG[NG];
__device__ int   g_pG[NG];
__device__ float g_SGP[NG*256];    // group exclusive prefixes (incl s0 init)
__device__ float g_ZGP[NG];
__device__ float g_ypre[TT*HH];
__device__ float g_x1[TT*HH];
__device__ int   g_startmode;   // 0=u8 bool, 1=int32, 2=float32

// bf16 hi/lo split operand storage
__device__ u16 g_h1hi[TT*HH];
__device__ u16 g_h1lo[TT*HH];
__device__ u16 g_h2hi[TT*HH];
__device__ u16 g_h2lo[TT*HH];
__device__ u16 g_x1hi[TT*HH];
__device__ u16 g_x1lo[TT*HH];
__device__ u16 g_xhi[TT*DD];
__device__ u16 g_xlo[TT*DD];
__device__ u16 g_whi[6*65536];  // [mat][256][256]: per block {Wm2, Wm3, Wskip}
__device__ u16 g_wlo[6*65536];

// ---------------- f32x2 packed helpers ----------------
__device__ __forceinline__ u64 dup2(float x) {
    u64 r;
    asm("mov.b64 %0, {%1, %1};" : "=l"(r) : "r"(__float_as_uint(x)));
    return r;
}
__device__ __forceinline__ u64 fma2(u64 a, u64 b, u64 c) {
    u64 d;
    asm("fma.rn.f32x2 %0, %1, %2, %3;" : "=l"(d) : "l"(a), "l"(b), "l"(c));
    return d;
}
__device__ __forceinline__ void unpack2(u64 v, float& lo, float& hi) {
    u32 a, b;
    asm("mov.b64 {%0, %1}, %2;" : "=r"(a), "=r"(b) : "l"(v));
    lo = __uint_as_float(a); hi = __uint_as_float(b);
}

__device__ __forceinline__ float phi_fn(float t) {
    return (t > 0.f) ? (1.f + t) : __expf(t);
}

__device__ __forceinline__ int read_start(const void* p, int t, int mode) {
    if (mode == 0) return ((const unsigned char*)p)[t] != 0;
    if (mode == 1) return ((const int*)p)[t] != 0;
    return ((const float*)p)[t] != 0.f;
}

// ---------------- bf16 pack helpers ----------------
__device__ __forceinline__ u32 pack_bf16x2(float lo, float hi) {
    u32 r;
    asm("cvt.rn.bf16x2.f32 %0, %1, %2;" : "=r"(r) : "f"(hi), "f"(lo));
    return r;
}
__device__ __forceinline__ float bf16lo_f(u32 p) { return __uint_as_float(p << 16); }
__device__ __forceinline__ float bf16hi_f(u32 p) { return __uint_as_float(p & 0xffff0000u); }

__device__ __forceinline__ u32 smem_to_u32(const void* smem_ptr) {
    u32 addr;
    asm("{ .reg .u64 tmp; cvta.to.shared.u64 tmp, %1; cvt.u32.u64 %0, tmp; }"
        : "=r"(addr) : "l"(smem_ptr));
    return addr;
}

__device__ __forceinline__ void cp_async16(u32 saddr, const void* gptr) {
    asm volatile("cp.async.cg.shared.global [%0], [%1], 16;" :: "r"(saddr), "l"(gptr));
}
__device__ __forceinline__ void cp_commit() {
    asm volatile("cp.async.commit_group;" ::: "memory");
}
__device__ __forceinline__ void cp_wait0() {
    asm volatile("cp.async.wait_group 0;" ::: "memory");
}
__device__ __forceinline__ void cp_wait1() {
    asm volatile("cp.async.wait_group 1;" ::: "memory");
}

__device__ __forceinline__ void ldsm_x4(u32& r0, u32& r1, u32& r2, u32& r3, u32 addr) {
    asm volatile("ldmatrix.sync.aligned.m8n8.x4.shared.b16 {%0,%1,%2,%3}, [%4];"
        : "=r"(r0), "=r"(r1), "=r"(r2), "=r"(r3) : "r"(addr));
}

__device__ __forceinline__ void mma16816(float* d, const u32* a, u32 b0, u32 b1) {
    asm volatile(
        "mma.sync.aligned.m16n8k16.row.col.f32.bf16.bf16.f32 "
        "{%0,%1,%2,%3}, {%4,%5,%6,%7}, {%8,%9}, {%0,%1,%2,%3};"
        : "+f"(d[0]), "+f"(d[1]), "+f"(d[2]), "+f"(d[3])
        : "r"(a[0]), "r"(a[1]), "r"(a[2]), "r"(a[3]), "r"(b0), "r"(b1));
}

// ---------------- init: weight split (vec4) + detect + x split (vec4 x4) ---------
// blocks [0,384): weights (98304 float4 total)
// block 384: detect start dtype
// blocks [385, 385+2048): x split, 4 float4 per thread
__global__ void init_kernel(const unsigned char* __restrict__ p,
                            const float* __restrict__ x,
                            const float* __restrict__ w0, const float* __restrict__ w1,
                            const float* __restrict__ w2, const float* __restrict__ w3,
                            const float* __restrict__ w4, const float* __restrict__ w5)
{
    int tid = threadIdx.x;
    int bid = blockIdx.x;
    if (bid < 384) {
        int qi = bid * 256 + tid;        // 0..98303
        int mat = qi >> 14;              // 0..5
        int idx = (qi & 16383) * 4;      // element index within mat
        const float* src;
        switch (mat) {
            case 0: src = w0; break;
            case 1: src = w1; break;
            case 2: src = w2; break;
            case 3: src = w3; break;
            case 4: src = w4; break;
            default: src = w5; break;
        }
        float4 v = *(const float4*)(src + idx);
        u32 h0 = pack_bf16x2(v.x, v.y);
        u32 h1 = pack_bf16x2(v.z, v.w);
        u32 l0 = pack_bf16x2(v.x - bf16lo_f(h0), v.y - bf16hi_f(h0));
        u32 l1 = pack_bf16x2(v.z - bf16lo_f(h1), v.w - bf16hi_f(h1));
        u16* dh = g_whi + mat*65536 + idx;
        u16* dl = g_wlo + mat*65536 + idx;
        *(u32*)(dh)     = h0;
        *(u32*)(dh + 2) = h1;
        *(u32*)(dl)     = l0;
        *(u32*)(dl + 2) = l1;
    } else if (bid == 384) {
        __shared__ int cnt1, cnt3f;
        if (tid == 0) { cnt1 = 0; cnt3f = 0; }
        __syncthreads();
        int l1 = 0, l3 = 0;
        for (int idx = tid; idx < 4096; idx += 256) {
            unsigned char b = p[idx];
            if ((idx & 3) != 0 && b != 0) l1++;
            if ((idx & 3) == 3 && b == 0x3F) l3++;
        }
        atomicAdd(&cnt1, l1); atomicAdd(&cnt3f, l3);
        __syncthreads();
        if (tid == 0) g_startmode = (cnt3f > 0) ? 2 : ((cnt1 > 0) ? 0 : 1);
    } else {
        int qbase = (bid - 385) * 1024;
        #pragma unroll
        for (int s = 0; s < 4; s++) {
            int base = (qbase + s*256 + tid) * 4;
            float4 v = *(const float4*)(x + base);
            u32 h0 = pack_bf16x2(v.x, v.y);
            u32 h1 = pack_bf16x2(v.z, v.w);
            u32 l0 = pack_bf16x2(v.x - bf16lo_f(h0), v.y - bf16hi_f(h0));
            u32 l1 = pack_bf16x2(v.z - bf16lo_f(h1), v.w - bf16hi_f(h1));
            *(u32*)(g_xhi + base)     = h0;
            *(u32*)(g_xhi + base + 2) = h1;
            *(u32*)(g_xlo + base)     = l0;
            *(u32*)(g_xlo + base + 2) = l1;
        }
    }
}

// ---------------- k,q,v projections + fused chunk aggregate ----------------
#define KQV_ROWS 128
__global__ void kqv_kernel(const float* __restrict__ xext, int use_x1,
                           const float* __restrict__ Wk, const float* __restrict__ Wq,
                           const float* __restrict__ Wv, const float* __restrict__ bv,
                           const void* __restrict__ startp)
{
    extern __shared__ float sm[];
    float* wt = sm;                  // 256*64
    float* xs = sm + 256*64;         // 128*257 (reused after compute)
    const float* x = use_x1 ? g_x1 : xext;
    int tid = threadIdx.x;
    int base = blockIdx.x * KQV_ROWS;
    int mode = g_startmode;

    for (int idx = tid; idx < 48*256; idx += 256) {
        int o = idx >> 8, c = idx & 255;
        float w;
        if (o < 16)      w = Wk[o*256 + c];
        else if (o < 32) w = Wq[(o-16)*256 + c];
        else             w = Wv[(o-32)*256 + c];
        int gg = o / 6, mm = o - gg*6;
        wt[c*64 + gg*8 + mm] = w;
    }
    {
        const float* xg = x + (size_t)base * 256;
        for (int idx = tid; idx < KQV_ROWS*64; idx += 256) {
            int r = idx >> 6, c4 = (idx & 63) * 4;
            float4 v = *(const float4*)(xg + r*256 + c4);
            float* d = xs + r*257 + c4;
            d[0] = v.x; d[1] = v.y; d[2] = v.z; d[3] = v.w;
        }
    }
    __syncthreads();

    int r0 = tid & 31;
    int g  = tid >> 5;
    u64 acc[4][3];
    #pragma unroll
    for (int rr = 0; rr < 4; rr++)
        #pragma unroll
        for (int pi = 0; pi < 3; pi++) acc[rr][pi] = 0ull;

    const float* wbase = wt + g*8;
    #pragma unroll 2
    for (int c = 0; c < 256; c++) {
        const float* wr = wbase + c*64;
        u64 w0 = *(const u64*)(wr + 0);
        u64 w1 = *(const u64*)(wr + 2);
        u64 w2 = *(const u64*)(wr + 4);
        #pragma unroll
        for (int rr = 0; rr < 4; rr++) {
            float xv = xs[(r0 + rr*32)*257 + c];
            u64 xd = dup2(xv);
            acc[rr][0] = fma2(xd, w0, acc[rr][0]);
            acc[rr][1] = fma2(xd, w1, acc[rr][1]);
            acc[rr][2] = fma2(xd, w2, acc[rr][2]);
        }
    }
    __syncthreads();   // xs reuse

    float* ks_sm = xs;
    float* vs_sm = xs + 2048;
    float* ksums = xs + 4096;
    int*   stb   = (int*)(xs + 4224);

    #pragma unroll
    for (int rr = 0; rr < 4; rr++) {
        int lr = r0 + rr*32;
        int t  = base + lr;
        #pragma unroll
        for (int pi = 0; pi < 3; pi++) {
            float lo, hi;
            unpack2(acc[rr][pi], lo, hi);
            #pragma unroll
            for (int h = 0; h < 2; h++) {
                int o = g*6 + pi*2 + h;
                float val = h ? hi : lo;
                if (o < 16) {
                    float pk = phi_fn(val);
                    g_k[t*16 + o] = pk;
                    ks_sm[lr*16 + o] = pk;
                } else if (o < 32) {
                    g_q[t*16 + (o-16)] = phi_fn(val);
                } else {
                    float vv = val + bv[o-32];
                    g_v[t*16 + (o-32)] = vv;
                    vs_sm[lr*16 + (o-32)] = vv;
                }
            }
        }
    }
    __syncthreads();

    if (tid < 128) {
        float s = 0.f;
        #pragma unroll
        for (int i = 0; i < 16; i++) s += ks_sm[tid*16 + i];
        ksums[tid] = s;
        stb[tid] = read_start(startp, base + tid, mode);
    }
    __syncthreads();

    int i = tid & 15, j = tid >> 4;
    float S = 0.f, Zs = 0.f; int p = 0;
    for (int t = 0; t < CH; t++) {
        if (stb[t]) { S = 0.f; Zs = 0.f; p = 1; }
        S  += ks_sm[t*16 + i] * vs_sm[t*16 + j];
        Zs += ksums[t];
    }
    g_Sagg[blockIdx.x*256 + tid] = S;
    if (tid == 0) { g_Zagg[blockIdx.x] = Zs; g_pagg[blockIdx.x] = p; }
}

// ---------------- prefix level 1: 16 CTAs, 16 chunks each (prefetched) --------
__global__ void prefix1_kernel()
{
    int tid = threadIdx.x;
    int g = blockIdx.x;
    float sa[16], za[16]; int pa[16];
    #pragma unroll
    for (int d = 0; d < 16; d++) {
        int c = g*16 + d;
        sa[d] = g_Sagg[c*256 + tid];
        za[d] = g_Zagg[c];
        pa[d] = g_pagg[c];
    }
    float S = 0.f, Zs = 0.f; int p = 0;
    #pragma unroll
    for (int d = 0; d < 16; d++) {
        int c = g*16 + d;
        g_Sloc[c*256 + tid] = S;
        if (tid == 0) { g_Zloc[c] = Zs; g_ploc[c] = p; }
        if (pa[d]) { S = 0.f; Zs = 0.f; }
        S += sa[d]; Zs += za[d]; p |= pa[d];
    }
    g_SG[g*256 + tid] = S;
    if (tid == 0) { g_ZG[g] = Zs; g_pG[g] = p; }
}

// ---------------- prefix level 2: scan 16 group aggregates (prefetched) -------
__global__ void prefix2_kernel(const float* __restrict__ s0, const float* __restrict__ z0)
{
    int tid = threadIdx.x;
    int i = tid & 15, j = tid >> 4;
    float sa[NG], za[NG]; int pa[NG];
    #pragma unroll
    for (int g = 0; g < NG; g++) {
        sa[g] = g_SG[g*256 + tid];
        za[g] = g_ZG[g];
        pa[g] = g_pG[g];
    }
    float S = s0[i*16 + j];
    float Zs = 0.f;
    #pragma unroll
    for (int l = 0; l < 16; l++) Zs += z0[l];
    #pragma unroll
    for (int g = 0; g < NG; g++) {
        g_SGP[g*256 + tid] = S;
        if (tid == 0) g_ZGP[g] = Zs;
        if (pa[g]) { S = 0.f; Zs = 0.f; }
        S += sa[g]; Zs += za[g];
    }
}

// ------- pass 3: replay + attention output + MLP layer 1 -------
__global__ void apply_kernel(const void* __restrict__ startp,
                             const float* __restrict__ Wm1, const float* __restrict__ bm1)
{
    __shared__ float ks[CH*16], qs[CH*16], vs[CH*16], ksums[CH], qsums[CH];
    __shared__ int stb[CH];
    __shared__ float outb[2][16][17];
    int tid = threadIdx.x;
    int c = blockIdx.x;
    int tb = c * CH;
    int mode = g_startmode;
    for (int idx = tid; idx < CH*16; idx += 256) {
        ks[idx] = g_k[tb*16 + idx];
        qs[idx] = g_q[tb*16 + idx];
        vs[idx] = g_v[tb*16 + idx];
    }
    for (int idx = tid; idx < CH; idx += 256)
        stb[idx] = read_start(startp, tb + idx, mode);
    __syncthreads();
    for (int t = tid; t < CH; t += 256) {
        float sk = 0.f, sq = 0.f;
        #pragma unroll
        for (int i = 0; i < 16; i++) { sk += ks[t*16+i]; sq += qs[t*16+i]; }
        ksums[t] = sk; qsums[t] = sq;
    }
    float wm1r[16];
    #pragma unroll
    for (int l = 0; l < 16; l++) wm1r[l] = Wm1[tid*16 + l];
    float b1 = bm1[tid];
    // combine local prefix with group prefix
    int grp = c >> 4;
    float Sl = g_Sloc[c*256 + tid];
    int   pl = g_ploc[c];
    float S  = pl ? Sl : (g_SGP[grp*256 + tid] + Sl);
    float Zl = g_Zloc[c];
    float Zs = pl ? Zl : (g_ZGP[grp] + Zl);
    __syncthreads();

    int i = tid & 15, j = tid >> 4;
    for (int t0 = 0; t0 < CH; t0 += 16) {
        int buf = (t0 >> 4) & 1;
        #pragma unroll
        for (int tt = 0; tt < 16; tt++) {
            int t = t0 + tt;
            if (stb[t]) { S = 0.f; Zs = 0.f; }
            S  += ks[t*16 + i] * vs[t*16 + j];
            Zs += ksums[t];
            float pv = S * qs[t*16 + i];
            pv += __shfl_down_sync(0xffffffffu, pv, 8, 16);
            pv += __shfl_down_sync(0xffffffffu, pv, 4, 16);
            pv += __shfl_down_sync(0xffffffffu, pv, 2, 16);
            pv += __shfl_down_sync(0xffffffffu, pv, 1, 16);
            if (i == 0) {
                float denom = fmaxf(Zs * qsums[t], 1e-6f);
                outb[buf][tt][j] = pv / denom;
            }
        }
        __syncthreads();
        #pragma unroll
        for (int tt = 0; tt < 16; tt++) {
            const float* ob = outb[buf][tt];
            float h = b1;
            #pragma unroll
            for (int l = 0; l < 16; l++) h += wm1r[l] * ob[l];
            h = (h > 0.f) ? h : 0.01f * h;
            u32 ph = pack_bf16x2(h, h);
            float res = h - bf16lo_f(ph);
            u32 plp = pack_bf16x2(res, res);
            size_t off = (size_t)(tb + t0 + tt) * 256 + tid;
            g_h1hi[off] = (u16)ph;
            g_h1lo[off] = (u16)plp;
        }
    }
}

// ===== HMMA big GEMM: bf16x3 split, 3-stage cp.async, K-chunk 32, XOR swizzle =====
// variant 0: h2(split) = leaky(h1 @ W1^T + b1)                   (K=256, 8 chunks)
// variant 1/2: g_ypre = A1 @ W1^T + A2 @ W2^T + b1 + b2          (K=512, 16 chunks)
// Tiles: 128 rows x 32 k bf16 = 64 B/row unpadded; chunk swizzle c^=(r>>1)&3
// keeps cp.async/ldmatrix 16B-aligned and ldsm conflict-free.
#define SOFF_AHI  0
#define SOFF_ALO  8192
#define SOFF_BHI  16384
#define SOFF_BLO  24576
#define STAGE_BYTES 32768
#define OFF_BIAS  (3*STAGE_BYTES)
#define GEMM_SMEM (OFF_BIAS + 512)

__device__ __forceinline__ void gemm_stage(
    u32 sbase, u32 stagebase, int kc,
    const u16* __restrict__ a1hi, const u16* __restrict__ a1lo,
    const u16* __restrict__ a2hi, const u16* __restrict__ a2lo,
    const u16* __restrict__ w1hi, const u16* __restrict__ w1lo,
    const u16* __restrict__ w2hi, const u16* __restrict__ w2lo,
    int rowbase, int colbase, int tid)
{
    int koff = (kc & 7) * 32;
    const u16* Whi = (kc < 8) ? w1hi : w2hi;
    const u16* Wlo = (kc < 8) ? w1lo : w2lo;
    const u16* Ahi = (kc < 8) ? a1hi : a2hi;
    const u16* Alo = (kc < 8) ? a1lo : a2lo;
    #pragma unroll
    for (int s = 0; s < 2; s++) {
        int idx = tid + s*256;        // 0..511
        int r  = idx >> 2;            // 0..127
        int sg = idx & 3;             // 16B chunk within 64B row
        u32 soff = (u32)(r*64 + ((sg ^ ((r >> 1) & 3)) << 4));
        size_t gea = (size_t)(rowbase + r) * 256 + koff + sg*8;
        size_t geb = (size_t)(colbase + r) * 256 + koff + sg*8;
        cp_async16(sbase + stagebase + SOFF_AHI + soff, Ahi + gea);
        cp_async16(sbase + stagebase + SOFF_ALO + soff, Alo + gea);
        cp_async16(sbase + stagebase + SOFF_BHI + soff, Whi + geb);
        cp_async16(sbase + stagebase + SOFF_BLO + soff, Wlo + geb);
    }
}

__global__ void __launch_bounds__(256, 2)
gemm_mma_kernel(const u16* __restrict__ a1hi, const u16* __restrict__ a1lo,
                const u16* __restrict__ a2hi, const u16* __restrict__ a2lo,
                const u16* __restrict__ w1hi, const u16* __restrict__ w1lo,
                const u16* __restrict__ w2hi, const u16* __restrict__ w2lo,
                const float* __restrict__ b1p, const float* __restrict__ b2p,
                int variant)
{
    extern __shared__ char smc[];
    u32 sbase = smem_to_u32(smc);
    float* bias_sm = (float*)(smc + OFF_BIAS);

    int nchunk = (variant == 0) ? 8 : 16;

    int tid  = threadIdx.x;
    int wid  = tid >> 5;
    int lane = tid & 31;
    int colbase = blockIdx.x * 128;
    int rowbase = blockIdx.y * 128;

    int warp_m = (wid >> 1) * 32;
    int warp_n = (wid & 1) * 64;

    for (int i = tid; i < 128; i += 256)
        bias_sm[i] = b1p[colbase + i] + ((variant != 0) ? b2p[colbase + i] : 0.f);

    float acc[2][8][4];
    #pragma unroll
    for (int mi = 0; mi < 2; mi++)
        #pragma unroll
        for (int nt = 0; nt < 8; nt++)
            #pragma unroll
            for (int r = 0; r < 4; r++) acc[mi][nt][r] = 0.f;

    // prologue: stage chunks 0 and 1
    gemm_stage(sbase, 0, 0, a1hi, a1lo, a2hi, a2lo, w1hi, w1lo, w2hi, w2lo,
               rowbase, colbase, tid);
    cp_commit();
    gemm_stage(sbase, STAGE_BYTES, 1, a1hi, a1lo, a2hi, a2lo, w1hi, w1lo, w2hi, w2lo,
               rowbase, colbase, tid);
    cp_commit();

    int lrow  = lane & 15;
    int chalf = lane >> 4;    // k8 half within the k16 step

    for (int kc = 0; kc < nchunk; kc++) {
        if (kc + 1 < nchunk) cp_wait1(); else cp_wait0();
        __syncthreads();

        u32 sb = (u32)((kc % 3) * STAGE_BYTES);
        // compute: 2 k16 steps on this k32 chunk
        #pragma unroll
        for (int ks = 0; ks < 2; ks++) {
            int cch = ks*2 + chalf;   // logical 16B chunk index 0..3
            u32 ahi[2][4], alo[2][4];
            #pragma unroll
            for (int mi = 0; mi < 2; mi++) {
                int row = warp_m + mi*16 + lrow;
                u32 off = sb + (u32)(row*64 + ((cch ^ ((row >> 1) & 3)) << 4));
                ldsm_x4(ahi[mi][0], ahi[mi][1], ahi[mi][2], ahi[mi][3], sbase + SOFF_AHI + off);
                ldsm_x4(alo[mi][0], alo[mi][1], alo[mi][2], alo[mi][3], sbase + SOFF_ALO + off);
            }
            #pragma unroll
            for (int gg = 0; gg < 4; gg++) {
                int row = warp_n + gg*16 + lrow;
                u32 off = sb + (u32)(row*64 + ((cch ^ ((row >> 1) & 3)) << 4));
                u32 bh[4], bl[4];
                ldsm_x4(bh[0], bh[1], bh[2], bh[3], sbase + SOFF_BHI + off);
                ldsm_x4(bl[0], bl[1], bl[2], bl[3], sbase + SOFF_BLO + off);
                #pragma unroll
                for (int mi = 0; mi < 2; mi++) {
                    #pragma unroll
                    for (int nj = 0; nj < 2; nj++) {
                        float* d = acc[mi][gg*2 + nj];
                        mma16816(d, ahi[mi], bh[nj], bh[2 + nj]);
                        mma16816(d, ahi[mi], bl[nj], bl[2 + nj]);
                        mma16816(d, alo[mi], bh[nj], bh[2 + nj]);
                    }
                }
            }
        }
        // stage kc+2 into buffer (kc+2)%3. Safe: that buffer held chunk kc-1,
        // whose compute finished in all warps before this iteration's barrier.
        if (kc + 2 < nchunk) {
            gemm_stage(sbase, (u32)(((kc + 2) % 3) * STAGE_BYTES), kc + 2,
                       a1hi, a1lo, a2hi, a2lo, w1hi, w1lo, w2hi, w2lo,
                       rowbase, colbase, tid);
            cp_commit();
        }
    }

    // ---------------- epilogue ----------------
    #pragma unroll
    for (int mi = 0; mi < 2; mi++) {
        int row0 = rowbase + warp_m + mi*16 + (lane >> 2);
        #pragma unroll
        for (int nt = 0; nt < 8; nt++) {
            int colL = warp_n + nt*8 + (lane & 3)*2;
            int col  = colbase + colL;
            float b0 = bias_sm[colL], b1 = bias_sm[colL + 1];
            float v0 = acc[mi][nt][0] + b0;
            float v1 = acc[mi][nt][1] + b1;
            float v2 = acc[mi][nt][2] + b0;
            float v3 = acc[mi][nt][3] + b1;
            if (variant == 0) {
                v0 = (v0 > 0.f) ? v0 : 0.01f * v0;
                v1 = (v1 > 0.f) ? v1 : 0.01f * v1;
                v2 = (v2 > 0.f) ? v2 : 0.01f * v2;
                v3 = (v3 > 0.f) ? v3 : 0.01f * v3;
                u32 hp0 = pack_bf16x2(v0, v1);
                u32 lp0 = pack_bf16x2(v0 - bf16lo_f(hp0), v1 - bf16hi_f(hp0));
                u32 hp1 = pack_bf16x2(v2, v3);
                u32 lp1 = pack_bf16x2(v2 - bf16lo_f(hp1), v3 - bf16hi_f(hp1));
                size_t o0 = (size_t)row0 * 256 + col;
                size_t o1 = (size_t)(row0 + 8) * 256 + col;
                *(u32*)(g_h2hi + o0) = hp0;
                *(u32*)(g_h2lo + o0) = lp0;
                *(u32*)(g_h2hi + o1) = hp1;
                *(u32*)(g_h2lo + o1) = lp1;
            } else {
                *(float2*)(g_ypre + (size_t)row0 * 256 + col)       = make_float2(v0, v1);
                *(float2*)(g_ypre + (size_t)(row0 + 8) * 256 + col) = make_float2(v2, v3);
            }
        }
    }
}

// ---------------- LayerNorm + residual ----------------
__global__ void ln_kernel(const float* __restrict__ xext, float* __restrict__ outext,
                          const float* __restrict__ lw, const float* __restrict__ lb, int mode)
{
    int tid = threadIdx.x;
    int lane = tid & 31, w = tid >> 5;
    int row = blockIdx.x * 8 + w;
    const float* yp = g_ypre + (size_t)row * 256;
    float vals[8];
    float s = 0.f;
    #pragma unroll
    for (int u = 0; u < 8; u++) { vals[u] = yp[lane + u*32]; s += vals[u]; }
    #pragma unroll
    for (int d = 16; d >= 1; d >>= 1) s += __shfl_xor_sync(0xffffffffu, s, d);
    float mean = s * (1.f / 256.f);
    float v2 = 0.f;
    #pragma unroll
    for (int u = 0; u < 8; u++) { float d = vals[u] - mean; v2 += d * d; }
    #pragma unroll
    for (int d = 16; d >= 1; d >>= 1) v2 += __shfl_xor_sync(0xffffffffu, v2, d);
    float rstd = rsqrtf(v2 * (1.f / 256.f) + 1e-5f);

    if (mode == 0) {
        float* o = g_x1 + (size_t)row * 256;
        const float* xr = xext + (size_t)row * 256;
        #pragma unroll
        for (int u = 0; u < 8; u++) {
            int cl = lane + u*32;
            float y = xr[cl] + (vals[u] - mean) * rstd * lw[cl] + lb[cl];
            o[cl] = y;
            u32 ph = pack_bf16x2(y, y);
            float res = y - bf16lo_f(ph);
            u32 pl = pack_bf16x2(res, res);
            size_t off = (size_t)row * 256 + cl;
            g_x1hi[off] = (u16)ph;
            g_x1lo[off] = (u16)pl;
        }
    } else {
        float* o = outext + (size_t)row * 256;
        #pragma unroll
        for (int u = 0; u < 8; u++) {
            int cl = lane + u*32;
            o[cl] = (vals[u] - mean) * rstd * lw[cl] + lb[cl];
        }
    }
}

// ---------------- launch ----------------
extern "C" void kernel_launch(void* const* d_in, const int* in_sizes, int n_in,
                              void* d_out, int out_size)
{
    const float* x     = (const float*)d_in[0];
    const void*  start = d_in[1];
    const float* s0    = (const float*)d_in[2];
    const float* z0    = (const float*)d_in[3];
    const float* Wk    = (const float*)d_in[4];
    const float* Wq    = (const float*)d_in[5];
    const float* Wv    = (const float*)d_in[6];
    const float* bv    = (const float*)d_in[7];
    const float* Wskip = (const float*)d_in[8];
    const float* bskip = (const float*)d_in[9];
    const float* Wm1   = (const float*)d_in[10];
    const float* bm1   = (const float*)d_in[11];
    const float* Wm2   = (const float*)d_in[12];
    const float* bm2   = (const float*)d_in[13];
    const float* Wm3   = (const float*)d_in[14];
    const float* bm3   = (const float*)d_in[15];
    const float* lnw   = (const float*)d_in[16];
    const float* lnb   = (const float*)d_in[17];
    float* out = (float*)d_out;

    const int kqv_smem = (256*64 + KQV_ROWS*257) * 4;
    cudaFuncSetAttribute(kqv_kernel, cudaFuncAttributeMaxDynamicSharedMemorySize, kqv_smem);
    cudaFuncSetAttribute(gemm_mma_kernel, cudaFuncAttributeMaxDynamicSharedMemorySize, GEMM_SMEM);

    static u16 *whi_p = nullptr, *wlo_p = nullptr;
    static u16 *h1hi_p, *h1lo_p, *h2hi_p, *h2lo_p, *x1hi_p, *x1lo_p, *xhi_p, *xlo_p;
    if (!whi_p) {
        cudaGetSymbolAddress((void**)&whi_p,  g_whi);
        cudaGetSymbolAddress((void**)&wlo_p,  g_wlo);
        cudaGetSymbolAddress((void**)&h1hi_p, g_h1hi);
        cudaGetSymbolAddress((void**)&h1lo_p, g_h1lo);
        cudaGetSymbolAddress((void**)&h2hi_p, g_h2hi);
        cudaGetSymbolAddress((void**)&h2lo_p, g_h2lo);
        cudaGetSymbolAddress((void**)&x1hi_p, g_x1hi);
        cudaGetSymbolAddress((void**)&x1lo_p, g_x1lo);
        cudaGetSymbolAddress((void**)&xhi_p,  g_xhi);
        cudaGetSymbolAddress((void**)&xlo_p,  g_xlo);
    }

    init_kernel<<<385 + 2048, 256>>>((const unsigned char*)start, x,
        Wm2, Wm3, Wskip, Wm2 + 65536, Wm3 + 65536, Wskip + 65536);

    for (int b = 0; b < NBLK; b++) {
        kqv_kernel<<<NC, 256, kqv_smem>>>(x, b,
            Wk + b*16*256, Wq + b*16*256, Wv + b*16*256, bv + b*16, start);
        prefix1_kernel<<<NG, 256>>>();
        prefix2_kernel<<<1, 256>>>(s0 + b*256, z0 + b*16);
        apply_kernel<<<NC, 256>>>(start, Wm1 + b*256*16, bm1 + b*256);

        const u16* wm2hi = whi_p + (b*3 + 0)*65536;
        const u16* wm2lo = wlo_p + (b*3 + 0)*65536;
        const u16* wm3hi = whi_p + (b*3 + 1)*65536;
        const u16* wm3lo = wlo_p + (b*3 + 1)*65536;
        const u16* wskhi = whi_p + (b*3 + 2)*65536;
        const u16* wsklo = wlo_p + (b*3 + 2)*65536;

        // h2 = leaky(h1 @ Wm2^T + bm2)
        gemm_mma_kernel<<<dim3(2, TT/128), 256, GEMM_SMEM>>>(
            h1hi_p, h1lo_p, h1hi_p, h1lo_p,
            wm2hi, wm2lo, wm2hi, wm2lo, bm2 + b*256, bm2 + b*256, 0);
        // ypre = h2 @ Wm3^T + A2 @ Wskip^T + bm3 + bskip
        gemm_mma_kernel<<<dim3(2, TT/128), 256, GEMM_SMEM>>>(
            h2hi_p, h2lo_p,
            (b == 0) ? xhi_p : x1hi_p, (b == 0) ? xlo_p : x1lo_p,
            wm3hi, wm3lo, wskhi, wsklo, bm3 + b*256, bskip + b*256,
            (b == 0) ? 1 : 2);
        ln_kernel<<<TT/8, 256>>>(x, out, lnw + b*256, lnb + b*256, (b == 0) ? 0 : 1);
    }
}

// round 10
// speedup vs baseline: 1.1318x; 1.0067x over previous
#include <cuda_runtime.h>
#include <cstdint>

typedef unsigned long long u64;
typedef unsigned int u32;
typedef unsigned short u16;

// Problem constants
#define TT   32768
#define DD   256
#define HH   256
#define KV   16
#define CH   128          // scan chunk length (kqv/prefix granularity)
#define CH2  64           // apply granularity (half chunks)
#define NC   (TT/CH)      // 256 chunks
#define NC2  (TT/CH2)     // 512 half-chunks
#define NG   16           // prefix groups (16 chunks each)
#define NBLK 2

// ---------------- device scratch (no allocations allowed) ----------------
__device__ float g_k[TT*KV];
__device__ float g_q[TT*KV];
__device__ float g_v[TT*KV];
__device__ float g_Sagg[NC*256];
__device__ float g_Zagg[NC];
__device__ int   g_pagg[NC];
__device__ float g_Shalf[NC*256];  // first-half (64-step) aggregates
__device__ float g_Zhalf[NC];
__device__ int   g_phalf[NC];
__device__ float g_Sloc[NC*256];   // local (within-group) exclusive prefixes
__device__ float g_Zloc[NC];
__device__ int   g_ploc[NC];
__device__ float g_SG[NG*256];     // group aggregates
__device__ float g_ZG[NG];
__device__ int   g_pG[NG];
__device__ float g_SGP[NG*256];    // group exclusive prefixes (incl s0 init)
__device__ float g_ZGP[NG];
__device__ float g_ypre[TT*HH];
__device__ float g_x1[TT*HH];
__device__ int   g_startmode;   // 0=u8 bool, 1=int32, 2=float32

// bf16 hi/lo split operand storage
__device__ u16 g_h1hi[TT*HH];
__device__ u16 g_h1lo[TT*HH];
__device__ u16 g_h2hi[TT*HH];
__device__ u16 g_h2lo[TT*HH];
__device__ u16 g_x1hi[TT*HH];
__device__ u16 g_x1lo[TT*HH];
__device__ u16 g_xhi[TT*DD];
__device__ u16 g_xlo[TT*DD];
__device__ u16 g_whi[6*65536];  // [mat][256][256]: per block {Wm2, Wm3, Wskip}
__device__ u16 g_wlo[6*65536];

// ---------------- f32x2 packed helpers ----------------
__device__ __forceinline__ u64 dup2(float x) {
    u64 r;
    asm("mov.b64 %0, {%1, %1};" : "=l"(r) : "r"(__float_as_uint(x)));
    return r;
}
__device__ __forceinline__ u64 fma2(u64 a, u64 b, u64 c) {
    u64 d;
    asm("fma.rn.f32x2 %0, %1, %2, %3;" : "=l"(d) : "l"(a), "l"(b), "l"(c));
    return d;
}
__device__ __forceinline__ void unpack2(u64 v, float& lo, float& hi) {
    u32 a, b;
    asm("mov.b64 {%0, %1}, %2;" : "=r"(a), "=r"(b) : "l"(v));
    lo = __uint_as_float(a); hi = __uint_as_float(b);
}

__device__ __forceinline__ float phi_fn(float t) {
    return (t > 0.f) ? (1.f + t) : __expf(t);
}

__device__ __forceinline__ int read_start(const void* p, int t, int mode) {
    if (mode == 0) return ((const unsigned char*)p)[t] != 0;
    if (mode == 1) return ((const int*)p)[t] != 0;
    return ((const float*)p)[t] != 0.f;
}

// ---------------- bf16 pack helpers ----------------
__device__ __forceinline__ u32 pack_bf16x2(float lo, float hi) {
    u32 r;
    asm("cvt.rn.bf16x2.f32 %0, %1, %2;" : "=r"(r) : "f"(hi), "f"(lo));
    return r;
}
__device__ __forceinline__ float bf16lo_f(u32 p) { return __uint_as_float(p << 16); }
__device__ __forceinline__ float bf16hi_f(u32 p) { return __uint_as_float(p & 0xffff0000u); }

__device__ __forceinline__ u32 smem_to_u32(const void* smem_ptr) {
    u32 addr;
    asm("{ .reg .u64 tmp; cvta.to.shared.u64 tmp, %1; cvt.u32.u64 %0, tmp; }"
        : "=r"(addr) : "l"(smem_ptr));
    return addr;
}

__device__ __forceinline__ void cp_async16(u32 saddr, const void* gptr) {
    asm volatile("cp.async.cg.shared.global [%0], [%1], 16;" :: "r"(saddr), "l"(gptr));
}
__device__ __forceinline__ void cp_commit() {
    asm volatile("cp.async.commit_group;" ::: "memory");
}
__device__ __forceinline__ void cp_wait0() {
    asm volatile("cp.async.wait_group 0;" ::: "memory");
}
__device__ __forceinline__ void cp_wait1() {
    asm volatile("cp.async.wait_group 1;" ::: "memory");
}

__device__ __forceinline__ void ldsm_x4(u32& r0, u32& r1, u32& r2, u32& r3, u32 addr) {
    asm volatile("ldmatrix.sync.aligned.m8n8.x4.shared.b16 {%0,%1,%2,%3}, [%4];"
        : "=r"(r0), "=r"(r1), "=r"(r2), "=r"(r3) : "r"(addr));
}

__device__ __forceinline__ void mma16816(float* d, const u32* a, u32 b0, u32 b1) {
    asm volatile(
        "mma.sync.aligned.m16n8k16.row.col.f32.bf16.bf16.f32 "
        "{%0,%1,%2,%3}, {%4,%5,%6,%7}, {%8,%9}, {%0,%1,%2,%3};"
        : "+f"(d[0]), "+f"(d[1]), "+f"(d[2]), "+f"(d[3])
        : "r"(a[0]), "r"(a[1]), "r"(a[2]), "r"(a[3]), "r"(b0), "r"(b1));
}

// ---------------- init: weight split (vec4) + detect + x split (vec4 x4) ---------
__global__ void init_kernel(const unsigned char* __restrict__ p,
                            const float* __restrict__ x,
                            const float* __restrict__ w0, const float* __restrict__ w1,
                            const float* __restrict__ w2, const float* __restrict__ w3,
                            const float* __restrict__ w4, const float* __restrict__ w5)
{
    int tid = threadIdx.x;
    int bid = blockIdx.x;
    if (bid < 384) {
        int qi = bid * 256 + tid;        // 0..98303
        int mat = qi >> 14;              // 0..5
        int idx = (qi & 16383) * 4;      // element index within mat
        const float* src;
        switch (mat) {
            case 0: src = w0; break;
            case 1: src = w1; break;
            case 2: src = w2; break;
            case 3: src = w3; break;
            case 4: src = w4; break;
            default: src = w5; break;
        }
        float4 v = *(const float4*)(src + idx);
        u32 h0 = pack_bf16x2(v.x, v.y);
        u32 h1 = pack_bf16x2(v.z, v.w);
        u32 l0 = pack_bf16x2(v.x - bf16lo_f(h0), v.y - bf16hi_f(h0));
        u32 l1 = pack_bf16x2(v.z - bf16lo_f(h1), v.w - bf16hi_f(h1));
        u16* dh = g_whi + mat*65536 + idx;
        u16* dl = g_wlo + mat*65536 + idx;
        *(u32*)(dh)     = h0;
        *(u32*)(dh + 2) = h1;
        *(u32*)(dl)     = l0;
        *(u32*)(dl + 2) = l1;
    } else if (bid == 384) {
        __shared__ int cnt1, cnt3f;
        if (tid == 0) { cnt1 = 0; cnt3f = 0; }
        __syncthreads();
        int l1 = 0, l3 = 0;
        for (int idx = tid; idx < 4096; idx += 256) {
            unsigned char b = p[idx];
            if ((idx & 3) != 0 && b != 0) l1++;
            if ((idx & 3) == 3 && b == 0x3F) l3++;
        }
        atomicAdd(&cnt1, l1); atomicAdd(&cnt3f, l3);
        __syncthreads();
        if (tid == 0) g_startmode = (cnt3f > 0) ? 2 : ((cnt1 > 0) ? 0 : 1);
    } else {
        int qbase = (bid - 385) * 1024;
        #pragma unroll
        for (int s = 0; s < 4; s++) {
            int base = (qbase + s*256 + tid) * 4;
            float4 v = *(const float4*)(x + base);
            u32 h0 = pack_bf16x2(v.x, v.y);
            u32 h1 = pack_bf16x2(v.z, v.w);
            u32 l0 = pack_bf16x2(v.x - bf16lo_f(h0), v.y - bf16hi_f(h0));
            u32 l1 = pack_bf16x2(v.z - bf16lo_f(h1), v.w - bf16hi_f(h1));
            *(u32*)(g_xhi + base)     = h0;
            *(u32*)(g_xhi + base + 2) = h1;
            *(u32*)(g_xlo + base)     = l0;
            *(u32*)(g_xlo + base + 2) = l1;
        }
    }
}

// ---------------- k,q,v projections + fused chunk aggregate (+half snapshot) ----
#define KQV_ROWS 128
__global__ void kqv_kernel(const float* __restrict__ xext, int use_x1,
                           const float* __restrict__ Wk, const float* __restrict__ Wq,
                           const float* __restrict__ Wv, const float* __restrict__ bv,
                           const void* __restrict__ startp)
{
    extern __shared__ float sm[];
    float* wt = sm;                  // 256*64
    float* xs = sm + 256*64;         // 128*257 (reused after compute)
    const float* x = use_x1 ? g_x1 : xext;
    int tid = threadIdx.x;
    int base = blockIdx.x * KQV_ROWS;
    int mode = g_startmode;

    for (int idx = tid; idx < 48*256; idx += 256) {
        int o = idx >> 8, c = idx & 255;
        float w;
        if (o < 16)      w = Wk[o*256 + c];
        else if (o < 32) w = Wq[(o-16)*256 + c];
        else             w = Wv[(o-32)*256 + c];
        int gg = o / 6, mm = o - gg*6;
        wt[c*64 + gg*8 + mm] = w;
    }
    {
        const float* xg = x + (size_t)base * 256;
        for (int idx = tid; idx < KQV_ROWS*64; idx += 256) {
            int r = idx >> 6, c4 = (idx & 63) * 4;
            float4 v = *(const float4*)(xg + r*256 + c4);
            float* d = xs + r*257 + c4;
            d[0] = v.x; d[1] = v.y; d[2] = v.z; d[3] = v.w;
        }
    }
    __syncthreads();

    int r0 = tid & 31;
    int g  = tid >> 5;
    u64 acc[4][3];
    #pragma unroll
    for (int rr = 0; rr < 4; rr++)
        #pragma unroll
        for (int pi = 0; pi < 3; pi++) acc[rr][pi] = 0ull;

    const float* wbase = wt + g*8;
    #pragma unroll 2
    for (int c = 0; c < 256; c++) {
        const float* wr = wbase + c*64;
        u64 w0 = *(const u64*)(wr + 0);
        u64 w1 = *(const u64*)(wr + 2);
        u64 w2 = *(const u64*)(wr + 4);
        #pragma unroll
        for (int rr = 0; rr < 4; rr++) {
            float xv = xs[(r0 + rr*32)*257 + c];
            u64 xd = dup2(xv);
            acc[rr][0] = fma2(xd, w0, acc[rr][0]);
            acc[rr][1] = fma2(xd, w1, acc[rr][1]);
            acc[rr][2] = fma2(xd, w2, acc[rr][2]);
        }
    }
    __syncthreads();   // xs reuse

    float* ks_sm = xs;
    float* vs_sm = xs + 2048;
    float* ksums = xs + 4096;
    int*   stb   = (int*)(xs + 4224);

    #pragma unroll
    for (int rr = 0; rr < 4; rr++) {
        int lr = r0 + rr*32;
        int t  = base + lr;
        #pragma unroll
        for (int pi = 0; pi < 3; pi++) {
            float lo, hi;
            unpack2(acc[rr][pi], lo, hi);
            #pragma unroll
            for (int h = 0; h < 2; h++) {
                int o = g*6 + pi*2 + h;
                float val = h ? hi : lo;
                if (o < 16) {
                    float pk = phi_fn(val);
                    g_k[t*16 + o] = pk;
                    ks_sm[lr*16 + o] = pk;
                } else if (o < 32) {
                    g_q[t*16 + (o-16)] = phi_fn(val);
                } else {
                    float vv = val + bv[o-32];
                    g_v[t*16 + (o-32)] = vv;
                    vs_sm[lr*16 + (o-32)] = vv;
                }
            }
        }
    }
    __syncthreads();

    if (tid < 128) {
        float s = 0.f;
        #pragma unroll
        for (int i = 0; i < 16; i++) s += ks_sm[tid*16 + i];
        ksums[tid] = s;
        stb[tid] = read_start(startp, base + tid, mode);
    }
    __syncthreads();

    int i = tid & 15, j = tid >> 4;
    float S = 0.f, Zs = 0.f; int p = 0;
    for (int t = 0; t < CH; t++) {
        if (t == CH2) {
            // snapshot: first-half aggregate
            g_Shalf[blockIdx.x*256 + tid] = S;
            if (tid == 0) { g_Zhalf[blockIdx.x] = Zs; g_phalf[blockIdx.x] = p; }
        }
        if (stb[t]) { S = 0.f; Zs = 0.f; p = 1; }
        S  += ks_sm[t*16 + i] * vs_sm[t*16 + j];
        Zs += ksums[t];
    }
    g_Sagg[blockIdx.x*256 + tid] = S;
    if (tid == 0) { g_Zagg[blockIdx.x] = Zs; g_pagg[blockIdx.x] = p; }
}

// ---------------- prefix level 1: 16 CTAs, 16 chunks each (prefetched) --------
__global__ void prefix1_kernel()
{
    int tid = threadIdx.x;
    int g = blockIdx.x;
    float sa[16], za[16]; int pa[16];
    #pragma unroll
    for (int d = 0; d < 16; d++) {
        int c = g*16 + d;
        sa[d] = g_Sagg[c*256 + tid];
        za[d] = g_Zagg[c];
        pa[d] = g_pagg[c];
    }
    float S = 0.f, Zs = 0.f; int p = 0;
    #pragma unroll
    for (int d = 0; d < 16; d++) {
        int c = g*16 + d;
        g_Sloc[c*256 + tid] = S;
        if (tid == 0) { g_Zloc[c] = Zs; g_ploc[c] = p; }
        if (pa[d]) { S = 0.f; Zs = 0.f; }
        S += sa[d]; Zs += za[d]; p |= pa[d];
    }
    g_SG[g*256 + tid] = S;
    if (tid == 0) { g_ZG[g] = Zs; g_pG[g] = p; }
}

// ---------------- prefix level 2: scan 16 group aggregates (prefetched) -------
__global__ void prefix2_kernel(const float* __restrict__ s0, const float* __restrict__ z0)
{
    int tid = threadIdx.x;
    int i = tid & 15, j = tid >> 4;
    float sa[NG], za[NG]; int pa[NG];
    #pragma unroll
    for (int g = 0; g < NG; g++) {
        sa[g] = g_SG[g*256 + tid];
        za[g] = g_ZG[g];
        pa[g] = g_pG[g];
    }
    float S = s0[i*16 + j];
    float Zs = 0.f;
    #pragma unroll
    for (int l = 0; l < 16; l++) Zs += z0[l];
    #pragma unroll
    for (int g = 0; g < NG; g++) {
        g_SGP[g*256 + tid] = S;
        if (tid == 0) g_ZGP[g] = Zs;
        if (pa[g]) { S = 0.f; Zs = 0.f; }
        S += sa[g]; Zs += za[g];
    }
}

// ------- pass 3: replay (64 steps) + attention output + MLP layer 1 -------
__global__ void apply_kernel(const void* __restrict__ startp,
                             const float* __restrict__ Wm1, const float* __restrict__ bm1)
{
    __shared__ float ks[CH2*16], qs[CH2*16], vs[CH2*16], ksums[CH2], qsums[CH2];
    __shared__ int stb[CH2];
    __shared__ float outb[2][16][17];
    int tid = threadIdx.x;
    int c2 = blockIdx.x;
    int c  = c2 >> 1;
    int odd = c2 & 1;
    int tb = c2 * CH2;
    int mode = g_startmode;
    for (int idx = tid; idx < CH2*16; idx += 256) {
        ks[idx] = g_k[tb*16 + idx];
        qs[idx] = g_q[tb*16 + idx];
        vs[idx] = g_v[tb*16 + idx];
    }
    if (tid < CH2)
        stb[tid] = read_start(startp, tb + tid, mode);
    __syncthreads();
    if (tid < CH2) {
        float sk = 0.f, sq = 0.f;
        #pragma unroll
        for (int i = 0; i < 16; i++) { sk += ks[tid*16+i]; sq += qs[tid*16+i]; }
        ksums[tid] = sk; qsums[tid] = sq;
    }
    float wm1r[16];
    #pragma unroll
    for (int l = 0; l < 16; l++) wm1r[l] = Wm1[tid*16 + l];
    float b1 = bm1[tid];
    // combine group prefix + local chunk prefix (+ first-half aggregate if odd)
    int grp = c >> 4;
    float Sl = g_Sloc[c*256 + tid];
    int   pl = g_ploc[c];
    float S  = pl ? Sl : (g_SGP[grp*256 + tid] + Sl);
    float Zl = g_Zloc[c];
    float Zs = pl ? Zl : (g_ZGP[grp] + Zl);
    if (odd) {
        float Sh = g_Shalf[c*256 + tid];
        float Zh = g_Zhalf[c];
        int   ph = g_phalf[c];
        if (ph) { S = Sh; Zs = Zh; }
        else    { S += Sh; Zs += Zh; }
    }
    __syncthreads();

    int i = tid & 15, j = tid >> 4;
    for (int t0 = 0; t0 < CH2; t0 += 16) {
        int buf = (t0 >> 4) & 1;
        #pragma unroll
        for (int tt = 0; tt < 16; tt++) {
            int t = t0 + tt;
            if (stb[t]) { S = 0.f; Zs = 0.f; }
            S  += ks[t*16 + i] * vs[t*16 + j];
            Zs += ksums[t];
            float pv = S * qs[t*16 + i];
            pv += __shfl_down_sync(0xffffffffu, pv, 8, 16);
            pv += __shfl_down_sync(0xffffffffu, pv, 4, 16);
            pv += __shfl_down_sync(0xffffffffu, pv, 2, 16);
            pv += __shfl_down_sync(0xffffffffu, pv, 1, 16);
            if (i == 0) {
                float denom = fmaxf(Zs * qsums[t], 1e-6f);
                outb[buf][tt][j] = pv / denom;
            }
        }
        __syncthreads();
        #pragma unroll
        for (int tt = 0; tt < 16; tt++) {
            const float* ob = outb[buf][tt];
            float h = b1;
            #pragma unroll
            for (int l = 0; l < 16; l++) h += wm1r[l] * ob[l];
            h = (h > 0.f) ? h : 0.01f * h;
            u32 ph = pack_bf16x2(h, h);
            float res = h - bf16lo_f(ph);
            u32 plp = pack_bf16x2(res, res);
            size_t off = (size_t)(tb + t0 + tt) * 256 + tid;
            g_h1hi[off] = (u16)ph;
            g_h1lo[off] = (u16)plp;
        }
    }
}

// ===== HMMA big GEMM: bf16x3 split, 3-stage cp.async, K-chunk 32, XOR swizzle =====
#define SOFF_AHI  0
#define SOFF_ALO  8192
#define SOFF_BHI  16384
#define SOFF_BLO  24576
#define STAGE_BYTES 32768
#define OFF_BIAS  (3*STAGE_BYTES)
#define GEMM_SMEM (OFF_BIAS + 512)

__device__ __forceinline__ void gemm_stage(
    u32 sbase, u32 stagebase, int kc,
    const u16* __restrict__ a1hi, const u16* __restrict__ a1lo,
    const u16* __restrict__ a2hi, const u16* __restrict__ a2lo,
    const u16* __restrict__ w1hi, const u16* __restrict__ w1lo,
    const u16* __restrict__ w2hi, const u16* __restrict__ w2lo,
    int rowbase, int colbase, int tid)
{
    int koff = (kc & 7) * 32;
    const u16* Whi = (kc < 8) ? w1hi : w2hi;
    const u16* Wlo = (kc < 8) ? w1lo : w2lo;
    const u16* Ahi = (kc < 8) ? a1hi : a2hi;
    const u16* Alo = (kc < 8) ? a1lo : a2lo;
    #pragma unroll
    for (int s = 0; s < 2; s++) {
        int idx = tid + s*256;        // 0..511
        int r  = idx >> 2;            // 0..127
        int sg = idx & 3;             // 16B chunk within 64B row
        u32 soff = (u32)(r*64 + ((sg ^ ((r >> 1) & 3)) << 4));
        size_t gea = (size_t)(rowbase + r) * 256 + koff + sg*8;
        size_t geb = (size_t)(colbase + r) * 256 + koff + sg*8;
        cp_async16(sbase + stagebase + SOFF_AHI + soff, Ahi + gea);
        cp_async16(sbase + stagebase + SOFF_ALO + soff, Alo + gea);
        cp_async16(sbase + stagebase + SOFF_BHI + soff, Whi + geb);
        cp_async16(sbase + stagebase + SOFF_BLO + soff, Wlo + geb);
    }
}

__global__ void __launch_bounds__(256, 2)
gemm_mma_kernel(const u16* __restrict__ a1hi, const u16* __restrict__ a1lo,
                const u16* __restrict__ a2hi, const u16* __restrict__ a2lo,
                const u16* __restrict__ w1hi, const u16* __restrict__ w1lo,
                const u16* __restrict__ w2hi, const u16* __restrict__ w2lo,
                const float* __restrict__ b1p, const float* __restrict__ b2p,
                int variant)
{
    extern __shared__ char smc[];
    u32 sbase = smem_to_u32(smc);
    float* bias_sm = (float*)(smc + OFF_BIAS);

    int nchunk = (variant == 0) ? 8 : 16;

    int tid  = threadIdx.x;
    int wid  = tid >> 5;
    int lane = tid & 31;
    int colbase = blockIdx.x * 128;
    int rowbase = blockIdx.y * 128;

    int warp_m = (wid >> 1) * 32;
    int warp_n = (wid & 1) * 64;

    for (int i = tid; i < 128; i += 256)
        bias_sm[i] = b1p[colbase + i] + ((variant != 0) ? b2p[colbase + i] : 0.f);

    float acc[2][8][4];
    #pragma unroll
    for (int mi = 0; mi < 2; mi++)
        #pragma unroll
        for (int nt = 0; nt < 8; nt++)
            #pragma unroll
            for (int r = 0; r < 4; r++) acc[mi][nt][r] = 0.f;

    // prologue: stage chunks 0 and 1
    gemm_stage(sbase, 0, 0, a1hi, a1lo, a2hi, a2lo, w1hi, w1lo, w2hi, w2lo,
               rowbase, colbase, tid);
    cp_commit();
    gemm_stage(sbase, STAGE_BYTES, 1, a1hi, a1lo, a2hi, a2lo, w1hi, w1lo, w2hi, w2lo,
               rowbase, colbase, tid);
    cp_commit();

    int lrow  = lane & 15;
    int chalf = lane >> 4;    // k8 half within the k16 step

    for (int kc = 0; kc < nchunk; kc++) {
        if (kc + 1 < nchunk) cp_wait1(); else cp_wait0();
        __syncthreads();

        u32 sb = (u32)((kc % 3) * STAGE_BYTES);
        // compute: 2 k16 steps on this k32 chunk
        #pragma unroll
        for (int ks = 0; ks < 2; ks++) {
            int cch = ks*2 + chalf;   // logical 16B chunk index 0..3
            u32 ahi[2][4], alo[2][4];
            #pragma unroll
            for (int mi = 0; mi < 2; mi++) {
                int row = warp_m + mi*16 + lrow;
                u32 off = sb + (u32)(row*64 + ((cch ^ ((row >> 1) & 3)) << 4));
                ldsm_x4(ahi[mi][0], ahi[mi][1], ahi[mi][2], ahi[mi][3], sbase + SOFF_AHI + off);
                ldsm_x4(alo[mi][0], alo[mi][1], alo[mi][2], alo[mi][3], sbase + SOFF_ALO + off);
            }
            #pragma unroll
            for (int gg = 0; gg < 4; gg++) {
                int row = warp_n + gg*16 + lrow;
                u32 off = sb + (u32)(row*64 + ((cch ^ ((row >> 1) & 3)) << 4));
                u32 bh[4], bl[4];
                ldsm_x4(bh[0], bh[1], bh[2], bh[3], sbase + SOFF_BHI + off);
                ldsm_x4(bl[0], bl[1], bl[2], bl[3], sbase + SOFF_BLO + off);
                #pragma unroll
                for (int mi = 0; mi < 2; mi++) {
                    #pragma unroll
                    for (int nj = 0; nj < 2; nj++) {
                        float* d = acc[mi][gg*2 + nj];
                        mma16816(d, ahi[mi], bh[nj], bh[2 + nj]);
                        mma16816(d, ahi[mi], bl[nj], bl[2 + nj]);
                        mma16816(d, alo[mi], bh[nj], bh[2 + nj]);
                    }
                }
            }
        }
        // stage kc+2 into buffer (kc+2)%3
        if (kc + 2 < nchunk) {
            gemm_stage(sbase, (u32)(((kc + 2) % 3) * STAGE_BYTES), kc + 2,
                       a1hi, a1lo, a2hi, a2lo, w1hi, w1lo, w2hi, w2lo,
                       rowbase, colbase, tid);
            cp_commit();
        }
    }

    // ---------------- epilogue ----------------
    #pragma unroll
    for (int mi = 0; mi < 2; mi++) {
        int row0 = rowbase + warp_m + mi*16 + (lane >> 2);
        #pragma unroll
        for (int nt = 0; nt < 8; nt++) {
            int colL = warp_n + nt*8 + (lane & 3)*2;
            int col  = colbase + colL;
            float b0 = bias_sm[colL], b1 = bias_sm[colL + 1];
            float v0 = acc[mi][nt][0] + b0;
            float v1 = acc[mi][nt][1] + b1;
            float v2 = acc[mi][nt][2] + b0;
            float v3 = acc[mi][nt][3] + b1;
            if (variant == 0) {
                v0 = (v0 > 0.f) ? v0 : 0.01f * v0;
                v1 = (v1 > 0.f) ? v1 : 0.01f * v1;
                v2 = (v2 > 0.f) ? v2 : 0.01f * v2;
                v3 = (v3 > 0.f) ? v3 : 0.01f * v3;
                u32 hp0 = pack_bf16x2(v0, v1);
                u32 lp0 = pack_bf16x2(v0 - bf16lo_f(hp0), v1 - bf16hi_f(hp0));
                u32 hp1 = pack_bf16x2(v2, v3);
                u32 lp1 = pack_bf16x2(v2 - bf16lo_f(hp1), v3 - bf16hi_f(hp1));
                size_t o0 = (size_t)row0 * 256 + col;
                size_t o1 = (size_t)(row0 + 8) * 256 + col;
                *(u32*)(g_h2hi + o0) = hp0;
                *(u32*)(g_h2lo + o0) = lp0;
                *(u32*)(g_h2hi + o1) = hp1;
                *(u32*)(g_h2lo + o1) = lp1;
            } else {
                *(float2*)(g_ypre + (size_t)row0 * 256 + col)       = make_float2(v0, v1);
                *(float2*)(g_ypre + (size_t)(row0 + 8) * 256 + col) = make_float2(v2, v3);
            }
        }
    }
}

// ---------------- LayerNorm + residual ----------------
__global__ void ln_kernel(const float* __restrict__ xext, float* __restrict__ outext,
                          const float* __restrict__ lw, const float* __restrict__ lb, int mode)
{
    int tid = threadIdx.x;
    int lane = tid & 31, w = tid >> 5;
    int row = blockIdx.x * 8 + w;
    const float* yp = g_ypre + (size_t)row * 256;
    float vals[8];
    float s = 0.f;
    #pragma unroll
    for (int u = 0; u < 8; u++) { vals[u] = yp[lane + u*32]; s += vals[u]; }
    #pragma unroll
    for (int d = 16; d >= 1; d >>= 1) s += __shfl_xor_sync(0xffffffffu, s, d);
    float mean = s * (1.f / 256.f);
    float v2 = 0.f;
    #pragma unroll
    for (int u = 0; u < 8; u++) { float d = vals[u] - mean; v2 += d * d; }
    #pragma unroll
    for (int d = 16; d >= 1; d >>= 1) v2 += __shfl_xor_sync(0xffffffffu, v2, d);
    float rstd = rsqrtf(v2 * (1.f / 256.f) + 1e-5f);

    if (mode == 0) {
        float* o = g_x1 + (size_t)row * 256;
        const float* xr = xext + (size_t)row * 256;
        #pragma unroll
        for (int u = 0; u < 8; u++) {
            int cl = lane + u*32;
            float y = xr[cl] + (vals[u] - mean) * rstd * lw[cl] + lb[cl];
            o[cl] = y;
            u32 ph = pack_bf16x2(y, y);
            float res = y - bf16lo_f(ph);
            u32 pl = pack_bf16x2(res, res);
            size_t off = (size_t)row * 256 + cl;
            g_x1hi[off] = (u16)ph;
            g_x1lo[off] = (u16)pl;
        }
    } else {
        float* o = outext + (size_t)row * 256;
        #pragma unroll
        for (int u = 0; u < 8; u++) {
            int cl = lane + u*32;
            o[cl] = (vals[u] - mean) * rstd * lw[cl] + lb[cl];
        }
    }
}

// ---------------- launch ----------------
extern "C" void kernel_launch(void* const* d_in, const int* in_sizes, int n_in,
                              void* d_out, int out_size)
{
    const float* x     = (const float*)d_in[0];
    const void*  start = d_in[1];
    const float* s0    = (const float*)d_in[2];
    const float* z0    = (const float*)d_in[3];
    const float* Wk    = (const float*)d_in[4];
    const float* Wq    = (const float*)d_in[5];
    const float* Wv    = (const float*)d_in[6];
    const float* bv    = (const float*)d_in[7];
    const float* Wskip = (const float*)d_in[8];
    const float* bskip = (const float*)d_in[9];
    const float* Wm1   = (const float*)d_in[10];
    const float* bm1   = (const float*)d_in[11];
    const float* Wm2   = (const float*)d_in[12];
    const float* bm2   = (const float*)d_in[13];
    const float* Wm3   = (const float*)d_in[14];
    const float* bm3   = (const float*)d_in[15];
    const float* lnw   = (const float*)d_in[16];
    const float* lnb   = (const float*)d_in[17];
    float* out = (float*)d_out;

    const int kqv_smem = (256*64 + KQV_ROWS*257) * 4;
    cudaFuncSetAttribute(kqv_kernel, cudaFuncAttributeMaxDynamicSharedMemorySize, kqv_smem);
    cudaFuncSetAttribute(gemm_mma_kernel, cudaFuncAttributeMaxDynamicSharedMemorySize, GEMM_SMEM);

    static u16 *whi_p = nullptr, *wlo_p = nullptr;
    static u16 *h1hi_p, *h1lo_p, *h2hi_p, *h2lo_p, *x1hi_p, *x1lo_p, *xhi_p, *xlo_p;
    if (!whi_p) {
        cudaGetSymbolAddress((void**)&whi_p,  g_whi);
        cudaGetSymbolAddress((void**)&wlo_p,  g_wlo);
        cudaGetSymbolAddress((void**)&h1hi_p, g_h1hi);
        cudaGetSymbolAddress((void**)&h1lo_p, g_h1lo);
        cudaGetSymbolAddress((void**)&h2hi_p, g_h2hi);
        cudaGetSymbolAddress((void**)&h2lo_p, g_h2lo);
        cudaGetSymbolAddress((void**)&x1hi_p, g_x1hi);
        cudaGetSymbolAddress((void**)&x1lo_p, g_x1lo);
        cudaGetSymbolAddress((void**)&xhi_p,  g_xhi);
        cudaGetSymbolAddress((void**)&xlo_p,  g_xlo);
    }

    init_kernel<<<385 + 2048, 256>>>((const unsigned char*)start, x,
        Wm2, Wm3, Wskip, Wm2 + 65536, Wm3 + 65536, Wskip + 65536);

    for (int b = 0; b < NBLK; b++) {
        kqv_kernel<<<NC, 256, kqv_smem>>>(x, b,
            Wk + b*16*256, Wq + b*16*256, Wv + b*16*256, bv + b*16, start);
        prefix1_kernel<<<NG, 256>>>();
        prefix2_kernel<<<1, 256>>>(s0 + b*256, z0 + b*16);
        apply_kernel<<<NC2, 256>>>(start, Wm1 + b*256*16, bm1 + b*256);

        const u16* wm2hi = whi_p + (b*3 + 0)*65536;
        const u16* wm2lo = wlo_p + (b*3 + 0)*65536;
        const u16* wm3hi = whi_p + (b*3 + 1)*65536;
        const u16* wm3lo = wlo_p + (b*3 + 1)*65536;
        const u16* wskhi = whi_p + (b*3 + 2)*65536;
        const u16* wsklo = wlo_p + (b*3 + 2)*65536;

        // h2 = leaky(h1 @ Wm2^T + bm2)
        gemm_mma_kernel<<<dim3(2, TT/128), 256, GEMM_SMEM>>>(
            h1hi_p, h1lo_p, h1hi_p, h1lo_p,
            wm2hi, wm2lo, wm2hi, wm2lo, bm2 + b*256, bm2 + b*256, 0);
        // ypre = h2 @ Wm3^T + A2 @ Wskip^T + bm3 + bskip
        gemm_mma_kernel<<<dim3(2, TT/128), 256, GEMM_SMEM>>>(
            h2hi_p, h2lo_p,
            (b == 0) ? xhi_p : x1hi_p, (b == 0) ? xlo_p : x1lo_p,
            wm3hi, wm3lo, wskhi, wsklo, bm3 + b*256, bskip + b*256,
            (b == 0) ? 1 : 2);
        ln_kernel<<<TT/8, 256>>>(x, out, lnw + b*256, lnb + b*256, (b == 0) ? 0 : 1);
    }
}

// round 12
// speedup vs baseline: 1.4706x; 1.2994x over previous
#include <cuda_runtime.h>
#include <cstdint>

typedef unsigned long long u64;
typedef unsigned int u32;
typedef unsigned short u16;

// Problem constants
#define TT   32768
#define DD   256
#define HH   256
#define KV   16
#define CH   128          // scan chunk length (kqv/prefix granularity)
#define CH2  64           // apply granularity (half chunks)
#define NC   (TT/CH)      // 256 chunks
#define NC2  (TT/CH2)     // 512 half-chunks
#define NG   16           // prefix groups (16 chunks each)
#define NBLK 2

// ---------------- device scratch (no allocations allowed) ----------------
__device__ float g_k[TT*KV];
__device__ float g_q[TT*KV];
__device__ float g_v[TT*KV];
__device__ float g_Sagg[NC*256];
__device__ float g_Zagg[NC];
__device__ int   g_pagg[NC];
__device__ float g_Shalf[NC*256];  // first-half (64-step) aggregates
__device__ float g_Zhalf[NC];
__device__ int   g_phalf[NC];
__device__ float g_Sloc[NC*256];   // local (within-group) exclusive prefixes
__device__ float g_Zloc[NC];
__device__ int   g_ploc[NC];
__device__ float g_SG[NG*256];     // group aggregates
__device__ float g_ZG[NG];
__device__ int   g_pG[NG];
__device__ float g_SGP[NG*256];    // group exclusive prefixes (incl s0 init)
__device__ float g_ZGP[NG];
__device__ float g_ypre[TT*HH];
__device__ int   g_startmode;   // 0=u8 bool, 1=int32, 2=float32

// bf16 hi/lo split operand storage
__device__ u16 g_h1hi[TT*HH];
__device__ u16 g_h1lo[TT*HH];
__device__ u16 g_h2hi[TT*HH];
__device__ u16 g_h2lo[TT*HH];
__device__ u16 g_x1hi[TT*HH];
__device__ u16 g_x1lo[TT*HH];
__device__ u16 g_xhi[TT*DD];
__device__ u16 g_xlo[TT*DD];
__device__ u16 g_whi[6*65536];   // [mat][256][256]: per block {Wm2, Wm3, Wskip}
__device__ u16 g_wlo[6*65536];
__device__ u16 g_kwhi[2*48*256]; // per block combined {Wk,Wq,Wv} rows 0..47
__device__ u16 g_kwlo[2*48*256];

// ---------------- helpers ----------------
__device__ __forceinline__ float phi_fn(float t) {
    return (t > 0.f) ? (1.f + t) : __expf(t);
}

__device__ __forceinline__ int read_start(const void* p, int t, int mode) {
    if (mode == 0) return ((const unsigned char*)p)[t] != 0;
    if (mode == 1) return ((const int*)p)[t] != 0;
    return ((const float*)p)[t] != 0.f;
}

__device__ __forceinline__ u32 pack_bf16x2(float lo, float hi) {
    u32 r;
    asm("cvt.rn.bf16x2.f32 %0, %1, %2;" : "=r"(r) : "f"(hi), "f"(lo));
    return r;
}
__device__ __forceinline__ float bf16lo_f(u32 p) { return __uint_as_float(p << 16); }
__device__ __forceinline__ float bf16hi_f(u32 p) { return __uint_as_float(p & 0xffff0000u); }

__device__ __forceinline__ u32 smem_to_u32(const void* smem_ptr) {
    u32 addr;
    asm("{ .reg .u64 tmp; cvta.to.shared.u64 tmp, %1; cvt.u32.u64 %0, tmp; }"
        : "=r"(addr) : "l"(smem_ptr));
    return addr;
}

__device__ __forceinline__ void cp_async16(u32 saddr, const void* gptr) {
    asm volatile("cp.async.cg.shared.global [%0], [%1], 16;" :: "r"(saddr), "l"(gptr));
}
__device__ __forceinline__ void cp_commit() {
    asm volatile("cp.async.commit_group;" ::: "memory");
}
__device__ __forceinline__ void cp_wait0() {
    asm volatile("cp.async.wait_group 0;" ::: "memory");
}
__device__ __forceinline__ void cp_wait1() {
    asm volatile("cp.async.wait_group 1;" ::: "memory");
}

__device__ __forceinline__ void ldsm_x4(u32& r0, u32& r1, u32& r2, u32& r3, u32 addr) {
    asm volatile("ldmatrix.sync.aligned.m8n8.x4.shared.b16 {%0,%1,%2,%3}, [%4];"
        : "=r"(r0), "=r"(r1), "=r"(r2), "=r"(r3) : "r"(addr));
}

__device__ __forceinline__ void mma16816(float* d, const u32* a, u32 b0, u32 b1) {
    asm volatile(
        "mma.sync.aligned.m16n8k16.row.col.f32.bf16.bf16.f32 "
        "{%0,%1,%2,%3}, {%4,%5,%6,%7}, {%8,%9}, {%0,%1,%2,%3};"
        : "+f"(d[0]), "+f"(d[1]), "+f"(d[2]), "+f"(d[3])
        : "r"(a[0]), "r"(a[1]), "r"(a[2]), "r"(a[3]), "r"(b0), "r"(b1));
}

// ---------------- init: weight split + detect + x split + kqv-weight split ------
// blocks [0,384): big weights; 384: detect; [385,2433): x split; [2433,2457): kqv W
__global__ void init_kernel(const unsigned char* __restrict__ p,
                            const float* __restrict__ x,
                            const float* __restrict__ w0, const float* __restrict__ w1,
                            const float* __restrict__ w2, const float* __restrict__ w3,
                            const float* __restrict__ w4, const float* __restrict__ w5,
                            const float* __restrict__ Wk, const float* __restrict__ Wq,
                            const float* __restrict__ Wv)
{
    int tid = threadIdx.x;
    int bid = blockIdx.x;
    if (bid < 384) {
        int qi = bid * 256 + tid;        // 0..98303
        int mat = qi >> 14;              // 0..5
        int idx = (qi & 16383) * 4;      // element index within mat
        const float* src;
        switch (mat) {
            case 0: src = w0; break;
            case 1: src = w1; break;
            case 2: src = w2; break;
            case 3: src = w3; break;
            case 4: src = w4; break;
            default: src = w5; break;
        }
        float4 v = *(const float4*)(src + idx);
        u32 h0 = pack_bf16x2(v.x, v.y);
        u32 h1 = pack_bf16x2(v.z, v.w);
        u32 l0 = pack_bf16x2(v.x - bf16lo_f(h0), v.y - bf16hi_f(h0));
        u32 l1 = pack_bf16x2(v.z - bf16lo_f(h1), v.w - bf16hi_f(h1));
        u16* dh = g_whi + mat*65536 + idx;
        u16* dl = g_wlo + mat*65536 + idx;
        *(u32*)(dh)     = h0;
        *(u32*)(dh + 2) = h1;
        *(u32*)(dl)     = l0;
        *(u32*)(dl + 2) = l1;
    } else if (bid == 384) {
        __shared__ int cnt1, cnt3f;
        if (tid == 0) { cnt1 = 0; cnt3f = 0; }
        __syncthreads();
        int l1 = 0, l3 = 0;
        for (int idx = tid; idx < 4096; idx += 256) {
            unsigned char b = p[idx];
            if ((idx & 3) != 0 && b != 0) l1++;
            if ((idx & 3) == 3 && b == 0x3F) l3++;
        }
        atomicAdd(&cnt1, l1); atomicAdd(&cnt3f, l3);
        __syncthreads();
        if (tid == 0) g_startmode = (cnt3f > 0) ? 2 : ((cnt1 > 0) ? 0 : 1);
    } else if (bid < 2433) {
        int qbase = (bid - 385) * 1024;
        #pragma unroll
        for (int s = 0; s < 4; s++) {
            int base = (qbase + s*256 + tid) * 4;
            float4 v = *(const float4*)(x + base);
            u32 h0 = pack_bf16x2(v.x, v.y);
            u32 h1 = pack_bf16x2(v.z, v.w);
            u32 l0 = pack_bf16x2(v.x - bf16lo_f(h0), v.y - bf16hi_f(h0));
            u32 l1 = pack_bf16x2(v.z - bf16lo_f(h1), v.w - bf16hi_f(h1));
            *(u32*)(g_xhi + base)     = h0;
            *(u32*)(g_xhi + base + 2) = h1;
            *(u32*)(g_xlo + base)     = l0;
            *(u32*)(g_xlo + base + 2) = l1;
        }
    } else {
        int qi = (bid - 2433) * 256 + tid;   // 0..6143 float4
        int el = qi * 4;                      // 0..24575
        int b  = el / 12288;
        int rem = el - b*12288;
        int row = rem >> 8;                   // 0..47
        int c   = rem & 255;
        const float* src;
        int lr;
        if (row < 16)      { src = Wk + b*16*256; lr = row; }
        else if (row < 32) { src = Wq + b*16*256; lr = row - 16; }
        else               { src = Wv + b*16*256; lr = row - 32; }
        float4 v = *(const float4*)(src + lr*256 + c);
        u32 h0 = pack_bf16x2(v.x, v.y);
        u32 h1 = pack_bf16x2(v.z, v.w);
        u32 l0 = pack_bf16x2(v.x - bf16lo_f(h0), v.y - bf16hi_f(h0));
        u32 l1 = pack_bf16x2(v.z - bf16lo_f(h1), v.w - bf16hi_f(h1));
        u16* dh = g_kwhi + el;
        u16* dl = g_kwlo + el;
        *(u32*)(dh)     = h0;
        *(u32*)(dh + 2) = h1;
        *(u32*)(dl)     = l0;
        *(u32*)(dl + 2) = l1;
    }
}

// ======= kqv via HMMA: x(128 rows) @ {Wk,Wq,Wv}^T (48 outs) + chunk aggregate =======
// SMEM: W tiles [8 chunks][48 rows][64B] hi+lo = 49152; A 3-stage 3*16384 = 49152.
// Scan arrays overlap A stages (used only after all compute). BVS lives OUTSIDE
// the A-stage region (bugfix R11: it must survive staging).
#define KQ_KWHI   0
#define KQ_KWLO   24576
#define KQ_ASTG   49152
#define KQ_ASTGB  16384      // per stage: AHI at +0 (8192), ALO at +8192
#define KQ_KS     49152      // overlap with A stages (floats) — post-compute only
#define KQ_VS     57344
#define KQ_KSUM   65536
#define KQ_STB    66048
#define KQ_BVS    98304      // OUTSIDE A stages (49152..98304)
#define KQV2_SMEM 98432

__global__ void __launch_bounds__(256, 2)
kqv_mma_kernel(const u16* __restrict__ axhi, const u16* __restrict__ axlo,
               const u16* __restrict__ kwhi, const u16* __restrict__ kwlo,
               const float* __restrict__ bv, const void* __restrict__ startp)
{
    extern __shared__ char smc[];
    u32 sbase = smem_to_u32(smc);
    int tid  = threadIdx.x;
    int wid  = tid >> 5;
    int lane = tid & 31;
    int lrow = lane & 15;
    int chalf = lane >> 4;
    int base = blockIdx.x * CH;
    int mode = g_startmode;

    float* bvs = (float*)(smc + KQ_BVS);
    if (tid < 16) bvs[tid] = bv[tid];

    // stage full W (one group)
    for (int idx = tid; idx < 1536; idx += 256) {
        int kc  = idx / 192;
        int rem = idx - kc*192;
        int r   = rem >> 2;
        int sg  = rem & 3;
        u32 soff = (u32)(kc*3072 + r*64 + ((sg ^ ((r >> 1) & 3)) << 4));
        size_t ge = (size_t)r*256 + kc*32 + sg*8;
        cp_async16(sbase + KQ_KWHI + soff, kwhi + ge);
        cp_async16(sbase + KQ_KWLO + soff, kwlo + ge);
    }
    cp_commit();

    // stage A chunks 0,1
    #pragma unroll
    for (int pk = 0; pk < 2; pk++) {
        u32 stg = KQ_ASTG + pk*KQ_ASTGB;
        #pragma unroll
        for (int s = 0; s < 2; s++) {
            int idx = tid + s*256;
            int r = idx >> 2, sg = idx & 3;
            u32 soff = (u32)(r*64 + ((sg ^ ((r >> 1) & 3)) << 4));
            size_t ge = (size_t)(base + r)*256 + pk*32 + sg*8;
            cp_async16(sbase + stg + soff, axhi + ge);
            cp_async16(sbase + stg + 8192 + soff, axlo + ge);
        }
        cp_commit();
    }

    float acc[6][4];
    #pragma unroll
    for (int nt = 0; nt < 6; nt++)
        #pragma unroll
        for (int r = 0; r < 4; r++) acc[nt][r] = 0.f;

    for (int kc = 0; kc < 8; kc++) {
        if (kc + 1 < 8) cp_wait1(); else cp_wait0();
        __syncthreads();

        u32 sb = (u32)(KQ_ASTG + (kc % 3)*KQ_ASTGB);
        #pragma unroll
        for (int ks = 0; ks < 2; ks++) {
            int cch = ks*2 + chalf;
            int arow = wid*16 + lrow;
            u32 aoff = sb + (u32)(arow*64 + ((cch ^ ((arow >> 1) & 3)) << 4));
            u32 ahi[4], alo[4];
            ldsm_x4(ahi[0], ahi[1], ahi[2], ahi[3], sbase + aoff);
            ldsm_x4(alo[0], alo[1], alo[2], alo[3], sbase + aoff + 8192);
            #pragma unroll
            for (int bg = 0; bg < 3; bg++) {
                int brow = bg*16 + lrow;
                u32 boff = (u32)(kc*3072 + brow*64 + ((cch ^ ((brow >> 1) & 3)) << 4));
                u32 bh[4], bl[4];
                ldsm_x4(bh[0], bh[1], bh[2], bh[3], sbase + KQ_KWHI + boff);
                ldsm_x4(bl[0], bl[1], bl[2], bl[3], sbase + KQ_KWLO + boff);
                #pragma unroll
                for (int nj = 0; nj < 2; nj++) {
                    float* d = acc[bg*2 + nj];
                    mma16816(d, ahi, bh[nj], bh[2 + nj]);
                    mma16816(d, ahi, bl[nj], bl[2 + nj]);
                    mma16816(d, alo, bh[nj], bh[2 + nj]);
                }
            }
        }
        if (kc + 2 < 8) {
            u32 stg = KQ_ASTG + ((kc + 2) % 3)*KQ_ASTGB;
            #pragma unroll
            for (int s = 0; s < 2; s++) {
                int idx = tid + s*256;
                int r = idx >> 2, sg = idx & 3;
                u32 soff = (u32)(r*64 + ((sg ^ ((r >> 1) & 3)) << 4));
                size_t ge = (size_t)(base + r)*256 + (kc + 2)*32 + sg*8;
                cp_async16(sbase + stg + soff, axhi + ge);
                cp_async16(sbase + stg + 8192 + soff, axlo + ge);
            }
            cp_commit();
        }
    }
    __syncthreads();   // all ldsm done before scan arrays overwrite A stages

    float* ks_sm = (float*)(smc + KQ_KS);
    float* vs_sm = (float*)(smc + KQ_VS);
    float* ksums = (float*)(smc + KQ_KSUM);
    int*   stb   = (int*)(smc + KQ_STB);

    // epilogue: phi/bias, write k/q/v (gmem) + ks/vs (smem)
    int r0 = wid*16 + (lane >> 2);
    #pragma unroll
    for (int nt = 0; nt < 6; nt++) {
        int colL = nt*8 + (lane & 3)*2;
        #pragma unroll
        for (int rr = 0; rr < 2; rr++) {
            int row = r0 + rr*8;
            int t   = base + row;
            float v0 = acc[nt][rr*2 + 0];
            float v1 = acc[nt][rr*2 + 1];
            if (colL < 16) {
                float p0 = phi_fn(v0), p1 = phi_fn(v1);
                *(float2*)(g_k + (size_t)t*16 + colL) = make_float2(p0, p1);
                ks_sm[row*16 + colL]     = p0;
                ks_sm[row*16 + colL + 1] = p1;
            } else if (colL < 32) {
                int o = colL - 16;
                *(float2*)(g_q + (size_t)t*16 + o) = make_float2(phi_fn(v0), phi_fn(v1));
            } else {
                int o = colL - 32;
                float w0 = v0 + bvs[o], w1 = v1 + bvs[o + 1];
                *(float2*)(g_v + (size_t)t*16 + o) = make_float2(w0, w1);
                vs_sm[row*16 + o]     = w0;
                vs_sm[row*16 + o + 1] = w1;
            }
        }
    }
    __syncthreads();

    if (tid < 128) {
        float s = 0.f;
        #pragma unroll
        for (int i = 0; i < 16; i++) s += ks_sm[tid*16 + i];
        ksums[tid] = s;
        stb[tid] = read_start(startp, base + tid, mode);
    }
    __syncthreads();

    int i = tid & 15, j = tid >> 4;
    float S = 0.f, Zs = 0.f; int p = 0;
    for (int t = 0; t < CH; t++) {
        if (t == CH2) {
            g_Shalf[blockIdx.x*256 + tid] = S;
            if (tid == 0) { g_Zhalf[blockIdx.x] = Zs; g_phalf[blockIdx.x] = p; }
        }
        if (stb[t]) { S = 0.f; Zs = 0.f; p = 1; }
        S  += ks_sm[t*16 + i] * vs_sm[t*16 + j];
        Zs += ksums[t];
    }
    g_Sagg[blockIdx.x*256 + tid] = S;
    if (tid == 0) { g_Zagg[blockIdx.x] = Zs; g_pagg[blockIdx.x] = p; }
}

// ---------------- prefix level 1: 16 CTAs, 16 chunks each (prefetched) --------
__global__ void prefix1_kernel()
{
    int tid = threadIdx.x;
    int g = blockIdx.x;
    float sa[16], za[16]; int pa[16];
    #pragma unroll
    for (int d = 0; d < 16; d++) {
        int c = g*16 + d;
        sa[d] = g_Sagg[c*256 + tid];
        za[d] = g_Zagg[c];
        pa[d] = g_pagg[c];
    }
    float S = 0.f, Zs = 0.f; int p = 0;
    #pragma unroll
    for (int d = 0; d < 16; d++) {
        int c = g*16 + d;
        g_Sloc[c*256 + tid] = S;
        if (tid == 0) { g_Zloc[c] = Zs; g_ploc[c] = p; }
        if (pa[d]) { S = 0.f; Zs = 0.f; }
        S += sa[d]; Zs += za[d]; p |= pa[d];
    }
    g_SG[g*256 + tid] = S;
    if (tid == 0) { g_ZG[g] = Zs; g_pG[g] = p; }
}

// ---------------- prefix level 2: scan 16 group aggregates (prefetched) -------
__global__ void prefix2_kernel(const float* __restrict__ s0, const float* __restrict__ z0)
{
    int tid = threadIdx.x;
    int i = tid & 15, j = tid >> 4;
    float sa[NG], za[NG]; int pa[NG];
    #pragma unroll
    for (int g = 0; g < NG; g++) {
        sa[g] = g_SG[g*256 + tid];
        za[g] = g_ZG[g];
        pa[g] = g_pG[g];
    }
    float S = s0[i*16 + j];
    float Zs = 0.f;
    #pragma unroll
    for (int l = 0; l < 16; l++) Zs += z0[l];
    #pragma unroll
    for (int g = 0; g < NG; g++) {
        g_SGP[g*256 + tid] = S;
        if (tid == 0) g_ZGP[g] = Zs;
        if (pa[g]) { S = 0.f; Zs = 0.f; }
        S += sa[g]; Zs += za[g];
    }
}

// ------- pass 3: replay (64 steps) + attention output + MLP layer 1 -------
__global__ void apply_kernel(const void* __restrict__ startp,
                             const float* __restrict__ Wm1, const float* __restrict__ bm1)
{
    __shared__ float ks[CH2*16], qs[CH2*16], vs[CH2*16], ksums[CH2], qsums[CH2];
    __shared__ int stb[CH2];
    __shared__ float outb[2][16][17];
    int tid = threadIdx.x;
    int c2 = blockIdx.x;
    int c  = c2 >> 1;
    int odd = c2 & 1;
    int tb = c2 * CH2;
    int mode = g_startmode;
    for (int idx = tid; idx < CH2*16; idx += 256) {
        ks[idx] = g_k[tb*16 + idx];
        qs[idx] = g_q[tb*16 + idx];
        vs[idx] = g_v[tb*16 + idx];
    }
    if (tid < CH2)
        stb[tid] = read_start(startp, tb + tid, mode);
    __syncthreads();
    if (tid < CH2) {
        float sk = 0.f, sq = 0.f;
        #pragma unroll
        for (int i = 0; i < 16; i++) { sk += ks[tid*16+i]; sq += qs[tid*16+i]; }
        ksums[tid] = sk; qsums[tid] = sq;
    }
    float wm1r[16];
    #pragma unroll
    for (int l = 0; l < 16; l++) wm1r[l] = Wm1[tid*16 + l];
    float b1 = bm1[tid];
    int grp = c >> 4;
    float Sl = g_Sloc[c*256 + tid];
    int   pl = g_ploc[c];
    float S  = pl ? Sl : (g_SGP[grp*256 + tid] + Sl);
    float Zl = g_Zloc[c];
    float Zs = pl ? Zl : (g_ZGP[grp] + Zl);
    if (odd) {
        float Sh = g_Shalf[c*256 + tid];
        float Zh = g_Zhalf[c];
        int   ph = g_phalf[c];
        if (ph) { S = Sh; Zs = Zh; }
        else    { S += Sh; Zs += Zh; }
    }
    __syncthreads();

    int i = tid & 15, j = tid >> 4;
    for (int t0 = 0; t0 < CH2; t0 += 16) {
        int buf = (t0 >> 4) & 1;
        #pragma unroll
        for (int tt = 0; tt < 16; tt++) {
            int t = t0 + tt;
            if (stb[t]) { S = 0.f; Zs = 0.f; }
            S  += ks[t*16 + i] * vs[t*16 + j];
            Zs += ksums[t];
            float pv = S * qs[t*16 + i];
            pv += __shfl_down_sync(0xffffffffu, pv, 8, 16);
            pv += __shfl_down_sync(0xffffffffu, pv, 4, 16);
            pv += __shfl_down_sync(0xffffffffu, pv, 2, 16);
            pv += __shfl_down_sync(0xffffffffu, pv, 1, 16);
            if (i == 0) {
                float denom = fmaxf(Zs * qsums[t], 1e-6f);
                outb[buf][tt][j] = pv / denom;
            }
        }
        __syncthreads();
        #pragma unroll
        for (int tt = 0; tt < 16; tt++) {
            const float* ob = outb[buf][tt];
            float h = b1;
            #pragma unroll
            for (int l = 0; l < 16; l++) h += wm1r[l] * ob[l];
            h = (h > 0.f) ? h : 0.01f * h;
            u32 ph = pack_bf16x2(h, h);
            float res = h - bf16lo_f(ph);
            u32 plp = pack_bf16x2(res, res);
            size_t off = (size_t)(tb + t0 + tt) * 256 + tid;
            g_h1hi[off] = (u16)ph;
            g_h1lo[off] = (u16)plp;
        }
    }
}

// ===== HMMA big GEMM: bf16x3 split, 3-stage cp.async, K-chunk 32, XOR swizzle =====
#define SOFF_AHI  0
#define SOFF_ALO  8192
#define SOFF_BHI  16384
#define SOFF_BLO  24576
#define STAGE_BYTES 32768
#define OFF_BIAS  (3*STAGE_BYTES)
#define GEMM_SMEM (OFF_BIAS + 512)

__device__ __forceinline__ void gemm_stage(
    u32 sbase, u32 stagebase, int kc,
    const u16* __restrict__ a1hi, const u16* __restrict__ a1lo,
    const u16* __restrict__ a2hi, const u16* __restrict__ a2lo,
    const u16* __restrict__ w1hi, const u16* __restrict__ w1lo,
    const u16* __restrict__ w2hi, const u16* __restrict__ w2lo,
    int rowbase, int colbase, int tid)
{
    int koff = (kc & 7) * 32;
    const u16* Whi = (kc < 8) ? w1hi : w2hi;
    const u16* Wlo = (kc < 8) ? w1lo : w2lo;
    const u16* Ahi = (kc < 8) ? a1hi : a2hi;
    const u16* Alo = (kc < 8) ? a1lo : a2lo;
    #pragma unroll
    for (int s = 0; s < 2; s++) {
        int idx = tid + s*256;        // 0..511
        int r  = idx >> 2;            // 0..127
        int sg = idx & 3;             // 16B chunk within 64B row
        u32 soff = (u32)(r*64 + ((sg ^ ((r >> 1) & 3)) << 4));
        size_t gea = (size_t)(rowbase + r) * 256 + koff + sg*8;
        size_t geb = (size_t)(colbase + r) * 256 + koff + sg*8;
        cp_async16(sbase + stagebase + SOFF_AHI + soff, Ahi + gea);
        cp_async16(sbase + stagebase + SOFF_ALO + soff, Alo + gea);
        cp_async16(sbase + stagebase + SOFF_BHI + soff, Whi + geb);
        cp_async16(sbase + stagebase + SOFF_BLO + soff, Wlo + geb);
    }
}

__global__ void __launch_bounds__(256, 2)
gemm_mma_kernel(const u16* __restrict__ a1hi, const u16* __restrict__ a1lo,
                const u16* __restrict__ a2hi, const u16* __restrict__ a2lo,
                const u16* __restrict__ w1hi, const u16* __restrict__ w1lo,
                const u16* __restrict__ w2hi, const u16* __restrict__ w2lo,
                const float* __restrict__ b1p, const float* __restrict__ b2p,
                int variant)
{
    extern __shared__ char smc[];
    u32 sbase = smem_to_u32(smc);
    float* bias_sm = (float*)(smc + OFF_BIAS);

    int nchunk = (variant == 0) ? 8 : 16;

    int tid  = threadIdx.x;
    int wid  = tid >> 5;
    int lane = tid & 31;
    int colbase = blockIdx.x * 128;
    int rowbase = blockIdx.y * 128;

    int warp_m = (wid >> 1) * 32;
    int warp_n = (wid & 1) * 64;

    for (int i = tid; i < 128; i += 256)
        bias_sm[i] = b1p[colbase + i] + ((variant != 0) ? b2p[colbase + i] : 0.f);

    float acc[2][8][4];
    #pragma unroll
    for (int mi = 0; mi < 2; mi++)
        #pragma unroll
        for (int nt = 0; nt < 8; nt++)
            #pragma unroll
            for (int r = 0; r < 4; r++) acc[mi][nt][r] = 0.f;

    gemm_stage(sbase, 0, 0, a1hi, a1lo, a2hi, a2lo, w1hi, w1lo, w2hi, w2lo,
               rowbase, colbase, tid);
    cp_commit();
    gemm_stage(sbase, STAGE_BYTES, 1, a1hi, a1lo, a2hi, a2lo, w1hi, w1lo, w2hi, w2lo,
               rowbase, colbase, tid);
    cp_commit();

    int lrow  = lane & 15;
    int chalf = lane >> 4;

    for (int kc = 0; kc < nchunk; kc++) {
        if (kc + 1 < nchunk) cp_wait1(); else cp_wait0();
        __syncthreads();

        u32 sb = (u32)((kc % 3) * STAGE_BYTES);
        #pragma unroll
        for (int ks = 0; ks < 2; ks++) {
            int cch = ks*2 + chalf;
            u32 ahi[2][4], alo[2][4];
            #pragma unroll
            for (int mi = 0; mi < 2; mi++) {
                int row = warp_m + mi*16 + lrow;
                u32 off = sb + (u32)(row*64 + ((cch ^ ((row >> 1) & 3)) << 4));
                ldsm_x4(ahi[mi][0], ahi[mi][1], ahi[mi][2], ahi[mi][3], sbase + SOFF_AHI + off);
                ldsm_x4(alo[mi][0], alo[mi][1], alo[mi][2], alo[mi][3], sbase + SOFF_ALO + off);
            }
            #pragma unroll
            for (int gg = 0; gg < 4; gg++) {
                int row = warp_n + gg*16 + lrow;
                u32 off = sb + (u32)(row*64 + ((cch ^ ((row >> 1) & 3)) << 4));
                u32 bh[4], bl[4];
                ldsm_x4(bh[0], bh[1], bh[2], bh[3], sbase + SOFF_BHI + off);
                ldsm_x4(bl[0], bl[1], bl[2], bl[3], sbase + SOFF_BLO + off);
                #pragma unroll
                for (int mi = 0; mi < 2; mi++) {
                    #pragma unroll
                    for (int nj = 0; nj < 2; nj++) {
                        float* d = acc[mi][gg*2 + nj];
                        mma16816(d, ahi[mi], bh[nj], bh[2 + nj]);
                        mma16816(d, ahi[mi], bl[nj], bl[2 + nj]);
                        mma16816(d, alo[mi], bh[nj], bh[2 + nj]);
                    }
                }
            }
        }
        if (kc + 2 < nchunk) {
            gemm_stage(sbase, (u32)(((kc + 2) % 3) * STAGE_BYTES), kc + 2,
                       a1hi, a1lo, a2hi, a2lo, w1hi, w1lo, w2hi, w2lo,
                       rowbase, colbase, tid);
            cp_commit();
        }
    }

    // ---------------- epilogue ----------------
    #pragma unroll
    for (int mi = 0; mi < 2; mi++) {
        int row0 = rowbase + warp_m + mi*16 + (lane >> 2);
        #pragma unroll
        for (int nt = 0; nt < 8; nt++) {
            int colL = warp_n + nt*8 + (lane & 3)*2;
            int col  = colbase + colL;
            float b0 = bias_sm[colL], b1 = bias_sm[colL + 1];
            float v0 = acc[mi][nt][0] + b0;
            float v1 = acc[mi][nt][1] + b1;
            float v2 = acc[mi][nt][2] + b0;
            float v3 = acc[mi][nt][3] + b1;
            if (variant == 0) {
                v0 = (v0 > 0.f) ? v0 : 0.01f * v0;
                v1 = (v1 > 0.f) ? v1 : 0.01f * v1;
                v2 = (v2 > 0.f) ? v2 : 0.01f * v2;
                v3 = (v3 > 0.f) ? v3 : 0.01f * v3;
                u32 hp0 = pack_bf16x2(v0, v1);
                u32 lp0 = pack_bf16x2(v0 - bf16lo_f(hp0), v1 - bf16hi_f(hp0));
                u32 hp1 = pack_bf16x2(v2, v3);
                u32 lp1 = pack_bf16x2(v2 - bf16lo_f(hp1), v3 - bf16hi_f(hp1));
                size_t o0 = (size_t)row0 * 256 + col;
                size_t o1 = (size_t)(row0 + 8) * 256 + col;
                *(u32*)(g_h2hi + o0) = hp0;
                *(u32*)(g_h2lo + o0) = lp0;
                *(u32*)(g_h2hi + o1) = hp1;
                *(u32*)(g_h2lo + o1) = lp1;
            } else {
                *(float2*)(g_ypre + (size_t)row0 * 256 + col)       = make_float2(v0, v1);
                *(float2*)(g_ypre + (size_t)(row0 + 8) * 256 + col) = make_float2(v2, v3);
            }
        }
    }
}

// ---------------- LayerNorm + residual ----------------
// mode 0: x1 split = xext + LN(g_ypre)    (block 0; splits only)
// mode 1: outext = LN(g_ypre)             (block 1, final output)
__global__ void ln_kernel(const float* __restrict__ xext, float* __restrict__ outext,
                          const float* __restrict__ lw, const float* __restrict__ lb, int mode)
{
    int tid = threadIdx.x;
    int lane = tid & 31, w = tid >> 5;
    int row = blockIdx.x * 8 + w;
    const float* yp = g_ypre + (size_t)row * 256;
    float vals[8];
    float s = 0.f;
    #pragma unroll
    for (int u = 0; u < 8; u++) { vals[u] = yp[lane + u*32]; s += vals[u]; }
    #pragma unroll
    for (int d = 16; d >= 1; d >>= 1) s += __shfl_xor_sync(0xffffffffu, s, d);
    float mean = s * (1.f / 256.f);
    float v2 = 0.f;
    #pragma unroll
    for (int u = 0; u < 8; u++) { float d = vals[u] - mean; v2 += d * d; }
    #pragma unroll
    for (int d = 16; d >= 1; d >>= 1) v2 += __shfl_xor_sync(0xffffffffu, v2, d);
    float rstd = rsqrtf(v2 * (1.f / 256.f) + 1e-5f);

    if (mode == 0) {
        const float* xr = xext + (size_t)row * 256;
        #pragma unroll
        for (int u = 0; u < 8; u++) {
            int cl = lane + u*32;
            float y = xr[cl] + (vals[u] - mean) * rstd * lw[cl] + lb[cl];
            u32 ph = pack_bf16x2(y, y);
            float res = y - bf16lo_f(ph);
            u32 pl = pack_bf16x2(res, res);
            size_t off = (size_t)row * 256 + cl;
            g_x1hi[off] = (u16)ph;
            g_x1lo[off] = (u16)pl;
        }
    } else {
        float* o = outext + (size_t)row * 256;
        #pragma unroll
        for (int u = 0; u < 8; u++) {
            int cl = lane + u*32;
            o[cl] = (vals[u] - mean) * rstd * lw[cl] + lb[cl];
        }
    }
}

// ---------------- launch ----------------
extern "C" void kernel_launch(void* const* d_in, const int* in_sizes, int n_in,
                              void* d_out, int out_size)
{
    const float* x     = (const float*)d_in[0];
    const void*  start = d_in[1];
    const float* s0    = (const float*)d_in[2];
    const float* z0    = (const float*)d_in[3];
    const float* Wk    = (const float*)d_in[4];
    const float* Wq    = (const float*)d_in[5];
    const float* Wv    = (const float*)d_in[6];
    const float* bv    = (const float*)d_in[7];
    const float* Wskip = (const float*)d_in[8];
    const float* bskip = (const float*)d_in[9];
    const float* Wm1   = (const float*)d_in[10];
    const float* bm1   = (const float*)d_in[11];
    const float* Wm2   = (const float*)d_in[12];
    const float* bm2   = (const float*)d_in[13];
    const float* Wm3   = (const float*)d_in[14];
    const float* bm3   = (const float*)d_in[15];
    const float* lnw   = (const float*)d_in[16];
    const float* lnb   = (const float*)d_in[17];
    float* out = (float*)d_out;

    cudaFuncSetAttribute(kqv_mma_kernel, cudaFuncAttributeMaxDynamicSharedMemorySize, KQV2_SMEM);
    cudaFuncSetAttribute(gemm_mma_kernel, cudaFuncAttributeMaxDynamicSharedMemorySize, GEMM_SMEM);

    static u16 *whi_p = nullptr, *wlo_p = nullptr;
    static u16 *h1hi_p, *h1lo_p, *h2hi_p, *h2lo_p, *x1hi_p, *x1lo_p, *xhi_p, *xlo_p;
    static u16 *kwhi_p, *kwlo_p;
    if (!whi_p) {
        cudaGetSymbolAddress((void**)&whi_p,  g_whi);
        cudaGetSymbolAddress((void**)&wlo_p,  g_wlo);
        cudaGetSymbolAddress((void**)&h1hi_p, g_h1hi);
        cudaGetSymbolAddress((void**)&h1lo_p, g_h1lo);
        cudaGetSymbolAddress((void**)&h2hi_p, g_h2hi);
        cudaGetSymbolAddress((void**)&h2lo_p, g_h2lo);
        cudaGetSymbolAddress((void**)&x1hi_p, g_x1hi);
        cudaGetSymbolAddress((void**)&x1lo_p, g_x1lo);
        cudaGetSymbolAddress((void**)&xhi_p,  g_xhi);
        cudaGetSymbolAddress((void**)&xlo_p,  g_xlo);
        cudaGetSymbolAddress((void**)&kwhi_p, g_kwhi);
        cudaGetSymbolAddress((void**)&kwlo_p, g_kwlo);
    }

    init_kernel<<<2457, 256>>>((const unsigned char*)start, x,
        Wm2, Wm3, Wskip, Wm2 + 65536, Wm3 + 65536, Wskip + 65536,
        Wk, Wq, Wv);

    for (int b = 0; b < NBLK; b++) {
        kqv_mma_kernel<<<NC, 256, KQV2_SMEM>>>(
            (b == 0) ? xhi_p : x1hi_p, (b == 0) ? xlo_p : x1lo_p,
            kwhi_p + b*48*256, kwlo_p + b*48*256, bv + b*16, start);
        prefix1_kernel<<<NG, 256>>>();
        prefix2_kernel<<<1, 256>>>(s0 + b*256, z0 + b*16);
        apply_kernel<<<NC2, 256>>>(start, Wm1 + b*256*16, bm1 + b*256);

        const u16* wm2hi = whi_p + (b*3 + 0)*65536;
        const u16* wm2lo = wlo_p + (b*3 + 0)*65536;
        const u16* wm3hi = whi_p + (b*3 + 1)*65536;
        const u16* wm3lo = wlo_p + (b*3 + 1)*65536;
        const u16* wskhi = whi_p + (b*3 + 2)*65536;
        const u16* wsklo = wlo_p + (b*3 + 2)*65536;

        // h2 = leaky(h1 @ Wm2^T + bm2)
        gemm_mma_kernel<<<dim3(2, TT/128), 256, GEMM_SMEM>>>(
            h1hi_p, h1lo_p, h1hi_p, h1lo_p,
            wm2hi, wm2lo, wm2hi, wm2lo, bm2 + b*256, bm2 + b*256, 0);
        // ypre = h2 @ Wm3^T + A2 @ Wskip^T + bm3 + bskip
        gemm_mma_kernel<<<dim3(2, TT/128), 256, GEMM_SMEM>>>(
            h2hi_p, h2lo_p,
            (b == 0) ? xhi_p : x1hi_p, (b == 0) ? xlo_p : x1lo_p,
            wm3hi, wm3lo, wskhi, wsklo, bm3 + b*256, bskip + b*256,
            (b == 0) ? 1 : 2);
        ln_kernel<<<TT/8, 256>>>(x, out, lnw + b*256, lnb + b*256, (b == 0) ? 0 : 1);
    }
}

// round 13
// speedup vs baseline: 1.4821x; 1.0078x over previous
#include <cuda_runtime.h>
#include <cstdint>

typedef unsigned long long u64;
typedef unsigned int u32;
typedef unsigned short u16;

// Problem constants
#define TT   32768
#define DD   256
#define HH   256
#define KV   16
#define CH   128          // scan chunk length (kqv/prefix granularity)
#define CH2  64           // apply granularity (half chunks)
#define NC   (TT/CH)      // 256 chunks
#define NC2  (TT/CH2)     // 512 half-chunks
#define NG   16           // prefix groups (16 chunks each)
#define NBLK 2

// ---------------- device scratch (no allocations allowed) ----------------
__device__ float g_k[TT*KV];
__device__ float g_q[TT*KV];
__device__ float g_v[TT*KV];
__device__ float g_Sagg[NC*256];
__device__ float g_Zagg[NC];
__device__ int   g_pagg[NC];
__device__ float g_Shalf[NC*256];  // first-half (64-step) aggregates
__device__ float g_Zhalf[NC];
__device__ int   g_phalf[NC];
__device__ float g_Sloc[NC*256];   // local (within-group) exclusive prefixes
__device__ float g_Zloc[NC];
__device__ int   g_ploc[NC];
__device__ float g_SG[NG*256];     // group aggregates
__device__ float g_ZG[NG];
__device__ int   g_pG[NG];
__device__ float g_SGP[NG*256];    // group exclusive prefixes (incl s0 init)
__device__ float g_ZGP[NG];
__device__ float g_ypre[TT*HH];
__device__ int   g_startmode;   // 0=u8 bool, 1=int32, 2=float32
__device__ int   g_pfcnt;       // prefix last-CTA counter (self-resetting)

// bf16 hi/lo split operand storage
__device__ u16 g_h1hi[TT*HH];
__device__ u16 g_h1lo[TT*HH];
__device__ u16 g_h2hi[TT*HH];
__device__ u16 g_h2lo[TT*HH];
__device__ u16 g_x1hi[TT*HH];
__device__ u16 g_x1lo[TT*HH];
__device__ u16 g_xhi[TT*DD];
__device__ u16 g_xlo[TT*DD];
__device__ u16 g_whi[6*65536];   // [mat][256][256]: per block {Wm2, Wm3, Wskip}
__device__ u16 g_wlo[6*65536];
__device__ u16 g_kwhi[2*48*256]; // per block combined {Wk,Wq,Wv} rows 0..47
__device__ u16 g_kwlo[2*48*256];

// ---------------- helpers ----------------
__device__ __forceinline__ float phi_fn(float t) {
    return (t > 0.f) ? (1.f + t) : __expf(t);
}

__device__ __forceinline__ int read_start(const void* p, int t, int mode) {
    if (mode == 0) return ((const unsigned char*)p)[t] != 0;
    if (mode == 1) return ((const int*)p)[t] != 0;
    return ((const float*)p)[t] != 0.f;
}

__device__ __forceinline__ u32 pack_bf16x2(float lo, float hi) {
    u32 r;
    asm("cvt.rn.bf16x2.f32 %0, %1, %2;" : "=r"(r) : "f"(hi), "f"(lo));
    return r;
}
__device__ __forceinline__ float bf16lo_f(u32 p) { return __uint_as_float(p << 16); }
__device__ __forceinline__ float bf16hi_f(u32 p) { return __uint_as_float(p & 0xffff0000u); }

__device__ __forceinline__ u64 pack2f(float a, float b) {
    u64 r;
    asm("mov.b64 %0, {%1, %2};" : "=l"(r) : "r"(__float_as_uint(a)), "r"(__float_as_uint(b)));
    return r;
}
__device__ __forceinline__ u64 fma2(u64 a, u64 b, u64 c) {
    u64 d;
    asm("fma.rn.f32x2 %0, %1, %2, %3;" : "=l"(d) : "l"(a), "l"(b), "l"(c));
    return d;
}
__device__ __forceinline__ void unpack2(u64 v, float& lo, float& hi) {
    u32 a, b;
    asm("mov.b64 {%0, %1}, %2;" : "=r"(a), "=r"(b) : "l"(v));
    lo = __uint_as_float(a); hi = __uint_as_float(b);
}

__device__ __forceinline__ u32 smem_to_u32(const void* smem_ptr) {
    u32 addr;
    asm("{ .reg .u64 tmp; cvta.to.shared.u64 tmp, %1; cvt.u32.u64 %0, tmp; }"
        : "=r"(addr) : "l"(smem_ptr));
    return addr;
}

__device__ __forceinline__ void cp_async16(u32 saddr, const void* gptr) {
    asm volatile("cp.async.cg.shared.global [%0], [%1], 16;" :: "r"(saddr), "l"(gptr));
}
__device__ __forceinline__ void cp_commit() {
    asm volatile("cp.async.commit_group;" ::: "memory");
}
__device__ __forceinline__ void cp_wait0() {
    asm volatile("cp.async.wait_group 0;" ::: "memory");
}
__device__ __forceinline__ void cp_wait1() {
    asm volatile("cp.async.wait_group 1;" ::: "memory");
}

__device__ __forceinline__ void ldsm_x4(u32& r0, u32& r1, u32& r2, u32& r3, u32 addr) {
    asm volatile("ldmatrix.sync.aligned.m8n8.x4.shared.b16 {%0,%1,%2,%3}, [%4];"
        : "=r"(r0), "=r"(r1), "=r"(r2), "=r"(r3) : "r"(addr));
}

__device__ __forceinline__ void mma16816(float* d, const u32* a, u32 b0, u32 b1) {
    asm volatile(
        "mma.sync.aligned.m16n8k16.row.col.f32.bf16.bf16.f32 "
        "{%0,%1,%2,%3}, {%4,%5,%6,%7}, {%8,%9}, {%0,%1,%2,%3};"
        : "+f"(d[0]), "+f"(d[1]), "+f"(d[2]), "+f"(d[3])
        : "r"(a[0]), "r"(a[1]), "r"(a[2]), "r"(a[3]), "r"(b0), "r"(b1));
}

// ---------------- init: weight split + detect + x split + kqv-weight split ------
// blocks [0,384): big weights; 384: detect; [385,2433): x split; [2433,2457): kqv W
__global__ void init_kernel(const unsigned char* __restrict__ p,
                            const float* __restrict__ x,
                            const float* __restrict__ w0, const float* __restrict__ w1,
                            const float* __restrict__ w2, const float* __restrict__ w3,
                            const float* __restrict__ w4, const float* __restrict__ w5,
                            const float* __restrict__ Wk, const float* __restrict__ Wq,
                            const float* __restrict__ Wv)
{
    int tid = threadIdx.x;
    int bid = blockIdx.x;
    if (bid < 384) {
        int qi = bid * 256 + tid;        // 0..98303
        int mat = qi >> 14;              // 0..5
        int idx = (qi & 16383) * 4;      // element index within mat
        const float* src;
        switch (mat) {
            case 0: src = w0; break;
            case 1: src = w1; break;
            case 2: src = w2; break;
            case 3: src = w3; break;
            case 4: src = w4; break;
            default: src = w5; break;
        }
        float4 v = *(const float4*)(src + idx);
        u32 h0 = pack_bf16x2(v.x, v.y);
        u32 h1 = pack_bf16x2(v.z, v.w);
        u32 l0 = pack_bf16x2(v.x - bf16lo_f(h0), v.y - bf16hi_f(h0));
        u32 l1 = pack_bf16x2(v.z - bf16lo_f(h1), v.w - bf16hi_f(h1));
        u16* dh = g_whi + mat*65536 + idx;
        u16* dl = g_wlo + mat*65536 + idx;
        *(u32*)(dh)     = h0;
        *(u32*)(dh + 2) = h1;
        *(u32*)(dl)     = l0;
        *(u32*)(dl + 2) = l1;
    } else if (bid == 384) {
        __shared__ int cnt1, cnt3f;
        if (tid == 0) { cnt1 = 0; cnt3f = 0; }
        __syncthreads();
        int l1 = 0, l3 = 0;
        for (int idx = tid; idx < 4096; idx += 256) {
            unsigned char b = p[idx];
            if ((idx & 3) != 0 && b != 0) l1++;
            if ((idx & 3) == 3 && b == 0x3F) l3++;
        }
        atomicAdd(&cnt1, l1); atomicAdd(&cnt3f, l3);
        __syncthreads();
        if (tid == 0) g_startmode = (cnt3f > 0) ? 2 : ((cnt1 > 0) ? 0 : 1);
    } else if (bid < 2433) {
        int qbase = (bid - 385) * 1024;
        #pragma unroll
        for (int s = 0; s < 4; s++) {
            int base = (qbase + s*256 + tid) * 4;
            float4 v = *(const float4*)(x + base);
            u32 h0 = pack_bf16x2(v.x, v.y);
            u32 h1 = pack_bf16x2(v.z, v.w);
            u32 l0 = pack_bf16x2(v.x - bf16lo_f(h0), v.y - bf16hi_f(h0));
            u32 l1 = pack_bf16x2(v.z - bf16lo_f(h1), v.w - bf16hi_f(h1));
            *(u32*)(g_xhi + base)     = h0;
            *(u32*)(g_xhi + base + 2) = h1;
            *(u32*)(g_xlo + base)     = l0;
            *(u32*)(g_xlo + base + 2) = l1;
        }
    } else {
        int qi = (bid - 2433) * 256 + tid;   // 0..6143 float4
        int el = qi * 4;                      // 0..24575
        int b  = el / 12288;
        int rem = el - b*12288;
        int row = rem >> 8;                   // 0..47
        int c   = rem & 255;
        const float* src;
        int lr;
        if (row < 16)      { src = Wk + b*16*256; lr = row; }
        else if (row < 32) { src = Wq + b*16*256; lr = row - 16; }
        else               { src = Wv + b*16*256; lr = row - 32; }
        float4 v = *(const float4*)(src + lr*256 + c);
        u32 h0 = pack_bf16x2(v.x, v.y);
        u32 h1 = pack_bf16x2(v.z, v.w);
        u32 l0 = pack_bf16x2(v.x - bf16lo_f(h0), v.y - bf16hi_f(h0));
        u32 l1 = pack_bf16x2(v.z - bf16lo_f(h1), v.w - bf16hi_f(h1));
        u16* dh = g_kwhi + el;
        u16* dl = g_kwlo + el;
        *(u32*)(dh)     = h0;
        *(u32*)(dh + 2) = h1;
        *(u32*)(dl)     = l0;
        *(u32*)(dl + 2) = l1;
    }
}

// ======= kqv via HMMA: x(128 rows) @ {Wk,Wq,Wv}^T (48 outs) + chunk aggregate =======
#define KQ_KWHI   0
#define KQ_KWLO   24576
#define KQ_ASTG   49152
#define KQ_ASTGB  16384      // per stage: AHI at +0 (8192), ALO at +8192
#define KQ_KS     49152      // overlap with A stages (floats) — post-compute only
#define KQ_VS     57344
#define KQ_KSUM   65536
#define KQ_STB    66048
#define KQ_BVS    98304      // OUTSIDE A stages (must survive staging)
#define KQV2_SMEM 98432

__global__ void __launch_bounds__(256, 2)
kqv_mma_kernel(const u16* __restrict__ axhi, const u16* __restrict__ axlo,
               const u16* __restrict__ kwhi, const u16* __restrict__ kwlo,
               const float* __restrict__ bv, const void* __restrict__ startp)
{
    extern __shared__ char smc[];
    u32 sbase = smem_to_u32(smc);
    int tid  = threadIdx.x;
    int wid  = tid >> 5;
    int lane = tid & 31;
    int lrow = lane & 15;
    int chalf = lane >> 4;
    int base = blockIdx.x * CH;
    int mode = g_startmode;

    float* bvs = (float*)(smc + KQ_BVS);
    if (tid < 16) bvs[tid] = bv[tid];

    // stage full W (one group)
    for (int idx = tid; idx < 1536; idx += 256) {
        int kc  = idx / 192;
        int rem = idx - kc*192;
        int r   = rem >> 2;
        int sg  = rem & 3;
        u32 soff = (u32)(kc*3072 + r*64 + ((sg ^ ((r >> 1) & 3)) << 4));
        size_t ge = (size_t)r*256 + kc*32 + sg*8;
        cp_async16(sbase + KQ_KWHI + soff, kwhi + ge);
        cp_async16(sbase + KQ_KWLO + soff, kwlo + ge);
    }
    cp_commit();

    // stage A chunks 0,1
    #pragma unroll
    for (int pk = 0; pk < 2; pk++) {
        u32 stg = KQ_ASTG + pk*KQ_ASTGB;
        #pragma unroll
        for (int s = 0; s < 2; s++) {
            int idx = tid + s*256;
            int r = idx >> 2, sg = idx & 3;
            u32 soff = (u32)(r*64 + ((sg ^ ((r >> 1) & 3)) << 4));
            size_t ge = (size_t)(base + r)*256 + pk*32 + sg*8;
            cp_async16(sbase + stg + soff, axhi + ge);
            cp_async16(sbase + stg + 8192 + soff, axlo + ge);
        }
        cp_commit();
    }

    float acc[6][4];
    #pragma unroll
    for (int nt = 0; nt < 6; nt++)
        #pragma unroll
        for (int r = 0; r < 4; r++) acc[nt][r] = 0.f;

    for (int kc = 0; kc < 8; kc++) {
        if (kc + 1 < 8) cp_wait1(); else cp_wait0();
        __syncthreads();

        u32 sb = (u32)(KQ_ASTG + (kc % 3)*KQ_ASTGB);
        #pragma unroll
        for (int ks = 0; ks < 2; ks++) {
            int cch = ks*2 + chalf;
            int arow = wid*16 + lrow;
            u32 aoff = sb + (u32)(arow*64 + ((cch ^ ((arow >> 1) & 3)) << 4));
            u32 ahi[4], alo[4];
            ldsm_x4(ahi[0], ahi[1], ahi[2], ahi[3], sbase + aoff);
            ldsm_x4(alo[0], alo[1], alo[2], alo[3], sbase + aoff + 8192);
            #pragma unroll
            for (int bg = 0; bg < 3; bg++) {
                int brow = bg*16 + lrow;
                u32 boff = (u32)(kc*3072 + brow*64 + ((cch ^ ((brow >> 1) & 3)) << 4));
                u32 bh[4], bl[4];
                ldsm_x4(bh[0], bh[1], bh[2], bh[3], sbase + KQ_KWHI + boff);
                ldsm_x4(bl[0], bl[1], bl[2], bl[3], sbase + KQ_KWLO + boff);
                #pragma unroll
                for (int nj = 0; nj < 2; nj++) {
                    float* d = acc[bg*2 + nj];
                    mma16816(d, ahi, bh[nj], bh[2 + nj]);
                    mma16816(d, ahi, bl[nj], bl[2 + nj]);
                    mma16816(d, alo, bh[nj], bh[2 + nj]);
                }
            }
        }
        if (kc + 2 < 8) {
            u32 stg = KQ_ASTG + ((kc + 2) % 3)*KQ_ASTGB;
            #pragma unroll
            for (int s = 0; s < 2; s++) {
                int idx = tid + s*256;
                int r = idx >> 2, sg = idx & 3;
                u32 soff = (u32)(r*64 + ((sg ^ ((r >> 1) & 3)) << 4));
                size_t ge = (size_t)(base + r)*256 + (kc + 2)*32 + sg*8;
                cp_async16(sbase + stg + soff, axhi + ge);
                cp_async16(sbase + stg + 8192 + soff, axlo + ge);
            }
            cp_commit();
        }
    }
    __syncthreads();   // all ldsm done before scan arrays overwrite A stages

    float* ks_sm = (float*)(smc + KQ_KS);
    float* vs_sm = (float*)(smc + KQ_VS);
    float* ksums = (float*)(smc + KQ_KSUM);
    int*   stb   = (int*)(smc + KQ_STB);

    // epilogue: phi/bias, write k/q/v (gmem) + ks/vs (smem)
    int r0 = wid*16 + (lane >> 2);
    #pragma unroll
    for (int nt = 0; nt < 6; nt++) {
        int colL = nt*8 + (lane & 3)*2;
        #pragma unroll
        for (int rr = 0; rr < 2; rr++) {
            int row = r0 + rr*8;
            int t   = base + row;
            float v0 = acc[nt][rr*2 + 0];
            float v1 = acc[nt][rr*2 + 1];
            if (colL < 16) {
                float p0 = phi_fn(v0), p1 = phi_fn(v1);
                *(float2*)(g_k + (size_t)t*16 + colL) = make_float2(p0, p1);
                ks_sm[row*16 + colL]     = p0;
                ks_sm[row*16 + colL + 1] = p1;
            } else if (colL < 32) {
                int o = colL - 16;
                *(float2*)(g_q + (size_t)t*16 + o) = make_float2(phi_fn(v0), phi_fn(v1));
            } else {
                int o = colL - 32;
                float w0 = v0 + bvs[o], w1 = v1 + bvs[o + 1];
                *(float2*)(g_v + (size_t)t*16 + o) = make_float2(w0, w1);
                vs_sm[row*16 + o]     = w0;
                vs_sm[row*16 + o + 1] = w1;
            }
        }
    }
    __syncthreads();

    if (tid < 128) {
        float s = 0.f;
        #pragma unroll
        for (int i = 0; i < 16; i++) s += ks_sm[tid*16 + i];
        ksums[tid] = s;
        stb[tid] = read_start(startp, base + tid, mode);
    }
    __syncthreads();

    int i = tid & 15, j = tid >> 4;
    float S = 0.f, Zs = 0.f; int p = 0;
    for (int t = 0; t < CH; t++) {
        if (t == CH2) {
            g_Shalf[blockIdx.x*256 + tid] = S;
            if (tid == 0) { g_Zhalf[blockIdx.x] = Zs; g_phalf[blockIdx.x] = p; }
        }
        if (stb[t]) { S = 0.f; Zs = 0.f; p = 1; }
        S  += ks_sm[t*16 + i] * vs_sm[t*16 + j];
        Zs += ksums[t];
    }
    g_Sagg[blockIdx.x*256 + tid] = S;
    if (tid == 0) { g_Zagg[blockIdx.x] = Zs; g_pagg[blockIdx.x] = p; }
}

// -------- prefix: level 1 (16 CTAs) + fused last-CTA level 2 --------
__global__ void prefix_kernel(const float* __restrict__ s0, const float* __restrict__ z0)
{
    int tid = threadIdx.x;
    int g = blockIdx.x;
    {
        float sa[16], za[16]; int pa[16];
        #pragma unroll
        for (int d = 0; d < 16; d++) {
            int c = g*16 + d;
            sa[d] = g_Sagg[c*256 + tid];
            za[d] = g_Zagg[c];
            pa[d] = g_pagg[c];
        }
        float S = 0.f, Zs = 0.f; int p = 0;
        #pragma unroll
        for (int d = 0; d < 16; d++) {
            int c = g*16 + d;
            g_Sloc[c*256 + tid] = S;
            if (tid == 0) { g_Zloc[c] = Zs; g_ploc[c] = p; }
            if (pa[d]) { S = 0.f; Zs = 0.f; }
            S += sa[d]; Zs += za[d]; p |= pa[d];
        }
        g_SG[g*256 + tid] = S;
        if (tid == 0) { g_ZG[g] = Zs; g_pG[g] = p; }
    }
    // last-CTA does level 2 (self-resetting counter; graph-replay safe)
    __threadfence();
    __shared__ int is_last;
    if (tid == 0) {
        int c = atomicAdd(&g_pfcnt, 1);
        is_last = (c == NG - 1);
    }
    __syncthreads();
    if (!is_last) return;

    float sa[NG], za[NG]; int pa[NG];
    #pragma unroll
    for (int gg = 0; gg < NG; gg++) {
        sa[gg] = g_SG[gg*256 + tid];
        za[gg] = g_ZG[gg];
        pa[gg] = g_pG[gg];
    }
    int i = tid & 15, j = tid >> 4;
    float S = s0[i*16 + j];
    float Zs = 0.f;
    #pragma unroll
    for (int l = 0; l < 16; l++) Zs += z0[l];
    #pragma unroll
    for (int gg = 0; gg < NG; gg++) {
        g_SGP[gg*256 + tid] = S;
        if (tid == 0) g_ZGP[gg] = Zs;
        if (pa[gg]) { S = 0.f; Zs = 0.f; }
        S += sa[gg]; Zs += za[gg];
    }
    if (tid == 0) g_pfcnt = 0;   // reset for next launch / next graph replay
}

// ------- pass 3: replay (64 steps) + attention output + MLP layer 1 (f32x2) -------
__global__ void apply_kernel(const void* __restrict__ startp,
                             const float* __restrict__ Wm1, const float* __restrict__ bm1)
{
    __shared__ float ks[CH2*16], qs[CH2*16], vs[CH2*16], ksums[CH2], qsums[CH2];
    __shared__ int stb[CH2];
    __shared__ __align__(16) float outb[2][16][18];
    int tid = threadIdx.x;
    int c2 = blockIdx.x;
    int c  = c2 >> 1;
    int odd = c2 & 1;
    int tb = c2 * CH2;
    int mode = g_startmode;
    for (int idx = tid; idx < CH2*16; idx += 256) {
        ks[idx] = g_k[tb*16 + idx];
        qs[idx] = g_q[tb*16 + idx];
        vs[idx] = g_v[tb*16 + idx];
    }
    if (tid < CH2)
        stb[tid] = read_start(startp, tb + tid, mode);
    __syncthreads();
    if (tid < CH2) {
        float sk = 0.f, sq = 0.f;
        #pragma unroll
        for (int i = 0; i < 16; i++) { sk += ks[tid*16+i]; sq += qs[tid*16+i]; }
        ksums[tid] = sk; qsums[tid] = sq;
    }
    u64 wm1p[8];
    #pragma unroll
    for (int l2 = 0; l2 < 8; l2++)
        wm1p[l2] = pack2f(Wm1[tid*16 + 2*l2], Wm1[tid*16 + 2*l2 + 1]);
    float b1 = bm1[tid];
    int grp = c >> 4;
    float Sl = g_Sloc[c*256 + tid];
    int   pl = g_ploc[c];
    float S  = pl ? Sl : (g_SGP[grp*256 + tid] + Sl);
    float Zl = g_Zloc[c];
    float Zs = pl ? Zl : (g_ZGP[grp] + Zl);
    if (odd) {
        float Sh = g_Shalf[c*256 + tid];
        float Zh = g_Zhalf[c];
        int   ph = g_phalf[c];
        if (ph) { S = Sh; Zs = Zh; }
        else    { S += Sh; Zs += Zh; }
    }
    __syncthreads();

    int i = tid & 15, j = tid >> 4;
    for (int t0 = 0; t0 < CH2; t0 += 16) {
        int buf = (t0 >> 4) & 1;
        #pragma unroll
        for (int tt = 0; tt < 16; tt++) {
            int t = t0 + tt;
            if (stb[t]) { S = 0.f; Zs = 0.f; }
            S  += ks[t*16 + i] * vs[t*16 + j];
            Zs += ksums[t];
            float pv = S * qs[t*16 + i];
            pv += __shfl_down_sync(0xffffffffu, pv, 8, 16);
            pv += __shfl_down_sync(0xffffffffu, pv, 4, 16);
            pv += __shfl_down_sync(0xffffffffu, pv, 2, 16);
            pv += __shfl_down_sync(0xffffffffu, pv, 1, 16);
            if (i == 0) {
                float denom = fmaxf(Zs * qsums[t], 1e-6f);
                outb[buf][tt][j] = pv / denom;
            }
        }
        __syncthreads();
        #pragma unroll
        for (int tt = 0; tt < 16; tt++) {
            const float* ob = outb[buf][tt];
            u64 hacc = 0ull;
            #pragma unroll
            for (int l2 = 0; l2 < 8; l2++) {
                u64 op = *(const u64*)(ob + 2*l2);
                hacc = fma2(op, wm1p[l2], hacc);
            }
            float hl, hh;
            unpack2(hacc, hl, hh);
            float h = hl + hh + b1;
            h = (h > 0.f) ? h : 0.01f * h;
            u32 ph = pack_bf16x2(h, h);
            float res = h - bf16lo_f(ph);
            u32 plp = pack_bf16x2(res, res);
            size_t off = (size_t)(tb + t0 + tt) * 256 + tid;
            g_h1hi[off] = (u16)ph;
            g_h1lo[off] = (u16)plp;
        }
    }
}

// ===== HMMA big GEMM: bf16x3 split, 3-stage cp.async, K-chunk 32, XOR swizzle =====
#define SOFF_AHI  0
#define SOFF_ALO  8192
#define SOFF_BHI  16384
#define SOFF_BLO  24576
#define STAGE_BYTES 32768
#define OFF_BIAS  (3*STAGE_BYTES)
#define GEMM_SMEM (OFF_BIAS + 512)

__device__ __forceinline__ void gemm_stage(
    u32 sbase, u32 stagebase, int kc,
    const u16* __restrict__ a1hi, const u16* __restrict__ a1lo,
    const u16* __restrict__ a2hi, const u16* __restrict__ a2lo,
    const u16* __restrict__ w1hi, const u16* __restrict__ w1lo,
    const u16* __restrict__ w2hi, const u16* __restrict__ w2lo,
    int rowbase, int colbase, int tid)
{
    int koff = (kc & 7) * 32;
    const u16* Whi = (kc < 8) ? w1hi : w2hi;
    const u16* Wlo = (kc < 8) ? w1lo : w2lo;
    const u16* Ahi = (kc < 8) ? a1hi : a2hi;
    const u16* Alo = (kc < 8) ? a1lo : a2lo;
    #pragma unroll
    for (int s = 0; s < 2; s++) {
        int idx = tid + s*256;        // 0..511
        int r  = idx >> 2;            // 0..127
        int sg = idx & 3;             // 16B chunk within 64B row
        u32 soff = (u32)(r*64 + ((sg ^ ((r >> 1) & 3)) << 4));
        size_t gea = (size_t)(rowbase + r) * 256 + koff + sg*8;
        size_t geb = (size_t)(colbase + r) * 256 + koff + sg*8;
        cp_async16(sbase + stagebase + SOFF_AHI + soff, Ahi + gea);
        cp_async16(sbase + stagebase + SOFF_ALO + soff, Alo + gea);
        cp_async16(sbase + stagebase + SOFF_BHI + soff, Whi + geb);
        cp_async16(sbase + stagebase + SOFF_BLO + soff, Wlo + geb);
    }
}

__global__ void __launch_bounds__(256, 2)
gemm_mma_kernel(const u16* __restrict__ a1hi, const u16* __restrict__ a1lo,
                const u16* __restrict__ a2hi, const u16* __restrict__ a2lo,
                const u16* __restrict__ w1hi, const u16* __restrict__ w1lo,
                const u16* __restrict__ w2hi, const u16* __restrict__ w2lo,
                const float* __restrict__ b1p, const float* __restrict__ b2p,
                int variant)
{
    extern __shared__ char smc[];
    u32 sbase = smem_to_u32(smc);
    float* bias_sm = (float*)(smc + OFF_BIAS);

    int nchunk = (variant == 0) ? 8 : 16;

    int tid  = threadIdx.x;
    int wid  = tid >> 5;
    int lane = tid & 31;
    int colbase = blockIdx.x * 128;
    int rowbase = blockIdx.y * 128;

    int warp_m = (wid >> 1) * 32;
    int warp_n = (wid & 1) * 64;

    for (int i = tid; i < 128; i += 256)
        bias_sm[i] = b1p[colbase + i] + ((variant != 0) ? b2p[colbase + i] : 0.f);

    float acc[2][8][4];
    #pragma unroll
    for (int mi = 0; mi < 2; mi++)
        #pragma unroll
        for (int nt = 0; nt < 8; nt++)
            #pragma unroll
            for (int r = 0; r < 4; r++) acc[mi][nt][r] = 0.f;

    gemm_stage(sbase, 0, 0, a1hi, a1lo, a2hi, a2lo, w1hi, w1lo, w2hi, w2lo,
               rowbase, colbase, tid);
    cp_commit();
    gemm_stage(sbase, STAGE_BYTES, 1, a1hi, a1lo, a2hi, a2lo, w1hi, w1lo, w2hi, w2lo,
               rowbase, colbase, tid);
    cp_commit();

    int lrow  = lane & 15;
    int chalf = lane >> 4;

    for (int kc = 0; kc < nchunk; kc++) {
        if (kc + 1 < nchunk) cp_wait1(); else cp_wait0();
        __syncthreads();

        u32 sb = (u32)((kc % 3) * STAGE_BYTES);
        #pragma unroll
        for (int ks = 0; ks < 2; ks++) {
            int cch = ks*2 + chalf;
            u32 ahi[2][4], alo[2][4];
            #pragma unroll
            for (int mi = 0; mi < 2; mi++) {
                int row = warp_m + mi*16 + lrow;
                u32 off = sb + (u32)(row*64 + ((cch ^ ((row >> 1) & 3)) << 4));
                ldsm_x4(ahi[mi][0], ahi[mi][1], ahi[mi][2], ahi[mi][3], sbase + SOFF_AHI + off);
                ldsm_x4(alo[mi][0], alo[mi][1], alo[mi][2], alo[mi][3], sbase + SOFF_ALO + off);
            }
            #pragma unroll
            for (int gg = 0; gg < 4; gg++) {
                int row = warp_n + gg*16 + lrow;
                u32 off = sb + (u32)(row*64 + ((cch ^ ((row >> 1) & 3)) << 4));
                u32 bh[4], bl[4];
                ldsm_x4(bh[0], bh[1], bh[2], bh[3], sbase + SOFF_BHI + off);
                ldsm_x4(bl[0], bl[1], bl[2], bl[3], sbase + SOFF_BLO + off);
                #pragma unroll
                for (int mi = 0; mi < 2; mi++) {
                    #pragma unroll
                    for (int nj = 0; nj < 2; nj++) {
                        float* d = acc[mi][gg*2 + nj];
                        mma16816(d, ahi[mi], bh[nj], bh[2 + nj]);
                        mma16816(d, ahi[mi], bl[nj], bl[2 + nj]);
                        mma16816(d, alo[mi], bh[nj], bh[2 + nj]);
                    }
                }
            }
        }
        if (kc + 2 < nchunk) {
            gemm_stage(sbase, (u32)(((kc + 2) % 3) * STAGE_BYTES), kc + 2,
                       a1hi, a1lo, a2hi, a2lo, w1hi, w1lo, w2hi, w2lo,
                       rowbase, colbase, tid);
            cp_commit();
        }
    }

    // ---------------- epilogue ----------------
    #pragma unroll
    for (int mi = 0; mi < 2; mi++) {
        int row0 = rowbase + warp_m + mi*16 + (lane >> 2);
        #pragma unroll
        for (int nt = 0; nt < 8; nt++) {
            int colL = warp_n + nt*8 + (lane & 3)*2;
            int col  = colbase + colL;
            float b0 = bias_sm[colL], b1 = bias_sm[colL + 1];
            float v0 = acc[mi][nt][0] + b0;
            float v1 = acc[mi][nt][1] + b1;
            float v2 = acc[mi][nt][2] + b0;
            float v3 = acc[mi][nt][3] + b1;
            if (variant == 0) {
                v0 = (v0 > 0.f) ? v0 : 0.01f * v0;
                v1 = (v1 > 0.f) ? v1 : 0.01f * v1;
                v2 = (v2 > 0.f) ? v2 : 0.01f * v2;
                v3 = (v3 > 0.f) ? v3 : 0.01f * v3;
                u32 hp0 = pack_bf16x2(v0, v1);
                u32 lp0 = pack_bf16x2(v0 - bf16lo_f(hp0), v1 - bf16hi_f(hp0));
                u32 hp1 = pack_bf16x2(v2, v3);
                u32 lp1 = pack_bf16x2(v2 - bf16lo_f(hp1), v3 - bf16hi_f(hp1));
                size_t o0 = (size_t)row0 * 256 + col;
                size_t o1 = (size_t)(row0 + 8) * 256 + col;
                *(u32*)(g_h2hi + o0) = hp0;
                *(u32*)(g_h2lo + o0) = lp0;
                *(u32*)(g_h2hi + o1) = hp1;
                *(u32*)(g_h2lo + o1) = lp1;
            } else {
                *(float2*)(g_ypre + (size_t)row0 * 256 + col)       = make_float2(v0, v1);
                *(float2*)(g_ypre + (size_t)(row0 + 8) * 256 + col) = make_float2(v2, v3);
            }
        }
    }
}

// ---------------- LayerNorm + residual ----------------
// mode 0: x1 split = xext + LN(g_ypre)    (block 0; splits only)
// mode 1: outext = LN(g_ypre)             (block 1, final output)
__global__ void ln_kernel(const float* __restrict__ xext, float* __restrict__ outext,
                          const float* __restrict__ lw, const float* __restrict__ lb, int mode)
{
    int tid = threadIdx.x;
    int lane = tid & 31, w = tid >> 5;
    int row = blockIdx.x * 8 + w;
    const float* yp = g_ypre + (size_t)row * 256;
    float vals[8];
    float s = 0.f;
    #pragma unroll
    for (int u = 0; u < 8; u++) { vals[u] = yp[lane + u*32]; s += vals[u]; }
    #pragma unroll
    for (int d = 16; d >= 1; d >>= 1) s += __shfl_xor_sync(0xffffffffu, s, d);
    float mean = s * (1.f / 256.f);
    float v2 = 0.f;
    #pragma unroll
    for (int u = 0; u < 8; u++) { float d = vals[u] - mean; v2 += d * d; }
    #pragma unroll
    for (int d = 16; d >= 1; d >>= 1) v2 += __shfl_xor_sync(0xffffffffu, v2, d);
    float rstd = rsqrtf(v2 * (1.f / 256.f) + 1e-5f);

    if (mode == 0) {
        const float* xr = xext + (size_t)row * 256;
        #pragma unroll
        for (int u = 0; u < 8; u++) {
            int cl = lane + u*32;
            float y = xr[cl] + (vals[u] - mean) * rstd * lw[cl] + lb[cl];
            u32 ph = pack_bf16x2(y, y);
            float res = y - bf16lo_f(ph);
            u32 pl = pack_bf16x2(res, res);
            size_t off = (size_t)row * 256 + cl;
            g_x1hi[off] = (u16)ph;
            g_x1lo[off] = (u16)pl;
        }
    } else {
        float* o = outext + (size_t)row * 256;
        #pragma unroll
        for (int u = 0; u < 8; u++) {
            int cl = lane + u*32;
            o[cl] = (vals[u] - mean) * rstd * lw[cl] + lb[cl];
        }
    }
}

// ---------------- launch ----------------
extern "C" void kernel_launch(void* const* d_in, const int* in_sizes, int n_in,
                              void* d_out, int out_size)
{
    const float* x     = (const float*)d_in[0];
    const void*  start = d_in[1];
    const float* s0    = (const float*)d_in[2];
    const float* z0    = (const float*)d_in[3];
    const float* Wk    = (const float*)d_in[4];
    const float* Wq    = (const float*)d_in[5];
    const float* Wv    = (const float*)d_in[6];
    const float* bv    = (const float*)d_in[7];
    const float* Wskip = (const float*)d_in[8];
    const float* bskip = (const float*)d_in[9];
    const float* Wm1   = (const float*)d_in[10];
    const float* bm1   = (const float*)d_in[11];
    const float* Wm2   = (const float*)d_in[12];
    const float* bm2   = (const float*)d_in[13];
    const float* Wm3   = (const float*)d_in[14];
    const float* bm3   = (const float*)d_in[15];
    const float* lnw   = (const float*)d_in[16];
    const float* lnb   = (const float*)d_in[17];
    float* out = (float*)d_out;

    cudaFuncSetAttribute(kqv_mma_kernel, cudaFuncAttributeMaxDynamicSharedMemorySize, KQV2_SMEM);
    cudaFuncSetAttribute(gemm_mma_kernel, cudaFuncAttributeMaxDynamicSharedMemorySize, GEMM_SMEM);

    static u16 *whi_p = nullptr, *wlo_p = nullptr;
    static u16 *h1hi_p, *h1lo_p, *h2hi_p, *h2lo_p, *x1hi_p, *x1lo_p, *xhi_p, *xlo_p;
    static u16 *kwhi_p, *kwlo_p;
    if (!whi_p) {
        cudaGetSymbolAddress((void**)&whi_p,  g_whi);
        cudaGetSymbolAddress((void**)&wlo_p,  g_wlo);
        cudaGetSymbolAddress((void**)&h1hi_p, g_h1hi);
        cudaGetSymbolAddress((void**)&h1lo_p, g_h1lo);
        cudaGetSymbolAddress((void**)&h2hi_p, g_h2hi);
        cudaGetSymbolAddress((void**)&h2lo_p, g_h2lo);
        cudaGetSymbolAddress((void**)&x1hi_p, g_x1hi);
        cudaGetSymbolAddress((void**)&x1lo_p, g_x1lo);
        cudaGetSymbolAddress((void**)&xhi_p,  g_xhi);
        cudaGetSymbolAddress((void**)&xlo_p,  g_xlo);
        cudaGetSymbolAddress((void**)&kwhi_p, g_kwhi);
        cudaGetSymbolAddress((void**)&kwlo_p, g_kwlo);
    }

    init_kernel<<<2457, 256>>>((const unsigned char*)start, x,
        Wm2, Wm3, Wskip, Wm2 + 65536, Wm3 + 65536, Wskip + 65536,
        Wk, Wq, Wv);

    for (int b = 0; b < NBLK; b++) {
        kqv_mma_kernel<<<NC, 256, KQV2_SMEM>>>(
            (b == 0) ? xhi_p : x1hi_p, (b == 0) ? xlo_p : x1lo_p,
            kwhi_p + b*48*256, kwlo_p + b*48*256, bv + b*16, start);
        prefix_kernel<<<NG, 256>>>(s0 + b*256, z0 + b*16);
        apply_kernel<<<NC2, 256>>>(start, Wm1 + b*256*16, bm1 + b*256);

        const u16* wm2hi = whi_p + (b*3 + 0)*65536;
        const u16* wm2lo = wlo_p + (b*3 + 0)*65536;
        const u16* wm3hi = whi_p + (b*3 + 1)*65536;
        const u16* wm3lo = wlo_p + (b*3 + 1)*65536;
        const u16* wskhi = whi_p + (b*3 + 2)*65536;
        const u16* wsklo = wlo_p + (b*3 + 2)*65536;

        // h2 = leaky(h1 @ Wm2^T + bm2)
        gemm_mma_kernel<<<dim3(2, TT/128), 256, GEMM_SMEM>>>(
            h1hi_p, h1lo_p, h1hi_p, h1lo_p,
            wm2hi, wm2lo, wm2hi, wm2lo, bm2 + b*256, bm2 + b*256, 0);
        // ypre = h2 @ Wm3^T + A2 @ Wskip^T + bm3 + bskip
        gemm_mma_kernel<<<dim3(2, TT/128), 256, GEMM_SMEM>>>(
            h2hi_p, h2lo_p,
            (b == 0) ? xhi_p : x1hi_p, (b == 0) ? xlo_p : x1lo_p,
            wm3hi, wm3lo, wskhi, wsklo, bm3 + b*256, bskip + b*256,
            (b == 0) ? 1 : 2);
        ln_kernel<<<TT/8, 256>>>(x, out, lnw + b*256, lnb + b*256, (b == 0) ? 0 : 1);
    }
}